// round 2
// baseline (speedup 1.0000x reference)
#include <cuda_runtime.h>
#include <math.h>

// ---------------- problem constants ----------------
#define NQ      13125
#define BATCH   2
#define MQ      (BATCH * NQ)     // 26250
#define DMODEL  256
#define HEADS   8
#define HD      32
#define LVL     3
#define PTS     4

// level geometry
__device__ __constant__ int c_HL[LVL]   = {100, 50, 25};
__device__ __constant__ int c_WL[LVL]   = {100, 50, 25};
__device__ __constant__ int c_LOFF[LVL] = {0, 10000, 12500};

// ---------------- scratch (static device memory; no allocation) ----------------
__device__ float g_vproj[(size_t)MQ * DMODEL];   // projected values, row = b*NQ + lvl_off + pix
__device__ float g_off  [(size_t)MQ * 192];      // sampling offsets
__device__ float g_attnl[(size_t)MQ * 96];       // attention logits
__device__ float g_mid  [(size_t)MQ * DMODEL];   // attention output before W_out

__device__ __forceinline__ float* gbuf(int sel) {
    switch (sel) {
        case 0:  return g_vproj;
        case 1:  return g_off;
        case 2:  return g_attnl;
        default: return g_mid;
    }
}

// ---------------- tiled SGEMM with bias: C[M,N] = A[M,K] @ W[K,N] + bias ----------------
// BM=64, BN=64, BK=16, 256 threads, 4x4 microtile per thread.
// hw_map > 0 remaps output row r -> (r / hw_map)*NQ + lvl_off + (r % hw_map)
__global__ __launch_bounds__(256, 4)
void sgemm_bias(const float* __restrict__ Ain, int asel,
                const float* __restrict__ W,
                const float* __restrict__ bias,
                float* __restrict__ Cout, int csel,
                int M, int N, int K,
                int hw_map, int lvl_off)
{
    const float* A = (asel >= 0) ? gbuf(asel) : Ain;
    float*       C = (csel >= 0) ? gbuf(csel) : Cout;

    __shared__ float As[16][68];   // [k][m], padded
    __shared__ float Ws[16][64];   // [k][n]

    const int tid = threadIdx.x;
    const int tx  = tid & 15;      // n-direction (x4)
    const int ty  = tid >> 4;      // m-direction (x4)
    const int row0 = blockIdx.x * 64;
    const int n0   = blockIdx.y * 64;

    const int ar = tid >> 2;        // 0..63   (m within tile)
    const int ac = (tid & 3) * 4;   // 0,4,8,12 (k within tile)
    const int wr = tid >> 4;        // 0..15   (k within tile)
    const int wc = (tid & 15) * 4;  // 0..60   (n within tile)

    float acc[4][4] = {};

    for (int k0 = 0; k0 < K; k0 += 16) {
        float4 av = make_float4(0.f, 0.f, 0.f, 0.f);
        if (row0 + ar < M)
            av = *(const float4*)(A + (size_t)(row0 + ar) * K + k0 + ac);
        As[ac + 0][ar] = av.x;
        As[ac + 1][ar] = av.y;
        As[ac + 2][ar] = av.z;
        As[ac + 3][ar] = av.w;

        float4 wv = make_float4(0.f, 0.f, 0.f, 0.f);
        if (n0 + wc < N)
            wv = *(const float4*)(W + (size_t)(k0 + wr) * N + n0 + wc);
        *(float4*)&Ws[wr][wc] = wv;

        __syncthreads();

        #pragma unroll
        for (int k = 0; k < 16; k++) {
            float4 a4 = *(const float4*)&As[k][ty * 4];
            float4 w4 = *(const float4*)&Ws[k][tx * 4];
            float a[4] = {a4.x, a4.y, a4.z, a4.w};
            float w[4] = {w4.x, w4.y, w4.z, w4.w};
            #pragma unroll
            for (int i = 0; i < 4; i++)
                #pragma unroll
                for (int j = 0; j < 4; j++)
                    acc[i][j] = fmaf(a[i], w[j], acc[i][j]);
        }
        __syncthreads();
    }

    #pragma unroll
    for (int i = 0; i < 4; i++) {
        int r = row0 + ty * 4 + i;
        if (r >= M) continue;
        int orow = r;
        if (hw_map > 0)
            orow = (r / hw_map) * NQ + lvl_off + (r % hw_map);
        #pragma unroll
        for (int j = 0; j < 4; j++) {
            int c = n0 + tx * 4 + j;
            if (c < N)
                C[(size_t)orow * N + c] = acc[i][j] + bias[c];
        }
    }
}

// ---------------- fused softmax + deformable bilinear sampling ----------------
// grid: MQ blocks; block: 256 threads = 8 warps; warp h handles head h of query bq.
// Lane = hd channel -> each corner gather is one coalesced 128B line.
__global__ __launch_bounds__(256, 8)
void msda_sample(const float* __restrict__ rp /* (B,Nq,L,2) */)
{
    const int bq   = blockIdx.x;
    const int h    = threadIdx.x >> 5;
    const int lane = threadIdx.x & 31;
    const int b    = bq / NQ;

    // --- softmax over 12 logits (per head) using warp shuffles ---
    float lv = -1e30f;
    if (lane < LVL * PTS)                                   // 12 logits per head
        lv = g_attnl[(size_t)bq * 96 + h * 12 + lane];      // per-head stride = L*P = 12
    float m = lv;
    #pragma unroll
    for (int o = 16; o; o >>= 1) m = fmaxf(m, __shfl_xor_sync(0xffffffffu, m, o));
    float e = (lane < LVL * PTS) ? __expf(lv - m) : 0.f;
    float s = e;
    #pragma unroll
    for (int o = 16; o; o >>= 1) s += __shfl_xor_sync(0xffffffffu, s, o);
    const float prob = e / s;

    const float* offp = g_off + (size_t)bq * 192 + h * 24;  // per-head stride = L*P*2 = 24
    float acc = 0.f;

    #pragma unroll
    for (int l = 0; l < LVL; l++) {
        const int   Wi = c_WL[l], Hi = c_HL[l];
        const float Wf = (float)Wi, Hf = (float)Hi;
        const float rx = rp[(size_t)bq * (LVL * 2) + l * 2 + 0];
        const float ry = rp[(size_t)bq * (LVL * 2) + l * 2 + 1];
        const float* vbase = g_vproj + ((size_t)(b * NQ + c_LOFF[l])) * DMODEL + h * HD + lane;

        #pragma unroll
        for (int p = 0; p < PTS; p++) {
            const float a  = __shfl_sync(0xffffffffu, prob, l * PTS + p);
            const float ox = offp[l * 8 + p * 2 + 0];
            const float oy = offp[l * 8 + p * 2 + 1];
            // match reference op order exactly: loc = rp + off/norm; x = loc*W - 0.5
            const float locx = rx + ox / Wf;
            const float locy = ry + oy / Hf;
            const float x = locx * Wf - 0.5f;
            const float y = locy * Hf - 0.5f;
            const float x0f = floorf(x), y0f = floorf(y);
            const float wx1 = x - x0f,  wy1 = y - y0f;
            const int ix0 = (int)x0f, iy0 = (int)y0f;

            float sv = 0.f;
            #pragma unroll
            for (int cy = 0; cy < 2; cy++) {
                const int   iy = iy0 + cy;
                const float wy = cy ? wy1 : (1.f - wy1);
                if (iy < 0 || iy >= Hi) continue;
                #pragma unroll
                for (int cx = 0; cx < 2; cx++) {
                    const int   ix = ix0 + cx;
                    const float wx = cx ? wx1 : (1.f - wx1);
                    if (ix < 0 || ix >= Wi) continue;
                    sv = fmaf(wx * wy, vbase[(size_t)(iy * Wi + ix) * DMODEL], sv);
                }
            }
            acc = fmaf(a, sv, acc);
        }
    }
    g_mid[(size_t)bq * DMODEL + h * HD + lane] = acc;
}

// ---------------- launch ----------------
extern "C" void kernel_launch(void* const* d_in, const int* in_sizes, int n_in,
                              void* d_out, int out_size)
{
    const float* query  = (const float*)d_in[0];
    const float* rp     = (const float*)d_in[1];
    const float* v0     = (const float*)d_in[2];
    const float* v1     = (const float*)d_in[3];
    const float* v2     = (const float*)d_in[4];
    const float* W_val  = (const float*)d_in[5];
    const float* b_val  = (const float*)d_in[6];
    const float* W_off  = (const float*)d_in[7];
    const float* b_off  = (const float*)d_in[8];
    const float* W_attn = (const float*)d_in[9];
    const float* b_attn = (const float*)d_in[10];
    const float* W_out  = (const float*)d_in[11];
    const float* b_out  = (const float*)d_in[12];
    float* out = (float*)d_out;

    dim3 blk(256);

    // 1) value projections -> g_vproj (sel 0), scattered by level/batch
    {
        const float* vs[3]  = {v0, v1, v2};
        const int    hws[3] = {10000, 2500, 625};
        const int    lofs[3]= {0, 10000, 12500};
        for (int l = 0; l < 3; l++) {
            int M = BATCH * hws[l];
            dim3 grid((M + 63) / 64, (DMODEL + 63) / 64);
            sgemm_bias<<<grid, blk>>>(vs[l], -1, W_val, b_val,
                                      nullptr, 0, M, DMODEL, DMODEL,
                                      hws[l], lofs[l]);
        }
    }

    // 2) sampling offsets: query @ W_off + b_off -> g_off (sel 1)
    {
        dim3 grid((MQ + 63) / 64, (192 + 63) / 64);
        sgemm_bias<<<grid, blk>>>(query, -1, W_off, b_off,
                                  nullptr, 1, MQ, 192, DMODEL, 0, 0);
    }

    // 3) attention logits: query @ W_attn + b_attn -> g_attnl (sel 2)
    {
        dim3 grid((MQ + 63) / 64, (96 + 63) / 64);
        sgemm_bias<<<grid, blk>>>(query, -1, W_attn, b_attn,
                                  nullptr, 2, MQ, 96, DMODEL, 0, 0);
    }

    // 4) fused softmax + deformable bilinear sampling -> g_mid
    msda_sample<<<MQ, blk>>>(rp);

    // 5) output projection: g_mid @ W_out + b_out -> d_out
    {
        dim3 grid((MQ + 63) / 64, (DMODEL + 63) / 64);
        sgemm_bias<<<grid, blk>>>(nullptr, 3, W_out, b_out,
                                  out, -1, MQ, DMODEL, DMODEL, 0, 0);
    }
}

// round 4
// speedup vs baseline: 1.4063x; 1.4063x over previous
#include <cuda_runtime.h>
#include <cuda_bf16.h>
#include <math.h>
#include <stdint.h>

// ---------------- problem constants ----------------
#define NQ      13125
#define BATCH   2
#define MQ      (BATCH * NQ)     // 26250
#define DMODEL  256
#define HEADS   8
#define HD      32
#define LVL     3
#define PTS     4

__device__ __constant__ int c_HL[LVL]   = {100, 50, 25};
__device__ __constant__ int c_WL[LVL]   = {100, 50, 25};
__device__ __constant__ int c_LOFF[LVL] = {0, 10000, 12500};

// ---------------- scratch (static device memory; no allocation) ----------------
__device__ __nv_bfloat16 g_qhi[(size_t)MQ * 256], g_qlo[(size_t)MQ * 256];
__device__ __nv_bfloat16 g_vhi[(size_t)MQ * 256], g_vlo[(size_t)MQ * 256];
__device__ __nv_bfloat16 g_mhi[(size_t)MQ * 256], g_mlo[(size_t)MQ * 256];
__device__ float g_vproj[(size_t)MQ * 256];   // projected values (fp32, for sampler)
__device__ float g_qout [(size_t)MQ * 320];   // [0..191]=offsets, [192..287]=logits, pad
// transposed weights, bf16 hi/lo, [row][k], rows: 0..255 = W_val^T, 256..575 = [W_off;W_attn;pad]^T, 576..831 = W_out^T
__device__ __nv_bfloat16 g_bthi[832 * 256], g_btlo[832 * 256];
__device__ float g_biasq[320];

// ---------------- small helpers ----------------
__device__ __forceinline__ uint32_t smem_to_u32(const void* p) {
    uint32_t a;
    asm("{ .reg .u64 t; cvta.to.shared.u64 t, %1; cvt.u32.u64 %0, t; }" : "=r"(a) : "l"(p));
    return a;
}
__device__ __forceinline__ void ldm4(uint32_t* f, uint32_t addr) {
    asm volatile("ldmatrix.sync.aligned.m8n8.x4.shared.b16 {%0,%1,%2,%3}, [%4];"
                 : "=r"(f[0]), "=r"(f[1]), "=r"(f[2]), "=r"(f[3]) : "r"(addr));
}
__device__ __forceinline__ void mma16816(float* d, const uint32_t* a, const uint32_t* b) {
    asm volatile("mma.sync.aligned.m16n8k16.row.col.f32.bf16.bf16.f32 "
                 "{%0,%1,%2,%3}, {%4,%5,%6,%7}, {%8,%9}, {%0,%1,%2,%3};"
                 : "+f"(d[0]), "+f"(d[1]), "+f"(d[2]), "+f"(d[3])
                 : "r"(a[0]), "r"(a[1]), "r"(a[2]), "r"(a[3]), "r"(b[0]), "r"(b[1]));
}
__device__ __forceinline__ void split2(float x, float y, __nv_bfloat162& hi, __nv_bfloat162& lo) {
    hi = __floats2bfloat162_rn(x, y);
    float rx = x - __bfloat162float(hi.x);
    float ry = y - __bfloat162float(hi.y);
    lo = __floats2bfloat162_rn(rx, ry);
}

// ---------------- convert kernels: fp32 -> bf16 hi/lo ----------------
__global__ void convert_q(const float* __restrict__ src) {
    size_t i = (size_t)blockIdx.x * 256 + threadIdx.x;   // one float4 per thread
    if (i >= (size_t)MQ * 64) return;
    float4 v = ((const float4*)src)[i];
    __nv_bfloat162 h0, l0, h1, l1;
    split2(v.x, v.y, h0, l0);
    split2(v.z, v.w, h1, l1);
    ((__nv_bfloat162*)g_qhi)[i * 2 + 0] = h0; ((__nv_bfloat162*)g_qhi)[i * 2 + 1] = h1;
    ((__nv_bfloat162*)g_qlo)[i * 2 + 0] = l0; ((__nv_bfloat162*)g_qlo)[i * 2 + 1] = l1;
}
__global__ void convert_v(const float* __restrict__ v0, const float* __restrict__ v1,
                          const float* __restrict__ v2) {
    size_t i = (size_t)blockIdx.x * 256 + threadIdx.x;
    if (i >= (size_t)MQ * 64) return;
    int row = (int)(i >> 6), c = (int)(i & 63);
    const float4* src;
    if (row < 20000)      src = (const float4*)(v0 + (size_t)row * 256);
    else if (row < 25000) src = (const float4*)(v1 + (size_t)(row - 20000) * 256);
    else                  src = (const float4*)(v2 + (size_t)(row - 25000) * 256);
    float4 v = src[c];
    __nv_bfloat162 h0, l0, h1, l1;
    split2(v.x, v.y, h0, l0);
    split2(v.z, v.w, h1, l1);
    ((__nv_bfloat162*)g_vhi)[i * 2 + 0] = h0; ((__nv_bfloat162*)g_vhi)[i * 2 + 1] = h1;
    ((__nv_bfloat162*)g_vlo)[i * 2 + 0] = l0; ((__nv_bfloat162*)g_vlo)[i * 2 + 1] = l1;
}

// ---------------- weight transpose + convert: BT[btrow+n][k] = W[k][n] ----------------
__global__ void wtrans(const float* __restrict__ W, int btrow, int N) {
    __shared__ float t[32][33];
    const int n0 = blockIdx.x * 32, k0 = blockIdx.y * 32;
    #pragma unroll
    for (int j = 0; j < 4; j++) {
        int k = k0 + threadIdx.y + 8 * j;
        int n = n0 + threadIdx.x;
        t[threadIdx.y + 8 * j][threadIdx.x] = W[(size_t)k * N + n];
    }
    __syncthreads();
    #pragma unroll
    for (int j = 0; j < 4; j++) {
        int n = n0 + threadIdx.y + 8 * j;
        int k = k0 + threadIdx.x;
        float x = t[threadIdx.x][threadIdx.y + 8 * j];
        __nv_bfloat16 hi = __float2bfloat16_rn(x);
        g_bthi[(size_t)(btrow + n) * 256 + k] = hi;
        g_btlo[(size_t)(btrow + n) * 256 + k] = __float2bfloat16_rn(x - __bfloat162float(hi));
    }
}
// zero pad rows 288..319 of the combined q-weight block; build combined bias
__global__ void fixup(const float* __restrict__ b_off, const float* __restrict__ b_attn) {
    int i = blockIdx.x * 256 + threadIdx.x;
    if (i < 32 * 256) {
        g_bthi[(size_t)(256 + 288) * 256 + i] = __float2bfloat16_rn(0.f);
        g_btlo[(size_t)(256 + 288) * 256 + i] = __float2bfloat16_rn(0.f);
    }
    if (i < 320)
        g_biasq[i] = (i < 192) ? b_off[i] : (i < 288 ? b_attn[i - 192] : 0.f);
}

// ---------------- split-bf16 tensor-core GEMM ----------------
// C[M,N] = Ah@Bh + Al@Bh + Ah@Bl + bias.  A: [M][256] bf16 hi/lo, B: [N][256] bf16 hi/lo (K-major).
// BM=128, BN=64, BK=32; 8 warps in 4(M)x2(N); 32x32 warp tile via m16n8k16.
#define ASTR 40   // smem row stride in halves (80B, conflict-free for ldmatrix)
__global__ __launch_bounds__(256, 2)
void gemm_bf16(int asel, int btoff, const float* __restrict__ biasp, int biassel,
               float* __restrict__ Cout, int csel, int M, int N, int remap)
{
    __shared__ __align__(16) __nv_bfloat16 sAh[128 * ASTR];
    __shared__ __align__(16) __nv_bfloat16 sAl[128 * ASTR];
    __shared__ __align__(16) __nv_bfloat16 sBh[64 * ASTR];
    __shared__ __align__(16) __nv_bfloat16 sBl[64 * ASTR];

    const __nv_bfloat16 *Ahi, *Alo;
    if (asel == 0)      { Ahi = g_qhi; Alo = g_qlo; }
    else if (asel == 1) { Ahi = g_vhi; Alo = g_vlo; }
    else                { Ahi = g_mhi; Alo = g_mlo; }
    const __nv_bfloat16* Bhi = g_bthi + (size_t)btoff * 256;
    const __nv_bfloat16* Blo = g_btlo + (size_t)btoff * 256;
    float* C = (csel == 0) ? g_vproj : (csel == 1 ? g_qout : Cout);
    const float* bias = biassel ? g_biasq : biasp;

    const int tid = threadIdx.x, lane = tid & 31, wid = tid >> 5;
    const int wm = wid >> 1, wn = wid & 1;
    const int row0 = blockIdx.x * 128, n0 = blockIdx.y * 64;

    const uint32_t uAh = smem_to_u32(sAh), uAl = smem_to_u32(sAl);
    const uint32_t uBh = smem_to_u32(sBh), uBl = smem_to_u32(sBl);

    const int lr = tid >> 2;           // load row (A: +0/+64; B: 0..63)
    const int lc = tid & 3;            // 16B chunk within 64B row

    uint4 rah[2], ral[2], rbh, rbl;
    const uint4 Z = make_uint4(0u, 0u, 0u, 0u);

    // prologue: load kt=0
    #pragma unroll
    for (int t = 0; t < 2; t++) {
        int gr = row0 + lr + t * 64;
        if (gr < M) {
            size_t o = (size_t)gr * 256 + lc * 8;
            rah[t] = *(const uint4*)(Ahi + o);
            ral[t] = *(const uint4*)(Alo + o);
        } else { rah[t] = Z; ral[t] = Z; }
    }
    {
        size_t o = (size_t)(n0 + lr) * 256 + lc * 8;
        rbh = *(const uint4*)(Bhi + o);
        rbl = *(const uint4*)(Blo + o);
    }

    float acc[2][4][4] = {};

    #pragma unroll 1
    for (int kt = 0; kt < 8; kt++) {
        if (kt) __syncthreads();
        // store staged regs -> smem
        #pragma unroll
        for (int t = 0; t < 2; t++) {
            int r = lr + t * 64;
            *(uint4*)(&sAh[r * ASTR + lc * 8]) = rah[t];
            *(uint4*)(&sAl[r * ASTR + lc * 8]) = ral[t];
        }
        *(uint4*)(&sBh[lr * ASTR + lc * 8]) = rbh;
        *(uint4*)(&sBl[lr * ASTR + lc * 8]) = rbl;
        __syncthreads();

        // prefetch next k-tile
        if (kt < 7) {
            const int k0 = (kt + 1) * 32;
            #pragma unroll
            for (int t = 0; t < 2; t++) {
                int gr = row0 + lr + t * 64;
                if (gr < M) {
                    size_t o = (size_t)gr * 256 + k0 + lc * 8;
                    rah[t] = *(const uint4*)(Ahi + o);
                    ral[t] = *(const uint4*)(Alo + o);
                } else { rah[t] = Z; ral[t] = Z; }
            }
            size_t o = (size_t)(n0 + lr) * 256 + k0 + lc * 8;
            rbh = *(const uint4*)(Bhi + o);
            rbl = *(const uint4*)(Blo + o);
        }

        // compute: 2 ksteps of k=16
        const int lrow = lane & 15, lkc = lane >> 4;
        #pragma unroll
        for (int kk = 0; kk < 2; kk++) {
            uint32_t fah[2][4], fal[2][4], fbh[2][4], fbl[2][4];
            #pragma unroll
            for (int mt = 0; mt < 2; mt++) {
                uint32_t off = (uint32_t)(((wm * 32 + mt * 16 + lrow) * ASTR + kk * 16 + lkc * 8) * 2);
                ldm4(fah[mt], uAh + off);
                ldm4(fal[mt], uAl + off);
            }
            #pragma unroll
            for (int ng = 0; ng < 2; ng++) {
                uint32_t off = (uint32_t)(((wn * 32 + ng * 16 + lrow) * ASTR + kk * 16 + lkc * 8) * 2);
                ldm4(fbh[ng], uBh + off);
                ldm4(fbl[ng], uBl + off);
            }
            #pragma unroll
            for (int mt = 0; mt < 2; mt++) {
                #pragma unroll
                for (int n = 0; n < 4; n++) {
                    uint32_t bh[2] = { fbh[n >> 1][n & 1], fbh[n >> 1][(n & 1) + 2] };
                    uint32_t bl[2] = { fbl[n >> 1][n & 1], fbl[n >> 1][(n & 1) + 2] };
                    mma16816(acc[mt][n], fah[mt], bh);
                    mma16816(acc[mt][n], fal[mt], bh);
                    mma16816(acc[mt][n], fah[mt], bl);
                }
            }
        }
    }

    // epilogue
    const int er = lane >> 2, ec = (lane & 3) * 2;
    #pragma unroll
    for (int mt = 0; mt < 2; mt++) {
        #pragma unroll
        for (int n = 0; n < 4; n++) {
            int col = n0 + wn * 32 + n * 8 + ec;
            float b0 = __ldg(bias + col), b1 = __ldg(bias + col + 1);
            #pragma unroll
            for (int h2 = 0; h2 < 2; h2++) {
                int row = row0 + wm * 32 + mt * 16 + er + 8 * h2;
                if (row < M) {
                    int orow = row;
                    if (remap) {
                        if (row < 20000)      orow = (row / 10000) * NQ + (row % 10000);
                        else if (row < 25000) { int rr = row - 20000; orow = (rr / 2500) * NQ + 10000 + rr % 2500; }
                        else                  { int rr = row - 25000; orow = (rr / 625)  * NQ + 12500 + rr % 625; }
                    }
                    float2 o = make_float2(acc[mt][n][2 * h2] + b0, acc[mt][n][2 * h2 + 1] + b1);
                    *(float2*)(C + (size_t)orow * N + col) = o;
                }
            }
        }
    }
}

// ---------------- fused softmax + deformable bilinear sampling ----------------
// reads g_qout (offsets cols 0..191, logits cols 192..287), writes g_mhi/g_mlo (bf16 hi/lo)
__global__ __launch_bounds__(256, 8)
void msda_sample(const float* __restrict__ rp)
{
    const int bq   = blockIdx.x;
    const int h    = threadIdx.x >> 5;
    const int lane = threadIdx.x & 31;
    const int b    = bq / NQ;

    float lv = -1e30f;
    if (lane < LVL * PTS)
        lv = g_qout[(size_t)bq * 320 + 192 + h * 12 + lane];
    float m = lv;
    #pragma unroll
    for (int o = 16; o; o >>= 1) m = fmaxf(m, __shfl_xor_sync(0xffffffffu, m, o));
    float e = (lane < LVL * PTS) ? __expf(lv - m) : 0.f;
    float s = e;
    #pragma unroll
    for (int o = 16; o; o >>= 1) s += __shfl_xor_sync(0xffffffffu, s, o);
    const float prob = e / s;

    const float* offp = g_qout + (size_t)bq * 320 + h * 24;
    float acc = 0.f;

    #pragma unroll
    for (int l = 0; l < LVL; l++) {
        const int   Wi = c_WL[l], Hi = c_HL[l];
        const float Wf = (float)Wi, Hf = (float)Hi;
        const float rx = rp[(size_t)bq * (LVL * 2) + l * 2 + 0];
        const float ry = rp[(size_t)bq * (LVL * 2) + l * 2 + 1];
        const float* vbase = g_vproj + ((size_t)(b * NQ + c_LOFF[l])) * DMODEL + h * HD + lane;

        #pragma unroll
        for (int p = 0; p < PTS; p++) {
            const float a  = __shfl_sync(0xffffffffu, prob, l * PTS + p);
            const float ox = offp[l * 8 + p * 2 + 0];
            const float oy = offp[l * 8 + p * 2 + 1];
            const float locx = rx + ox / Wf;
            const float locy = ry + oy / Hf;
            const float x = locx * Wf - 0.5f;
            const float y = locy * Hf - 0.5f;
            const float x0f = floorf(x), y0f = floorf(y);
            const float wx1 = x - x0f,  wy1 = y - y0f;
            const int ix0 = (int)x0f, iy0 = (int)y0f;

            float sv = 0.f;
            #pragma unroll
            for (int cy = 0; cy < 2; cy++) {
                const int   iy = iy0 + cy;
                const float wy = cy ? wy1 : (1.f - wy1);
                if (iy < 0 || iy >= Hi) continue;
                #pragma unroll
                for (int cx = 0; cx < 2; cx++) {
                    const int   ix = ix0 + cx;
                    const float wx = cx ? wx1 : (1.f - wx1);
                    if (ix < 0 || ix >= Wi) continue;
                    sv = fmaf(wx * wy, vbase[(size_t)(iy * Wi + ix) * DMODEL], sv);
                }
            }
            acc = fmaf(a, sv, acc);
        }
    }
    const size_t oi = (size_t)bq * DMODEL + h * HD + lane;
    __nv_bfloat16 hi = __float2bfloat16_rn(acc);
    g_mhi[oi] = hi;
    g_mlo[oi] = __float2bfloat16_rn(acc - __bfloat162float(hi));
}

// ---------------- launch ----------------
extern "C" void kernel_launch(void* const* d_in, const int* in_sizes, int n_in,
                              void* d_out, int out_size)
{
    const float* query  = (const float*)d_in[0];
    const float* rp     = (const float*)d_in[1];
    const float* v0     = (const float*)d_in[2];
    const float* v1     = (const float*)d_in[3];
    const float* v2     = (const float*)d_in[4];
    const float* W_val  = (const float*)d_in[5];
    const float* b_val  = (const float*)d_in[6];
    const float* W_off  = (const float*)d_in[7];
    const float* b_off  = (const float*)d_in[8];
    const float* W_attn = (const float*)d_in[9];
    const float* b_attn = (const float*)d_in[10];
    const float* W_out  = (const float*)d_in[11];
    const float* b_out  = (const float*)d_in[12];
    float* out = (float*)d_out;

    const int cgrid = (MQ * 64 + 255) / 256;   // 6563

    // converts + weight prep (independent)
    convert_q<<<cgrid, 256>>>(query);
    convert_v<<<cgrid, 256>>>(v0, v1, v2);
    {
        dim3 tb(32, 8);
        wtrans<<<dim3(8, 8), tb>>>(W_val,  0,   256);
        wtrans<<<dim3(6, 8), tb>>>(W_off,  256, 192);
        wtrans<<<dim3(3, 8), tb>>>(W_attn, 448, 96);
        wtrans<<<dim3(8, 8), tb>>>(W_out,  576, 256);
        fixup<<<32, 256>>>(b_off, b_attn);
    }

    // value projection (all levels, one launch), scattered rows -> g_vproj
    gemm_bf16<<<dim3(206, 4), 256>>>(1, 0, b_val, 0, nullptr, 0, MQ, 256, 1);
    // combined offsets+logits projection -> g_qout (N padded to 320)
    gemm_bf16<<<dim3(206, 5), 256>>>(0, 256, nullptr, 1, nullptr, 1, MQ, 320, 0);
    // fused softmax + sampling -> g_mhi/g_mlo
    msda_sample<<<MQ, 256>>>(rp);
    // output projection -> d_out
    gemm_bf16<<<dim3(206, 4), 256>>>(2, 576, b_out, 0, out, -1, MQ, 256, 0);
}

// round 5
// speedup vs baseline: 1.4407x; 1.0245x over previous
#include <cuda_runtime.h>
#include <cuda_bf16.h>
#include <math.h>
#include <stdint.h>

// ---------------- problem constants ----------------
#define NQ      13125
#define BATCH   2
#define MQ      (BATCH * NQ)     // 26250
#define DMODEL  256
#define HEADS   8
#define HD      32
#define LVL     3
#define PTS     4

__device__ __constant__ int c_HL[LVL]   = {100, 50, 25};
__device__ __constant__ int c_WL[LVL]   = {100, 50, 25};
__device__ __constant__ int c_LOFF[LVL] = {0, 10000, 12500};

// ---------------- scratch (static device memory; no allocation) ----------------
__device__ __nv_bfloat16 g_qhi[(size_t)MQ * 256], g_qlo[(size_t)MQ * 256];
__device__ __nv_bfloat16 g_vhi[(size_t)MQ * 256], g_vlo[(size_t)MQ * 256];
__device__ __nv_bfloat16 g_mhi[(size_t)MQ * 256], g_mlo[(size_t)MQ * 256];
__device__ float g_vproj[(size_t)MQ * 256];   // projected values (fp32, for sampler)
__device__ float g_qout [(size_t)MQ * 320];   // [0..191]=offsets, [192..287]=logits, pad
// transposed weights, bf16 hi/lo, [row][k]; rows: 0..255 W_val^T, 256..575 [W_off;W_attn;pad]^T, 576..831 W_out^T
__device__ __nv_bfloat16 g_bthi[832 * 256], g_btlo[832 * 256];
__device__ float g_biasq[320];

// ---------------- small helpers ----------------
__device__ __forceinline__ uint32_t smem_to_u32(const void* p) {
    uint32_t a;
    asm("{ .reg .u64 t; cvta.to.shared.u64 t, %1; cvt.u32.u64 %0, t; }" : "=r"(a) : "l"(p));
    return a;
}
__device__ __forceinline__ void ldm4(uint32_t* f, uint32_t addr) {
    asm volatile("ldmatrix.sync.aligned.m8n8.x4.shared.b16 {%0,%1,%2,%3}, [%4];"
                 : "=r"(f[0]), "=r"(f[1]), "=r"(f[2]), "=r"(f[3]) : "r"(addr));
}
__device__ __forceinline__ void mma16816(float* d, const uint32_t* a, const uint32_t* b) {
    asm volatile("mma.sync.aligned.m16n8k16.row.col.f32.bf16.bf16.f32 "
                 "{%0,%1,%2,%3}, {%4,%5,%6,%7}, {%8,%9}, {%0,%1,%2,%3};"
                 : "+f"(d[0]), "+f"(d[1]), "+f"(d[2]), "+f"(d[3])
                 : "r"(a[0]), "r"(a[1]), "r"(a[2]), "r"(a[3]), "r"(b[0]), "r"(b[1]));
}
__device__ __forceinline__ void cpa16(uint32_t dst, const void* src, int bytes) {
    asm volatile("cp.async.cg.shared.global [%0], [%1], 16, %2;"
                 :: "r"(dst), "l"(src), "r"(bytes) : "memory");
}
__device__ __forceinline__ void split2(float x, float y, __nv_bfloat162& hi, __nv_bfloat162& lo) {
    hi = __floats2bfloat162_rn(x, y);
    float rx = x - __bfloat162float(hi.x);
    float ry = y - __bfloat162float(hi.y);
    lo = __floats2bfloat162_rn(rx, ry);
}

// ---------------- convert kernels: fp32 -> bf16 hi/lo ----------------
__global__ void convert_q(const float* __restrict__ src) {
    size_t i = (size_t)blockIdx.x * 256 + threadIdx.x;
    if (i >= (size_t)MQ * 64) return;
    float4 v = ((const float4*)src)[i];
    __nv_bfloat162 h0, l0, h1, l1;
    split2(v.x, v.y, h0, l0);
    split2(v.z, v.w, h1, l1);
    ((__nv_bfloat162*)g_qhi)[i * 2 + 0] = h0; ((__nv_bfloat162*)g_qhi)[i * 2 + 1] = h1;
    ((__nv_bfloat162*)g_qlo)[i * 2 + 0] = l0; ((__nv_bfloat162*)g_qlo)[i * 2 + 1] = l1;
}
__global__ void convert_v(const float* __restrict__ v0, const float* __restrict__ v1,
                          const float* __restrict__ v2) {
    size_t i = (size_t)blockIdx.x * 256 + threadIdx.x;
    if (i >= (size_t)MQ * 64) return;
    int row = (int)(i >> 6), c = (int)(i & 63);
    const float4* src;
    if (row < 20000)      src = (const float4*)(v0 + (size_t)row * 256);
    else if (row < 25000) src = (const float4*)(v1 + (size_t)(row - 20000) * 256);
    else                  src = (const float4*)(v2 + (size_t)(row - 25000) * 256);
    float4 v = src[c];
    __nv_bfloat162 h0, l0, h1, l1;
    split2(v.x, v.y, h0, l0);
    split2(v.z, v.w, h1, l1);
    ((__nv_bfloat162*)g_vhi)[i * 2 + 0] = h0; ((__nv_bfloat162*)g_vhi)[i * 2 + 1] = h1;
    ((__nv_bfloat162*)g_vlo)[i * 2 + 0] = l0; ((__nv_bfloat162*)g_vlo)[i * 2 + 1] = l1;
}

// ---------------- weight transpose + convert: BT[btrow+n][k] = W[k][n] ----------------
__global__ void wtrans(const float* __restrict__ W, int btrow, int N) {
    __shared__ float t[32][33];
    const int n0 = blockIdx.x * 32, k0 = blockIdx.y * 32;
    #pragma unroll
    for (int j = 0; j < 4; j++) {
        int k = k0 + threadIdx.y + 8 * j;
        int n = n0 + threadIdx.x;
        t[threadIdx.y + 8 * j][threadIdx.x] = W[(size_t)k * N + n];
    }
    __syncthreads();
    #pragma unroll
    for (int j = 0; j < 4; j++) {
        int n = n0 + threadIdx.y + 8 * j;
        int k = k0 + threadIdx.x;
        float x = t[threadIdx.x][threadIdx.y + 8 * j];
        __nv_bfloat16 hi = __float2bfloat16_rn(x);
        g_bthi[(size_t)(btrow + n) * 256 + k] = hi;
        g_btlo[(size_t)(btrow + n) * 256 + k] = __float2bfloat16_rn(x - __bfloat162float(hi));
    }
}
__global__ void fixup(const float* __restrict__ b_off, const float* __restrict__ b_attn) {
    int i = blockIdx.x * 256 + threadIdx.x;
    if (i < 32 * 256) {
        g_bthi[(size_t)(256 + 288) * 256 + i] = __float2bfloat16_rn(0.f);
        g_btlo[(size_t)(256 + 288) * 256 + i] = __float2bfloat16_rn(0.f);
    }
    if (i < 320)
        g_biasq[i] = (i < 192) ? b_off[i] : (i < 288 ? b_attn[i - 192] : 0.f);
}

// ---------------- split-bf16 tensor-core GEMM, cp.async double-buffered ----------------
// C[M,N] = Ah@Bh + Al@Bh (+ Ah@Bl if nterms==3) + bias.
// BM=128, BN=64, BK=32; 8 warps 4(M)x2(N); 32x32 warp tile via m16n8k16.
#define ASTR 40                              // smem row stride in halves (80B)
#define A_HALVES (128 * ASTR)                // 5120
#define B_HALVES (64 * ASTR)                 // 2560
#define STG_HALVES (2 * A_HALVES + 2 * B_HALVES)   // 15360
#define OFF_AH 0
#define OFF_AL A_HALVES
#define OFF_BH (2 * A_HALVES)
#define OFF_BL (2 * A_HALVES + B_HALVES)
#define GEMM_DYNSMEM (2 * STG_HALVES * 2)    // 61440 bytes

__global__ __launch_bounds__(256, 2)
void gemm_bf16(int asel, int btoff, const float* __restrict__ biasp, int biassel,
               float* __restrict__ Cout, int csel, int M, int N, int remap, int nterms)
{
    extern __shared__ __align__(16) __nv_bfloat16 dsm[];
    const uint32_t sbase = smem_to_u32(dsm);

    const __nv_bfloat16 *Ahi, *Alo;
    if (asel == 0)      { Ahi = g_qhi; Alo = g_qlo; }
    else if (asel == 1) { Ahi = g_vhi; Alo = g_vlo; }
    else                { Ahi = g_mhi; Alo = g_mlo; }
    const __nv_bfloat16* Bhi = g_bthi + (size_t)btoff * 256;
    const __nv_bfloat16* Blo = g_btlo + (size_t)btoff * 256;
    float* C = (csel == 0) ? g_vproj : (csel == 1 ? g_qout : Cout);
    const float* bias = biassel ? g_biasq : biasp;

    const int tid = threadIdx.x, lane = tid & 31, wid = tid >> 5;
    const int wm = wid >> 1, wn = wid & 1;
    const int row0 = blockIdx.x * 128, n0 = blockIdx.y * 64;
    const int lr = tid >> 2, lc = tid & 3;    // loader row / 16B-chunk

    auto issue = [&](int kt) {
        const int s = kt & 1;
        const uint32_t st = sbase + (uint32_t)(s * STG_HALVES * 2);
        const int k0 = kt * 32;
        #pragma unroll
        for (int t = 0; t < 2; t++) {
            const int r  = lr + t * 64;
            const int gr = row0 + r;
            const bool v = (gr < M);
            const size_t go = (size_t)(v ? gr : 0) * 256 + k0 + lc * 8;
            const uint32_t so = (uint32_t)((r * ASTR + lc * 8) * 2);
            cpa16(st + OFF_AH * 2 + so, Ahi + go, v ? 16 : 0);
            cpa16(st + OFF_AL * 2 + so, Alo + go, v ? 16 : 0);
        }
        {
            const size_t go = (size_t)(n0 + lr) * 256 + k0 + lc * 8;
            const uint32_t so = (uint32_t)((lr * ASTR + lc * 8) * 2);
            cpa16(st + OFF_BH * 2 + so, Bhi + go, 16);
            if (nterms == 3) cpa16(st + OFF_BL * 2 + so, Blo + go, 16);
        }
        asm volatile("cp.async.commit_group;" ::: "memory");
    };

    float acc[2][4][4] = {};

    issue(0);
    #pragma unroll 1
    for (int kt = 0; kt < 8; kt++) {
        if (kt < 7) {
            issue(kt + 1);
            asm volatile("cp.async.wait_group 1;" ::: "memory");
        } else {
            asm volatile("cp.async.wait_group 0;" ::: "memory");
        }
        __syncthreads();

        const uint32_t st = sbase + (uint32_t)((kt & 1) * STG_HALVES * 2);
        const uint32_t uAh = st + OFF_AH * 2, uAl = st + OFF_AL * 2;
        const uint32_t uBh = st + OFF_BH * 2, uBl = st + OFF_BL * 2;
        const int lrow = lane & 15, lkc = lane >> 4;

        #pragma unroll
        for (int kk = 0; kk < 2; kk++) {
            uint32_t fah[2][4], fal[2][4], fbh[2][4], fbl[2][4];
            #pragma unroll
            for (int mt = 0; mt < 2; mt++) {
                uint32_t off = (uint32_t)(((wm * 32 + mt * 16 + lrow) * ASTR + kk * 16 + lkc * 8) * 2);
                ldm4(fah[mt], uAh + off);
                ldm4(fal[mt], uAl + off);
            }
            #pragma unroll
            for (int ng = 0; ng < 2; ng++) {
                uint32_t off = (uint32_t)(((wn * 32 + ng * 16 + lrow) * ASTR + kk * 16 + lkc * 8) * 2);
                ldm4(fbh[ng], uBh + off);
                if (nterms == 3) ldm4(fbl[ng], uBl + off);
            }
            #pragma unroll
            for (int mt = 0; mt < 2; mt++) {
                #pragma unroll
                for (int n = 0; n < 4; n++) {
                    uint32_t bh[2] = { fbh[n >> 1][n & 1], fbh[n >> 1][(n & 1) + 2] };
                    mma16816(acc[mt][n], fah[mt], bh);
                    mma16816(acc[mt][n], fal[mt], bh);
                    if (nterms == 3) {
                        uint32_t bl[2] = { fbl[n >> 1][n & 1], fbl[n >> 1][(n & 1) + 2] };
                        mma16816(acc[mt][n], fah[mt], bl);
                    }
                }
            }
        }
        __syncthreads();
    }

    // epilogue
    const int er = lane >> 2, ec = (lane & 3) * 2;
    #pragma unroll
    for (int mt = 0; mt < 2; mt++) {
        #pragma unroll
        for (int n = 0; n < 4; n++) {
            int col = n0 + wn * 32 + n * 8 + ec;
            float b0 = __ldg(bias + col), b1 = __ldg(bias + col + 1);
            #pragma unroll
            for (int h2 = 0; h2 < 2; h2++) {
                int row = row0 + wm * 32 + mt * 16 + er + 8 * h2;
                if (row < M) {
                    int orow = row;
                    if (remap) {
                        if (row < 20000)      orow = (row / 10000) * NQ + (row % 10000);
                        else if (row < 25000) { int rr = row - 20000; orow = (rr / 2500) * NQ + 10000 + rr % 2500; }
                        else                  { int rr = row - 25000; orow = (rr / 625)  * NQ + 12500 + rr % 625; }
                    }
                    float2 o = make_float2(acc[mt][n][2 * h2] + b0, acc[mt][n][2 * h2 + 1] + b1);
                    *(float2*)(C + (size_t)orow * N + col) = o;
                }
            }
        }
    }
}

// ---------------- fused softmax + deformable bilinear sampling ----------------
__global__ __launch_bounds__(256, 8)
void msda_sample(const float* __restrict__ rp)
{
    const int bq   = blockIdx.x;
    const int h    = threadIdx.x >> 5;
    const int lane = threadIdx.x & 31;
    const int b    = bq / NQ;

    float lv = -1e30f;
    if (lane < LVL * PTS)
        lv = g_qout[(size_t)bq * 320 + 192 + h * 12 + lane];
    float m = lv;
    #pragma unroll
    for (int o = 16; o; o >>= 1) m = fmaxf(m, __shfl_xor_sync(0xffffffffu, m, o));
    float e = (lane < LVL * PTS) ? __expf(lv - m) : 0.f;
    float s = e;
    #pragma unroll
    for (int o = 16; o; o >>= 1) s += __shfl_xor_sync(0xffffffffu, s, o);
    const float prob = e / s;

    const float* offp = g_qout + (size_t)bq * 320 + h * 24;
    float acc = 0.f;

    #pragma unroll
    for (int l = 0; l < LVL; l++) {
        const int   Wi = c_WL[l], Hi = c_HL[l];
        const float Wf = (float)Wi, Hf = (float)Hi;
        const float rx = rp[(size_t)bq * (LVL * 2) + l * 2 + 0];
        const float ry = rp[(size_t)bq * (LVL * 2) + l * 2 + 1];
        const float* vbase = g_vproj + ((size_t)(b * NQ + c_LOFF[l])) * DMODEL + h * HD + lane;

        #pragma unroll
        for (int p = 0; p < PTS; p++) {
            const float a  = __shfl_sync(0xffffffffu, prob, l * PTS + p);
            const float ox = offp[l * 8 + p * 2 + 0];
            const float oy = offp[l * 8 + p * 2 + 1];
            const float locx = rx + ox / Wf;
            const float locy = ry + oy / Hf;
            const float x = locx * Wf - 0.5f;
            const float y = locy * Hf - 0.5f;
            const float x0f = floorf(x), y0f = floorf(y);
            const float wx1 = x - x0f,  wy1 = y - y0f;
            const int ix0 = (int)x0f, iy0 = (int)y0f;

            float sv = 0.f;
            #pragma unroll
            for (int cy = 0; cy < 2; cy++) {
                const int   iy = iy0 + cy;
                const float wy = cy ? wy1 : (1.f - wy1);
                if (iy < 0 || iy >= Hi) continue;
                #pragma unroll
                for (int cx = 0; cx < 2; cx++) {
                    const int   ix = ix0 + cx;
                    const float wx = cx ? wx1 : (1.f - wx1);
                    if (ix < 0 || ix >= Wi) continue;
                    sv = fmaf(wx * wy, vbase[(size_t)(iy * Wi + ix) * DMODEL], sv);
                }
            }
            acc = fmaf(a, sv, acc);
        }
    }
    const size_t oi = (size_t)bq * DMODEL + h * HD + lane;
    __nv_bfloat16 hi = __float2bfloat16_rn(acc);
    g_mhi[oi] = hi;
    g_mlo[oi] = __float2bfloat16_rn(acc - __bfloat162float(hi));
}

// ---------------- launch ----------------
extern "C" void kernel_launch(void* const* d_in, const int* in_sizes, int n_in,
                              void* d_out, int out_size)
{
    const float* query  = (const float*)d_in[0];
    const float* rp     = (const float*)d_in[1];
    const float* v0     = (const float*)d_in[2];
    const float* v1     = (const float*)d_in[3];
    const float* v2     = (const float*)d_in[4];
    const float* W_val  = (const float*)d_in[5];
    const float* b_val  = (const float*)d_in[6];
    const float* W_off  = (const float*)d_in[7];
    const float* b_off  = (const float*)d_in[8];
    const float* W_attn = (const float*)d_in[9];
    const float* b_attn = (const float*)d_in[10];
    const float* W_out  = (const float*)d_in[11];
    const float* b_out  = (const float*)d_in[12];
    float* out = (float*)d_out;

    cudaFuncSetAttribute(gemm_bf16, cudaFuncAttributeMaxDynamicSharedMemorySize, GEMM_DYNSMEM);

    const int cgrid = (MQ * 64 + 255) / 256;   // 6563
    dim3 tb(32, 8);

    // ordered so the profiled launch (#6 in-stream) is the value-projection GEMM
    wtrans<<<dim3(8, 8), tb>>>(W_val,  0,   256);            // 1
    convert_v<<<cgrid, 256>>>(v0, v1, v2);                   // 2
    convert_q<<<cgrid, 256>>>(query);                        // 3
    wtrans<<<dim3(6, 8), tb>>>(W_off,  256, 192);            // 4
    wtrans<<<dim3(3, 8), tb>>>(W_attn, 448, 96);             // 5
    // 6: value projection (all levels), scattered rows -> g_vproj   [PROFILED]
    gemm_bf16<<<dim3(206, 4), 256, GEMM_DYNSMEM>>>(1, 0, b_val, 0, nullptr, 0, MQ, 256, 1, 3);
    wtrans<<<dim3(8, 8), tb>>>(W_out,  576, 256);            // 7
    fixup<<<32, 256>>>(b_off, b_attn);                       // 8
    // 9: combined offsets+logits projection -> g_qout (2-term split is ample here)
    gemm_bf16<<<dim3(206, 5), 256, GEMM_DYNSMEM>>>(0, 256, nullptr, 1, nullptr, 1, MQ, 320, 0, 2);
    // 10: fused softmax + sampling -> g_mhi/g_mlo
    msda_sample<<<MQ, 256>>>(rp);
    // 11: output projection -> d_out
    gemm_bf16<<<dim3(206, 4), 256, GEMM_DYNSMEM>>>(2, 576, b_out, 0, out, -1, MQ, 256, 0, 3);
}

// round 7
// speedup vs baseline: 1.4597x; 1.0131x over previous
#include <cuda_runtime.h>
#include <cuda_bf16.h>
#include <math.h>
#include <stdint.h>

// ---------------- problem constants ----------------
#define NQ      13125
#define BATCH   2
#define MQ      (BATCH * NQ)     // 26250
#define DMODEL  256
#define HEADS   8
#define HD      32
#define LVL     3
#define PTS     4

__device__ __constant__ int c_HL[LVL]   = {100, 50, 25};
__device__ __constant__ int c_WL[LVL]   = {100, 50, 25};
__device__ __constant__ int c_LOFF[LVL] = {0, 10000, 12500};

// ---------------- scratch (static device memory; no allocation) ----------------
__device__ __nv_bfloat16 g_qhi[(size_t)MQ * 256], g_qlo[(size_t)MQ * 256];
__device__ __nv_bfloat16 g_vhi[(size_t)MQ * 256], g_vlo[(size_t)MQ * 256];
__device__ __nv_bfloat16 g_mhi[(size_t)MQ * 256], g_mlo[(size_t)MQ * 256];
__device__ float g_vproj[(size_t)MQ * 256];   // projected values (fp32, for sampler)
__device__ float g_qout [(size_t)MQ * 320];   // [0..191]=offsets, [192..287]=logits, pad
// transposed weights, bf16 hi/lo, [row][k]; rows: 0..255 W_val^T, 256..575 [W_off;W_attn;pad]^T, 576..831 W_out^T
__device__ __nv_bfloat16 g_bthi[832 * 256], g_btlo[832 * 256];
__device__ float g_biasq[320];

// ---------------- small helpers ----------------
__device__ __forceinline__ uint32_t smem_to_u32(const void* p) {
    uint32_t a;
    asm("{ .reg .u64 t; cvta.to.shared.u64 t, %1; cvt.u32.u64 %0, t; }" : "=r"(a) : "l"(p));
    return a;
}
__device__ __forceinline__ void ldm4(uint32_t* f, uint32_t addr) {
    asm volatile("ldmatrix.sync.aligned.m8n8.x4.shared.b16 {%0,%1,%2,%3}, [%4];"
                 : "=r"(f[0]), "=r"(f[1]), "=r"(f[2]), "=r"(f[3]) : "r"(addr));
}
__device__ __forceinline__ void mma16816(float* d, const uint32_t* a, const uint32_t* b) {
    asm volatile("mma.sync.aligned.m16n8k16.row.col.f32.bf16.bf16.f32 "
                 "{%0,%1,%2,%3}, {%4,%5,%6,%7}, {%8,%9}, {%0,%1,%2,%3};"
                 : "+f"(d[0]), "+f"(d[1]), "+f"(d[2]), "+f"(d[3])
                 : "r"(a[0]), "r"(a[1]), "r"(a[2]), "r"(a[3]), "r"(b[0]), "r"(b[1]));
}
__device__ __forceinline__ void cpa16(uint32_t dst, const void* src, int bytes) {
    asm volatile("cp.async.cg.shared.global [%0], [%1], 16, %2;"
                 :: "r"(dst), "l"(src), "r"(bytes) : "memory");
}
__device__ __forceinline__ void split2(float x, float y, __nv_bfloat162& hi, __nv_bfloat162& lo) {
    hi = __floats2bfloat162_rn(x, y);
    float rx = x - __bfloat162float(hi.x);
    float ry = y - __bfloat162float(hi.y);
    lo = __floats2bfloat162_rn(rx, ry);
}

// ---------------- prep: activations fp32 -> bf16 hi/lo (q and v in one launch) ----------------
#define CBLK 6563   // ceil(MQ*64/256)
__global__ void prep_acts(const float* __restrict__ q, const float* __restrict__ v0,
                          const float* __restrict__ v1, const float* __restrict__ v2) {
    const int bid = blockIdx.x;
    const bool isq = (bid < CBLK);
    size_t i = (size_t)(isq ? bid : bid - CBLK) * 256 + threadIdx.x;
    if (i >= (size_t)MQ * 64) return;
    float4 v;
    if (isq) {
        v = ((const float4*)q)[i];
    } else {
        int row = (int)(i >> 6), c = (int)(i & 63);
        const float4* src;
        if (row < 20000)      src = (const float4*)(v0 + (size_t)row * 256);
        else if (row < 25000) src = (const float4*)(v1 + (size_t)(row - 20000) * 256);
        else                  src = (const float4*)(v2 + (size_t)(row - 25000) * 256);
        v = src[c];
    }
    __nv_bfloat162 h0, l0, h1, l1;
    split2(v.x, v.y, h0, l0);
    split2(v.z, v.w, h1, l1);
    __nv_bfloat16 *dh = isq ? g_qhi : g_vhi, *dl = isq ? g_qlo : g_vlo;
    ((__nv_bfloat162*)dh)[i * 2 + 0] = h0; ((__nv_bfloat162*)dh)[i * 2 + 1] = h1;
    ((__nv_bfloat162*)dl)[i * 2 + 0] = l0; ((__nv_bfloat162*)dl)[i * 2 + 1] = l1;
}

// ---------------- prep: all weight transposes + pad + combined bias, one launch ----------------
__global__ void prep_weights(const float* __restrict__ W_val, const float* __restrict__ W_off,
                             const float* __restrict__ W_attn, const float* __restrict__ W_out,
                             const float* __restrict__ b_off, const float* __restrict__ b_attn) {
    const int id = blockIdx.x;
    if (id >= 200) {   // fixup: zero pad rows 544..575 + combined bias (FLAT thread index!)
        const int t = threadIdx.y * 32 + threadIdx.x;
        const int i = (id - 200) * 256 + t;
        if (i < 32 * 256) {
            g_bthi[(size_t)544 * 256 + i] = __float2bfloat16_rn(0.f);
            g_btlo[(size_t)544 * 256 + i] = __float2bfloat16_rn(0.f);
        }
        if (i < 320)
            g_biasq[i] = (i < 192) ? b_off[i] : (i < 288 ? b_attn[i - 192] : 0.f);
        return;
    }
    const float* W; int btrow, N, tix;
    if (id < 64)       { W = W_val;  btrow = 0;   N = 256; tix = id;      }
    else if (id < 112) { W = W_off;  btrow = 256; N = 192; tix = id - 64; }
    else if (id < 136) { W = W_attn; btrow = 448; N = 96;  tix = id - 112;}
    else               { W = W_out;  btrow = 576; N = 256; tix = id - 136;}
    const int ntiles = N / 32;
    const int n0 = (tix % ntiles) * 32, k0 = (tix / ntiles) * 32;

    __shared__ float t[32][33];
    #pragma unroll
    for (int j = 0; j < 4; j++) {
        int k = k0 + threadIdx.y + 8 * j;
        int n = n0 + threadIdx.x;
        t[threadIdx.y + 8 * j][threadIdx.x] = W[(size_t)k * N + n];
    }
    __syncthreads();
    #pragma unroll
    for (int j = 0; j < 4; j++) {
        int n = n0 + threadIdx.y + 8 * j;
        int k = k0 + threadIdx.x;
        float x = t[threadIdx.x][threadIdx.y + 8 * j];
        __nv_bfloat16 hi = __float2bfloat16_rn(x);
        g_bthi[(size_t)(btrow + n) * 256 + k] = hi;
        g_btlo[(size_t)(btrow + n) * 256 + k] = __float2bfloat16_rn(x - __bfloat162float(hi));
    }
}

// ---------------- split-bf16 tensor-core GEMM, 3-stage cp.async pipeline ----------------
// C[M,N] = Ah@Bh + Al@Bh + Ah@Bl + bias.  BM=128, BN=64, BK=32; 8 warps 4(M)x2(N).
#define ASTR 40
#define A_HALVES (128 * ASTR)                      // 5120
#define B_HALVES (64 * ASTR)                       // 2560
#define STG_HALVES (2 * A_HALVES + 2 * B_HALVES)   // 15360
#define STG_BYTES  (STG_HALVES * 2)                // 30720
#define OFF_AH 0
#define OFF_AL A_HALVES
#define OFF_BH (2 * A_HALVES)
#define OFF_BL (2 * A_HALVES + B_HALVES)
#define GEMM_DYNSMEM (3 * STG_BYTES)               // 92160

__global__ __launch_bounds__(256, 2)
void gemm_bf16(int fusedvq, int asel_p, int btoff_p, const float* __restrict__ biasp,
               float* __restrict__ Cout, int M, int N_p, int remap_p)
{
    extern __shared__ __align__(16) __nv_bfloat16 dsm[];
    const uint32_t sbase = smem_to_u32(dsm);

    // resolve per-problem parameters (fused vproj+qout launch uses blockIdx.y split)
    int asel = asel_p, btoff = btoff_p, N = N_p, remap = remap_p, n0;
    const float* bias = biasp;
    float* C;
    if (fusedvq) {
        if (blockIdx.y < 4) { asel = 1; btoff = 0;   N = 256; remap = 1; n0 = blockIdx.y * 64;      C = g_vproj; }
        else                { asel = 0; btoff = 256; N = 320; remap = 0; n0 = (blockIdx.y - 4) * 64; C = g_qout; bias = g_biasq; }
    } else {
        n0 = blockIdx.y * 64;
        C = Cout;
    }

    const __nv_bfloat16 *Ahi, *Alo;
    if (asel == 0)      { Ahi = g_qhi; Alo = g_qlo; }
    else if (asel == 1) { Ahi = g_vhi; Alo = g_vlo; }
    else                { Ahi = g_mhi; Alo = g_mlo; }
    const __nv_bfloat16* Bhi = g_bthi + (size_t)btoff * 256;
    const __nv_bfloat16* Blo = g_btlo + (size_t)btoff * 256;

    const int tid = threadIdx.x, lane = tid & 31, wid = tid >> 5;
    const int wm = wid >> 1, wn = wid & 1;
    const int row0 = blockIdx.x * 128;
    const int lr = tid >> 2, lc = tid & 3;

    auto issue = [&](int kt) {
        const uint32_t st = sbase + (uint32_t)((kt % 3) * STG_BYTES);
        const int k0 = kt * 32;
        #pragma unroll
        for (int t = 0; t < 2; t++) {
            const int r  = lr + t * 64;
            const int gr = row0 + r;
            const bool v = (gr < M);
            const size_t go = (size_t)(v ? gr : 0) * 256 + k0 + lc * 8;
            const uint32_t so = (uint32_t)((r * ASTR + lc * 8) * 2);
            cpa16(st + OFF_AH * 2 + so, Ahi + go, v ? 16 : 0);
            cpa16(st + OFF_AL * 2 + so, Alo + go, v ? 16 : 0);
        }
        {
            const size_t go = (size_t)(n0 + lr) * 256 + k0 + lc * 8;
            const uint32_t so = (uint32_t)((lr * ASTR + lc * 8) * 2);
            cpa16(st + OFF_BH * 2 + so, Bhi + go, 16);
            cpa16(st + OFF_BL * 2 + so, Blo + go, 16);
        }
        asm volatile("cp.async.commit_group;" ::: "memory");
    };

    float acc[2][4][4] = {};

    issue(0);
    issue(1);
    #pragma unroll 1
    for (int kt = 0; kt < 8; kt++) {
        if (kt < 7) asm volatile("cp.async.wait_group 1;" ::: "memory");
        else        asm volatile("cp.async.wait_group 0;" ::: "memory");
        __syncthreads();
        if (kt + 2 < 8) issue(kt + 2);

        const uint32_t st = sbase + (uint32_t)((kt % 3) * STG_BYTES);
        const uint32_t uAh = st + OFF_AH * 2, uAl = st + OFF_AL * 2;
        const uint32_t uBh = st + OFF_BH * 2, uBl = st + OFF_BL * 2;
        const int lrow = lane & 15, lkc = lane >> 4;

        #pragma unroll
        for (int kk = 0; kk < 2; kk++) {
            uint32_t fah[2][4], fal[2][4], fbh[2][4], fbl[2][4];
            #pragma unroll
            for (int mt = 0; mt < 2; mt++) {
                uint32_t off = (uint32_t)(((wm * 32 + mt * 16 + lrow) * ASTR + kk * 16 + lkc * 8) * 2);
                ldm4(fah[mt], uAh + off);
                ldm4(fal[mt], uAl + off);
            }
            #pragma unroll
            for (int ng = 0; ng < 2; ng++) {
                uint32_t off = (uint32_t)(((wn * 32 + ng * 16 + lrow) * ASTR + kk * 16 + lkc * 8) * 2);
                ldm4(fbh[ng], uBh + off);
                ldm4(fbl[ng], uBl + off);
            }
            #pragma unroll
            for (int mt = 0; mt < 2; mt++) {
                #pragma unroll
                for (int n = 0; n < 4; n++) {
                    uint32_t bh[2] = { fbh[n >> 1][n & 1], fbh[n >> 1][(n & 1) + 2] };
                    uint32_t bl[2] = { fbl[n >> 1][n & 1], fbl[n >> 1][(n & 1) + 2] };
                    mma16816(acc[mt][n], fah[mt], bh);
                    mma16816(acc[mt][n], fal[mt], bh);
                    mma16816(acc[mt][n], fah[mt], bl);
                }
            }
        }
    }

    // epilogue
    const int er = lane >> 2, ec = (lane & 3) * 2;
    #pragma unroll
    for (int mt = 0; mt < 2; mt++) {
        #pragma unroll
        for (int n = 0; n < 4; n++) {
            int col = n0 + wn * 32 + n * 8 + ec;
            float b0 = __ldg(bias + col), b1 = __ldg(bias + col + 1);
            #pragma unroll
            for (int h2 = 0; h2 < 2; h2++) {
                int row = row0 + wm * 32 + mt * 16 + er + 8 * h2;
                if (row < M) {
                    int orow = row;
                    if (remap) {
                        if (row < 20000)      orow = (row / 10000) * NQ + (row % 10000);
                        else if (row < 25000) { int rr = row - 20000; orow = (rr / 2500) * NQ + 10000 + rr % 2500; }
                        else                  { int rr = row - 25000; orow = (rr / 625)  * NQ + 12500 + rr % 625; }
                    }
                    float2 o = make_float2(acc[mt][n][2 * h2] + b0, acc[mt][n][2 * h2 + 1] + b1);
                    *(float2*)(C + (size_t)orow * N + col) = o;
                }
            }
        }
    }
}

// ---------------- fused softmax + deformable bilinear sampling ----------------
__global__ __launch_bounds__(256, 8)
void msda_sample(const float* __restrict__ rp)
{
    const int bq   = blockIdx.x;
    const int h    = threadIdx.x >> 5;
    const int lane = threadIdx.x & 31;
    const int b    = bq / NQ;

    float lv = -1e30f;
    if (lane < LVL * PTS)
        lv = g_qout[(size_t)bq * 320 + 192 + h * 12 + lane];
    float m = lv;
    #pragma unroll
    for (int o = 16; o; o >>= 1) m = fmaxf(m, __shfl_xor_sync(0xffffffffu, m, o));
    float e = (lane < LVL * PTS) ? __expf(lv - m) : 0.f;
    float s = e;
    #pragma unroll
    for (int o = 16; o; o >>= 1) s += __shfl_xor_sync(0xffffffffu, s, o);
    const float prob = e / s;

    const float* offp = g_qout + (size_t)bq * 320 + h * 24;
    float acc = 0.f;

    #pragma unroll
    for (int l = 0; l < LVL; l++) {
        const int   Wi = c_WL[l], Hi = c_HL[l];
        const float Wf = (float)Wi, Hf = (float)Hi;
        const float rx = rp[(size_t)bq * (LVL * 2) + l * 2 + 0];
        const float ry = rp[(size_t)bq * (LVL * 2) + l * 2 + 1];
        const float* vbase = g_vproj + ((size_t)(b * NQ + c_LOFF[l])) * DMODEL + h * HD + lane;

        #pragma unroll
        for (int p = 0; p < PTS; p++) {
            const float a  = __shfl_sync(0xffffffffu, prob, l * PTS + p);
            const float ox = offp[l * 8 + p * 2 + 0];
            const float oy = offp[l * 8 + p * 2 + 1];
            const float locx = rx + ox / Wf;
            const float locy = ry + oy / Hf;
            const float x = locx * Wf - 0.5f;
            const float y = locy * Hf - 0.5f;
            const float x0f = floorf(x), y0f = floorf(y);
            const float wx1 = x - x0f,  wy1 = y - y0f;
            const int ix0 = (int)x0f, iy0 = (int)y0f;

            float sv = 0.f;
            #pragma unroll
            for (int cy = 0; cy < 2; cy++) {
                const int   iy = iy0 + cy;
                const float wy = cy ? wy1 : (1.f - wy1);
                if (iy < 0 || iy >= Hi) continue;
                #pragma unroll
                for (int cx = 0; cx < 2; cx++) {
                    const int   ix = ix0 + cx;
                    const float wx = cx ? wx1 : (1.f - wx1);
                    if (ix < 0 || ix >= Wi) continue;
                    sv = fmaf(wx * wy, vbase[(size_t)(iy * Wi + ix) * DMODEL], sv);
                }
            }
            acc = fmaf(a, sv, acc);
        }
    }
    const size_t oi = (size_t)bq * DMODEL + h * HD + lane;
    __nv_bfloat16 hi = __float2bfloat16_rn(acc);
    g_mhi[oi] = hi;
    g_mlo[oi] = __float2bfloat16_rn(acc - __bfloat162float(hi));
}

// ---------------- launch ----------------
extern "C" void kernel_launch(void* const* d_in, const int* in_sizes, int n_in,
                              void* d_out, int out_size)
{
    const float* query  = (const float*)d_in[0];
    const float* rp     = (const float*)d_in[1];
    const float* v0     = (const float*)d_in[2];
    const float* v1     = (const float*)d_in[3];
    const float* v2     = (const float*)d_in[4];
    const float* W_val  = (const float*)d_in[5];
    const float* b_val  = (const float*)d_in[6];
    const float* W_off  = (const float*)d_in[7];
    const float* b_off  = (const float*)d_in[8];
    const float* W_attn = (const float*)d_in[9];
    const float* b_attn = (const float*)d_in[10];
    const float* W_out  = (const float*)d_in[11];
    const float* b_out  = (const float*)d_in[12];
    float* out = (float*)d_out;

    cudaFuncSetAttribute(gemm_bf16, cudaFuncAttributeMaxDynamicSharedMemorySize, GEMM_DYNSMEM);

    // 1: all weight prep (4 transposes + pad + bias) in one launch
    prep_weights<<<233, dim3(32, 8)>>>(W_val, W_off, W_attn, W_out, b_off, b_attn);
    // 2: activation bf16 hi/lo splits (q + v) in one launch
    prep_acts<<<2 * CBLK, 256>>>(query, v0, v1, v2);
    // 3: fused vproj (y=0..3) + qout (y=4..8) GEMM, 3-term split-bf16
    gemm_bf16<<<dim3(206, 9), 256, GEMM_DYNSMEM>>>(1, 0, 0, b_val, nullptr, MQ, 0, 0);
    // 4: fused softmax + deformable sampling
    msda_sample<<<MQ, 256>>>(rp);
    // 5: output projection
    gemm_bf16<<<dim3(206, 4), 256, GEMM_DYNSMEM>>>(0, 2, 576, b_out, out, MQ, 256, 0);
}

// round 8
// speedup vs baseline: 2.1905x; 1.5007x over previous
#include <cuda_runtime.h>
#include <cuda_bf16.h>
#include <math.h>
#include <stdint.h>

// ---------------- problem constants ----------------
#define NQ      13125
#define BATCH   2
#define MQ      (BATCH * NQ)     // 26250
#define DMODEL  256
#define HEADS   8
#define HD      32
#define LVL     3
#define PTS     4

__device__ __constant__ int c_HL[LVL]   = {100, 50, 25};
__device__ __constant__ int c_WL[LVL]   = {100, 50, 25};
__device__ __constant__ int c_LOFF[LVL] = {0, 10000, 12500};

// ---------------- scratch (static device memory; no allocation) ----------------
__device__ __nv_bfloat16 g_qhi[(size_t)MQ * 256], g_qlo[(size_t)MQ * 256];
__device__ __nv_bfloat16 g_vhi[(size_t)MQ * 256], g_vlo[(size_t)MQ * 256];
__device__ __nv_bfloat16 g_mhi[(size_t)MQ * 256], g_mlo[(size_t)MQ * 256];
__device__ float g_vproj[(size_t)MQ * 256];   // projected values (fp32, for sampler)
__device__ float g_qout [(size_t)MQ * 320];   // [0..191]=offsets, [192..287]=logits, pad
// transposed weights, bf16 hi/lo, [row][k]; rows: 0..255 W_val^T, 256..575 [W_off;W_attn;pad]^T, 576..831 W_out^T
__device__ __nv_bfloat16 g_bthi[832 * 256], g_btlo[832 * 256];
__device__ float g_biasq[320];

// ---------------- small helpers ----------------
__device__ __forceinline__ uint32_t smem_to_u32(const void* p) {
    uint32_t a;
    asm("{ .reg .u64 t; cvta.to.shared.u64 t, %1; cvt.u32.u64 %0, t; }" : "=r"(a) : "l"(p));
    return a;
}
__device__ __forceinline__ void ldm4(uint32_t* f, uint32_t addr) {
    asm volatile("ldmatrix.sync.aligned.m8n8.x4.shared.b16 {%0,%1,%2,%3}, [%4];"
                 : "=r"(f[0]), "=r"(f[1]), "=r"(f[2]), "=r"(f[3]) : "r"(addr));
}
__device__ __forceinline__ void mma16816(float* d, const uint32_t* a, const uint32_t* b) {
    asm volatile("mma.sync.aligned.m16n8k16.row.col.f32.bf16.bf16.f32 "
                 "{%0,%1,%2,%3}, {%4,%5,%6,%7}, {%8,%9}, {%0,%1,%2,%3};"
                 : "+f"(d[0]), "+f"(d[1]), "+f"(d[2]), "+f"(d[3])
                 : "r"(a[0]), "r"(a[1]), "r"(a[2]), "r"(a[3]), "r"(b[0]), "r"(b[1]));
}
__device__ __forceinline__ void cpa16(uint32_t dst, const void* src, int bytes) {
    asm volatile("cp.async.cg.shared.global [%0], [%1], 16, %2;"
                 :: "r"(dst), "l"(src), "r"(bytes) : "memory");
}
__device__ __forceinline__ void split2(float x, float y, __nv_bfloat162& hi, __nv_bfloat162& lo) {
    hi = __floats2bfloat162_rn(x, y);
    float rx = x - __bfloat162float(hi.x);
    float ry = y - __bfloat162float(hi.y);
    lo = __floats2bfloat162_rn(rx, ry);
}

// ---------------- prep: activations fp32 -> bf16 hi/lo (q and v in one launch) ----------------
#define CBLK 6563   // ceil(MQ*64/256)
__global__ void prep_acts(const float* __restrict__ q, const float* __restrict__ v0,
                          const float* __restrict__ v1, const float* __restrict__ v2) {
    const int bid = blockIdx.x;
    const bool isq = (bid < CBLK);
    size_t i = (size_t)(isq ? bid : bid - CBLK) * 256 + threadIdx.x;
    if (i >= (size_t)MQ * 64) return;
    float4 v;
    if (isq) {
        v = ((const float4*)q)[i];
    } else {
        int row = (int)(i >> 6), c = (int)(i & 63);
        const float4* src;
        if (row < 20000)      src = (const float4*)(v0 + (size_t)row * 256);
        else if (row < 25000) src = (const float4*)(v1 + (size_t)(row - 20000) * 256);
        else                  src = (const float4*)(v2 + (size_t)(row - 25000) * 256);
        v = src[c];
    }
    __nv_bfloat162 h0, l0, h1, l1;
    split2(v.x, v.y, h0, l0);
    split2(v.z, v.w, h1, l1);
    __nv_bfloat16 *dh = isq ? g_qhi : g_vhi, *dl = isq ? g_qlo : g_vlo;
    ((__nv_bfloat162*)dh)[i * 2 + 0] = h0; ((__nv_bfloat162*)dh)[i * 2 + 1] = h1;
    ((__nv_bfloat162*)dl)[i * 2 + 0] = l0; ((__nv_bfloat162*)dl)[i * 2 + 1] = l1;
}

// ---------------- prep: all weight transposes + pad + combined bias, one launch ----------------
__global__ void prep_weights(const float* __restrict__ W_val, const float* __restrict__ W_off,
                             const float* __restrict__ W_attn, const float* __restrict__ W_out,
                             const float* __restrict__ b_off, const float* __restrict__ b_attn) {
    const int id = blockIdx.x;
    if (id >= 200) {   // fixup: zero pad rows 544..575 + combined bias (flat thread index)
        const int t = threadIdx.y * 32 + threadIdx.x;
        const int i = (id - 200) * 256 + t;
        if (i < 32 * 256) {
            g_bthi[(size_t)544 * 256 + i] = __float2bfloat16_rn(0.f);
            g_btlo[(size_t)544 * 256 + i] = __float2bfloat16_rn(0.f);
        }
        if (i < 320)
            g_biasq[i] = (i < 192) ? b_off[i] : (i < 288 ? b_attn[i - 192] : 0.f);
        return;
    }
    const float* W; int btrow, N, tix;
    if (id < 64)       { W = W_val;  btrow = 0;   N = 256; tix = id;      }
    else if (id < 112) { W = W_off;  btrow = 256; N = 192; tix = id - 64; }
    else if (id < 136) { W = W_attn; btrow = 448; N = 96;  tix = id - 112;}
    else               { W = W_out;  btrow = 576; N = 256; tix = id - 136;}
    const int ntiles = N / 32;
    const int n0 = (tix % ntiles) * 32, k0 = (tix / ntiles) * 32;

    __shared__ float t[32][33];
    #pragma unroll
    for (int j = 0; j < 4; j++) {
        int k = k0 + threadIdx.y + 8 * j;
        int n = n0 + threadIdx.x;
        t[threadIdx.y + 8 * j][threadIdx.x] = W[(size_t)k * N + n];
    }
    __syncthreads();
    #pragma unroll
    for (int j = 0; j < 4; j++) {
        int n = n0 + threadIdx.y + 8 * j;
        int k = k0 + threadIdx.x;
        float x = t[threadIdx.x][threadIdx.y + 8 * j];
        __nv_bfloat16 hi = __float2bfloat16_rn(x);
        g_bthi[(size_t)(btrow + n) * 256 + k] = hi;
        g_btlo[(size_t)(btrow + n) * 256 + k] = __float2bfloat16_rn(x - __bfloat162float(hi));
    }
}

// ---------------- split-bf16 tensor-core GEMM, 3-stage cp.async pipeline ----------------
// C[M,N] = Ah@Bh + Al@Bh + Ah@Bl + bias.  BM=128, BN=64, BK=32; 8 warps 4(M)x2(N).
#define ASTR 40
#define A_HALVES (128 * ASTR)                      // 5120
#define B_HALVES (64 * ASTR)                       // 2560
#define STG_HALVES (2 * A_HALVES + 2 * B_HALVES)   // 15360
#define STG_BYTES  (STG_HALVES * 2)                // 30720
#define OFF_AH 0
#define OFF_AL A_HALVES
#define OFF_BH (2 * A_HALVES)
#define OFF_BL (2 * A_HALVES + B_HALVES)
#define GEMM_DYNSMEM (3 * STG_BYTES)               // 92160

__global__ __launch_bounds__(256, 2)
void gemm_bf16(int fusedvq, int asel_p, int btoff_p, const float* __restrict__ biasp,
               float* __restrict__ Cout, int M, int N_p, int remap_p)
{
    extern __shared__ __align__(16) __nv_bfloat16 dsm[];
    const uint32_t sbase = smem_to_u32(dsm);

    int asel = asel_p, btoff = btoff_p, N = N_p, remap = remap_p, n0;
    const float* bias = biasp;
    float* C;
    if (fusedvq) {
        if (blockIdx.y < 4) { asel = 1; btoff = 0;   N = 256; remap = 1; n0 = blockIdx.y * 64;      C = g_vproj; }
        else                { asel = 0; btoff = 256; N = 320; remap = 0; n0 = (blockIdx.y - 4) * 64; C = g_qout; bias = g_biasq; }
    } else {
        n0 = blockIdx.y * 64;
        C = Cout;
    }

    const __nv_bfloat16 *Ahi, *Alo;
    if (asel == 0)      { Ahi = g_qhi; Alo = g_qlo; }
    else if (asel == 1) { Ahi = g_vhi; Alo = g_vlo; }
    else                { Ahi = g_mhi; Alo = g_mlo; }
    const __nv_bfloat16* Bhi = g_bthi + (size_t)btoff * 256;
    const __nv_bfloat16* Blo = g_btlo + (size_t)btoff * 256;

    const int tid = threadIdx.x, lane = tid & 31, wid = tid >> 5;
    const int wm = wid >> 1, wn = wid & 1;
    const int row0 = blockIdx.x * 128;
    const int lr = tid >> 2, lc = tid & 3;

    auto issue = [&](int kt) {
        const uint32_t st = sbase + (uint32_t)((kt % 3) * STG_BYTES);
        const int k0 = kt * 32;
        #pragma unroll
        for (int t = 0; t < 2; t++) {
            const int r  = lr + t * 64;
            const int gr = row0 + r;
            const bool v = (gr < M);
            const size_t go = (size_t)(v ? gr : 0) * 256 + k0 + lc * 8;
            const uint32_t so = (uint32_t)((r * ASTR + lc * 8) * 2);
            cpa16(st + OFF_AH * 2 + so, Ahi + go, v ? 16 : 0);
            cpa16(st + OFF_AL * 2 + so, Alo + go, v ? 16 : 0);
        }
        {
            const size_t go = (size_t)(n0 + lr) * 256 + k0 + lc * 8;
            const uint32_t so = (uint32_t)((lr * ASTR + lc * 8) * 2);
            cpa16(st + OFF_BH * 2 + so, Bhi + go, 16);
            cpa16(st + OFF_BL * 2 + so, Blo + go, 16);
        }
        asm volatile("cp.async.commit_group;" ::: "memory");
    };

    float acc[2][4][4] = {};

    issue(0);
    issue(1);
    #pragma unroll 1
    for (int kt = 0; kt < 8; kt++) {
        if (kt < 7) asm volatile("cp.async.wait_group 1;" ::: "memory");
        else        asm volatile("cp.async.wait_group 0;" ::: "memory");
        __syncthreads();
        if (kt + 2 < 8) issue(kt + 2);

        const uint32_t st = sbase + (uint32_t)((kt % 3) * STG_BYTES);
        const uint32_t uAh = st + OFF_AH * 2, uAl = st + OFF_AL * 2;
        const uint32_t uBh = st + OFF_BH * 2, uBl = st + OFF_BL * 2;
        const int lrow = lane & 15, lkc = lane >> 4;

        #pragma unroll
        for (int kk = 0; kk < 2; kk++) {
            uint32_t fah[2][4], fal[2][4], fbh[2][4], fbl[2][4];
            #pragma unroll
            for (int mt = 0; mt < 2; mt++) {
                uint32_t off = (uint32_t)(((wm * 32 + mt * 16 + lrow) * ASTR + kk * 16 + lkc * 8) * 2);
                ldm4(fah[mt], uAh + off);
                ldm4(fal[mt], uAl + off);
            }
            #pragma unroll
            for (int ng = 0; ng < 2; ng++) {
                uint32_t off = (uint32_t)(((wn * 32 + ng * 16 + lrow) * ASTR + kk * 16 + lkc * 8) * 2);
                ldm4(fbh[ng], uBh + off);
                ldm4(fbl[ng], uBl + off);
            }
            #pragma unroll
            for (int mt = 0; mt < 2; mt++) {
                #pragma unroll
                for (int n = 0; n < 4; n++) {
                    uint32_t bh[2] = { fbh[n >> 1][n & 1], fbh[n >> 1][(n & 1) + 2] };
                    uint32_t bl[2] = { fbl[n >> 1][n & 1], fbl[n >> 1][(n & 1) + 2] };
                    mma16816(acc[mt][n], fah[mt], bh);
                    mma16816(acc[mt][n], fal[mt], bh);
                    mma16816(acc[mt][n], fah[mt], bl);
                }
            }
        }
    }

    // epilogue
    const int er = lane >> 2, ec = (lane & 3) * 2;
    #pragma unroll
    for (int mt = 0; mt < 2; mt++) {
        #pragma unroll
        for (int n = 0; n < 4; n++) {
            int col = n0 + wn * 32 + n * 8 + ec;
            float b0 = __ldg(bias + col), b1 = __ldg(bias + col + 1);
            #pragma unroll
            for (int h2 = 0; h2 < 2; h2++) {
                int row = row0 + wm * 32 + mt * 16 + er + 8 * h2;
                if (row < M) {
                    int orow = row;
                    if (remap) {
                        if (row < 20000)      orow = (row / 10000) * NQ + (row % 10000);
                        else if (row < 25000) { int rr = row - 20000; orow = (rr / 2500) * NQ + 10000 + rr % 2500; }
                        else                  { int rr = row - 25000; orow = (rr / 625)  * NQ + 12500 + rr % 625; }
                    }
                    float2 o = make_float2(acc[mt][n][2 * h2] + b0, acc[mt][n][2 * h2 + 1] + b1);
                    *(float2*)(C + (size_t)orow * N + col) = o;
                }
            }
        }
    }
}

// ---------------- fused softmax + deformable bilinear sampling (point-parallel) ----------------
// warp = (query, head). lane = pg(2b) x cq(3b): pg = one of 4 sample points in flight,
// cq = float4 channel quad (8 lanes x 16B = one 128B line per corner gather).
__global__ __launch_bounds__(256, 8)
void msda_sample(const float* __restrict__ rp)
{
    const int bq   = blockIdx.x;
    const int h    = threadIdx.x >> 5;
    const int lane = threadIdx.x & 31;
    const int pg   = lane >> 3;     // point group 0..3
    const int cq   = lane & 7;      // channel quad 0..7
    const int b    = bq / NQ;

    // --- softmax over 12 logits (lanes 0..11 hold them) ---
    float lv = -1e30f;
    if (lane < LVL * PTS)
        lv = g_qout[(size_t)bq * 320 + 192 + h * 12 + lane];
    float m = lv;
    #pragma unroll
    for (int o = 16; o; o >>= 1) m = fmaxf(m, __shfl_xor_sync(0xffffffffu, m, o));
    float e = (lane < LVL * PTS) ? __expf(lv - m) : 0.f;
    float s = e;
    #pragma unroll
    for (int o = 16; o; o >>= 1) s += __shfl_xor_sync(0xffffffffu, s, o);
    const float prob = e / s;

    const float* offp  = g_qout + (size_t)bq * 320 + h * 24;
    const float* rpq   = rp + (size_t)bq * (LVL * 2);
    float4 acc = make_float4(0.f, 0.f, 0.f, 0.f);

    #pragma unroll
    for (int l = 0; l < LVL; l++) {
        const int   Wi = c_WL[l], Hi = c_HL[l];
        const float Wf = (float)Wi, Hf = (float)Hi;
        const float rWf = 1.0f / Wf, rHf = 1.0f / Hf;
        const float2 rxy = *(const float2*)(rpq + l * 2);
        const float* vbase = g_vproj + ((size_t)(b * NQ + c_LOFF[l])) * DMODEL + h * HD + cq * 4;

        const float a = __shfl_sync(0xffffffffu, prob, l * PTS + pg);
        const float2 oxy = *(const float2*)(offp + l * 8 + pg * 2);

        const float x = (rxy.x + oxy.x * rWf) * Wf - 0.5f;
        const float y = (rxy.y + oxy.y * rHf) * Hf - 0.5f;
        const float x0f = floorf(x), y0f = floorf(y);
        const float wx1 = x - x0f,  wy1 = y - y0f;
        const float wx0 = 1.f - wx1, wy0 = 1.f - wy1;
        const int ix0 = (int)x0f, iy0 = (int)y0f;

        float4 sv = make_float4(0.f, 0.f, 0.f, 0.f);
        #pragma unroll
        for (int cy = 0; cy < 2; cy++) {
            const int   iy = iy0 + cy;
            const float wy = cy ? wy1 : wy0;
            if (iy < 0 || iy >= Hi) continue;
            const float* vrow = vbase + (size_t)iy * Wi * DMODEL;
            #pragma unroll
            for (int cx = 0; cx < 2; cx++) {
                const int   ix = ix0 + cx;
                const float wx = cx ? wx1 : wx0;
                if (ix < 0 || ix >= Wi) continue;
                const float w = wx * wy;
                const float4 v = *(const float4*)(vrow + (size_t)ix * DMODEL);
                sv.x = fmaf(w, v.x, sv.x);
                sv.y = fmaf(w, v.y, sv.y);
                sv.z = fmaf(w, v.z, sv.z);
                sv.w = fmaf(w, v.w, sv.w);
            }
        }
        acc.x = fmaf(a, sv.x, acc.x);
        acc.y = fmaf(a, sv.y, acc.y);
        acc.z = fmaf(a, sv.z, acc.z);
        acc.w = fmaf(a, sv.w, acc.w);
    }

    // reduce across the 4 point groups (lanes differing in bits 3,4)
    #pragma unroll
    for (int o = 8; o <= 16; o <<= 1) {
        acc.x += __shfl_xor_sync(0xffffffffu, acc.x, o);
        acc.y += __shfl_xor_sync(0xffffffffu, acc.y, o);
        acc.z += __shfl_xor_sync(0xffffffffu, acc.z, o);
        acc.w += __shfl_xor_sync(0xffffffffu, acc.w, o);
    }

    if (pg == 0) {
        const size_t oi = (size_t)bq * DMODEL + h * HD + cq * 4;   // multiple of 4
        __nv_bfloat162 h0, l0, h1, l1;
        split2(acc.x, acc.y, h0, l0);
        split2(acc.z, acc.w, h1, l1);
        *(uint2*)(g_mhi + oi) = make_uint2(*(uint32_t*)&h0, *(uint32_t*)&h1);
        *(uint2*)(g_mlo + oi) = make_uint2(*(uint32_t*)&l0, *(uint32_t*)&l1);
    }
}

// ---------------- launch ----------------
extern "C" void kernel_launch(void* const* d_in, const int* in_sizes, int n_in,
                              void* d_out, int out_size)
{
    const float* query  = (const float*)d_in[0];
    const float* rp     = (const float*)d_in[1];
    const float* v0     = (const float*)d_in[2];
    const float* v1     = (const float*)d_in[3];
    const float* v2     = (const float*)d_in[4];
    const float* W_val  = (const float*)d_in[5];
    const float* b_val  = (const float*)d_in[6];
    const float* W_off  = (const float*)d_in[7];
    const float* b_off  = (const float*)d_in[8];
    const float* W_attn = (const float*)d_in[9];
    const float* b_attn = (const float*)d_in[10];
    const float* W_out  = (const float*)d_in[11];
    const float* b_out  = (const float*)d_in[12];
    float* out = (float*)d_out;

    cudaFuncSetAttribute(gemm_bf16, cudaFuncAttributeMaxDynamicSharedMemorySize, GEMM_DYNSMEM);

    // 1: all weight prep (4 transposes + pad + bias) in one launch
    prep_weights<<<233, dim3(32, 8)>>>(W_val, W_off, W_attn, W_out, b_off, b_attn);
    // 2: activation bf16 hi/lo splits (q + v) in one launch
    prep_acts<<<2 * CBLK, 256>>>(query, v0, v1, v2);
    // 3: fused vproj (y=0..3) + qout (y=4..8) GEMM, 3-term split-bf16
    gemm_bf16<<<dim3(206, 9), 256, GEMM_DYNSMEM>>>(1, 0, 0, b_val, nullptr, MQ, 0, 0);
    // 4: fused softmax + deformable sampling (point-parallel lanes)
    msda_sample<<<MQ, 256>>>(rp);
    // 5: output projection
    gemm_bf16<<<dim3(206, 4), 256, GEMM_DYNSMEM>>>(0, 2, 576, b_out, out, MQ, 256, 0);
}

// round 9
// speedup vs baseline: 2.4343x; 1.1113x over previous
#include <cuda_runtime.h>
#include <cuda_bf16.h>
#include <math.h>
#include <stdint.h>

// ---------------- problem constants ----------------
#define NQ      13125
#define BATCH   2
#define MQ      (BATCH * NQ)     // 26250
#define DMODEL  256
#define HEADS   8
#define HD      32
#define LVL     3
#define PTS     4

// ---------------- scratch (static device memory; no allocation) ----------------
__device__ __nv_bfloat16 g_qhi[(size_t)MQ * 256], g_qlo[(size_t)MQ * 256];
__device__ __nv_bfloat16 g_vhi[(size_t)MQ * 256], g_vlo[(size_t)MQ * 256];
__device__ __nv_bfloat16 g_mhi[(size_t)MQ * 256], g_mlo[(size_t)MQ * 256];
__device__ float g_vproj[(size_t)MQ * 256];   // projected values (fp32, for sampler)
__device__ float g_qout [(size_t)MQ * 320];   // [0..191]=offsets, [192..287]=logits, pad
// transposed weights, bf16 hi/lo, [row][k]; rows: 0..255 W_val^T, 256..575 [W_off;W_attn;pad]^T, 576..831 W_out^T
__device__ __nv_bfloat16 g_bthi[832 * 256], g_btlo[832 * 256];
__device__ float g_biasq[320];

// ---------------- small helpers ----------------
__device__ __forceinline__ uint32_t smem_to_u32(const void* p) {
    uint32_t a;
    asm("{ .reg .u64 t; cvta.to.shared.u64 t, %1; cvt.u32.u64 %0, t; }" : "=r"(a) : "l"(p));
    return a;
}
__device__ __forceinline__ void ldm4(uint32_t* f, uint32_t addr) {
    asm volatile("ldmatrix.sync.aligned.m8n8.x4.shared.b16 {%0,%1,%2,%3}, [%4];"
                 : "=r"(f[0]), "=r"(f[1]), "=r"(f[2]), "=r"(f[3]) : "r"(addr));
}
__device__ __forceinline__ void mma16816(float* d, const uint32_t* a, const uint32_t* b) {
    asm volatile("mma.sync.aligned.m16n8k16.row.col.f32.bf16.bf16.f32 "
                 "{%0,%1,%2,%3}, {%4,%5,%6,%7}, {%8,%9}, {%0,%1,%2,%3};"
                 : "+f"(d[0]), "+f"(d[1]), "+f"(d[2]), "+f"(d[3])
                 : "r"(a[0]), "r"(a[1]), "r"(a[2]), "r"(a[3]), "r"(b[0]), "r"(b[1]));
}
__device__ __forceinline__ void cpa16(uint32_t dst, const void* src, int bytes) {
    asm volatile("cp.async.cg.shared.global [%0], [%1], 16, %2;"
                 :: "r"(dst), "l"(src), "r"(bytes) : "memory");
}
__device__ __forceinline__ void split2(float x, float y, __nv_bfloat162& hi, __nv_bfloat162& lo) {
    hi = __floats2bfloat162_rn(x, y);
    float rx = x - __bfloat162float(hi.x);
    float ry = y - __bfloat162float(hi.y);
    lo = __floats2bfloat162_rn(rx, ry);
}

// ---------------- prep: activations fp32 -> bf16 hi/lo (q and v in one launch) ----------------
#define CBLK 6563   // ceil(MQ*64/256)
__global__ void prep_acts(const float* __restrict__ q, const float* __restrict__ v0,
                          const float* __restrict__ v1, const float* __restrict__ v2) {
    const int bid = blockIdx.x;
    const bool isq = (bid < CBLK);
    size_t i = (size_t)(isq ? bid : bid - CBLK) * 256 + threadIdx.x;
    if (i >= (size_t)MQ * 64) return;
    float4 v;
    if (isq) {
        v = ((const float4*)q)[i];
    } else {
        int row = (int)(i >> 6), c = (int)(i & 63);
        const float4* src;
        if (row < 20000)      src = (const float4*)(v0 + (size_t)row * 256);
        else if (row < 25000) src = (const float4*)(v1 + (size_t)(row - 20000) * 256);
        else                  src = (const float4*)(v2 + (size_t)(row - 25000) * 256);
        v = src[c];
    }
    __nv_bfloat162 h0, l0, h1, l1;
    split2(v.x, v.y, h0, l0);
    split2(v.z, v.w, h1, l1);
    __nv_bfloat16 *dh = isq ? g_qhi : g_vhi, *dl = isq ? g_qlo : g_vlo;
    ((__nv_bfloat162*)dh)[i * 2 + 0] = h0; ((__nv_bfloat162*)dh)[i * 2 + 1] = h1;
    ((__nv_bfloat162*)dl)[i * 2 + 0] = l0; ((__nv_bfloat162*)dl)[i * 2 + 1] = l1;
}

// ---------------- prep: all weight transposes + pad + combined bias, one launch ----------------
__global__ void prep_weights(const float* __restrict__ W_val, const float* __restrict__ W_off,
                             const float* __restrict__ W_attn, const float* __restrict__ W_out,
                             const float* __restrict__ b_off, const float* __restrict__ b_attn) {
    const int id = blockIdx.x;
    if (id >= 200) {   // fixup: zero pad rows 544..575 + combined bias (flat thread index)
        const int t = threadIdx.y * 32 + threadIdx.x;
        const int i = (id - 200) * 256 + t;
        if (i < 32 * 256) {
            g_bthi[(size_t)544 * 256 + i] = __float2bfloat16_rn(0.f);
            g_btlo[(size_t)544 * 256 + i] = __float2bfloat16_rn(0.f);
        }
        if (i < 320)
            g_biasq[i] = (i < 192) ? b_off[i] : (i < 288 ? b_attn[i - 192] : 0.f);
        return;
    }
    const float* W; int btrow, N, tix;
    if (id < 64)       { W = W_val;  btrow = 0;   N = 256; tix = id;      }
    else if (id < 112) { W = W_off;  btrow = 256; N = 192; tix = id - 64; }
    else if (id < 136) { W = W_attn; btrow = 448; N = 96;  tix = id - 112;}
    else               { W = W_out;  btrow = 576; N = 256; tix = id - 136;}
    const int ntiles = N / 32;
    const int n0 = (tix % ntiles) * 32, k0 = (tix / ntiles) * 32;

    __shared__ float t[32][33];
    #pragma unroll
    for (int j = 0; j < 4; j++) {
        int k = k0 + threadIdx.y + 8 * j;
        int n = n0 + threadIdx.x;
        t[threadIdx.y + 8 * j][threadIdx.x] = W[(size_t)k * N + n];
    }
    __syncthreads();
    #pragma unroll
    for (int j = 0; j < 4; j++) {
        int n = n0 + threadIdx.y + 8 * j;
        int k = k0 + threadIdx.x;
        float x = t[threadIdx.x][threadIdx.y + 8 * j];
        __nv_bfloat16 hi = __float2bfloat16_rn(x);
        g_bthi[(size_t)(btrow + n) * 256 + k] = hi;
        g_btlo[(size_t)(btrow + n) * 256 + k] = __float2bfloat16_rn(x - __bfloat162float(hi));
    }
}

// ---------------- split-bf16 tensor-core GEMM, 3-stage cp.async pipeline ----------------
#define ASTR 40
#define A_HALVES (128 * ASTR)
#define B_HALVES (64 * ASTR)
#define STG_HALVES (2 * A_HALVES + 2 * B_HALVES)
#define STG_BYTES  (STG_HALVES * 2)
#define OFF_AH 0
#define OFF_AL A_HALVES
#define OFF_BH (2 * A_HALVES)
#define OFF_BL (2 * A_HALVES + B_HALVES)
#define GEMM_DYNSMEM (3 * STG_BYTES)

__global__ __launch_bounds__(256, 2)
void gemm_bf16(int fusedvq, int asel_p, int btoff_p, const float* __restrict__ biasp,
               float* __restrict__ Cout, int M, int N_p, int remap_p)
{
    extern __shared__ __align__(16) __nv_bfloat16 dsm[];
    const uint32_t sbase = smem_to_u32(dsm);

    int asel = asel_p, btoff = btoff_p, N = N_p, remap = remap_p, n0;
    const float* bias = biasp;
    float* C;
    if (fusedvq) {
        if (blockIdx.y < 4) { asel = 1; btoff = 0;   N = 256; remap = 1; n0 = blockIdx.y * 64;      C = g_vproj; }
        else                { asel = 0; btoff = 256; N = 320; remap = 0; n0 = (blockIdx.y - 4) * 64; C = g_qout; bias = g_biasq; }
    } else {
        n0 = blockIdx.y * 64;
        C = Cout;
    }

    const __nv_bfloat16 *Ahi, *Alo;
    if (asel == 0)      { Ahi = g_qhi; Alo = g_qlo; }
    else if (asel == 1) { Ahi = g_vhi; Alo = g_vlo; }
    else                { Ahi = g_mhi; Alo = g_mlo; }
    const __nv_bfloat16* Bhi = g_bthi + (size_t)btoff * 256;
    const __nv_bfloat16* Blo = g_btlo + (size_t)btoff * 256;

    const int tid = threadIdx.x, lane = tid & 31, wid = tid >> 5;
    const int wm = wid >> 1, wn = wid & 1;
    const int row0 = blockIdx.x * 128;
    const int lr = tid >> 2, lc = tid & 3;

    auto issue = [&](int kt) {
        const uint32_t st = sbase + (uint32_t)((kt % 3) * STG_BYTES);
        const int k0 = kt * 32;
        #pragma unroll
        for (int t = 0; t < 2; t++) {
            const int r  = lr + t * 64;
            const int gr = row0 + r;
            const bool v = (gr < M);
            const size_t go = (size_t)(v ? gr : 0) * 256 + k0 + lc * 8;
            const uint32_t so = (uint32_t)((r * ASTR + lc * 8) * 2);
            cpa16(st + OFF_AH * 2 + so, Ahi + go, v ? 16 : 0);
            cpa16(st + OFF_AL * 2 + so, Alo + go, v ? 16 : 0);
        }
        {
            const size_t go = (size_t)(n0 + lr) * 256 + k0 + lc * 8;
            const uint32_t so = (uint32_t)((lr * ASTR + lc * 8) * 2);
            cpa16(st + OFF_BH * 2 + so, Bhi + go, 16);
            cpa16(st + OFF_BL * 2 + so, Blo + go, 16);
        }
        asm volatile("cp.async.commit_group;" ::: "memory");
    };

    float acc[2][4][4] = {};

    issue(0);
    issue(1);
    #pragma unroll 1
    for (int kt = 0; kt < 8; kt++) {
        if (kt < 7) asm volatile("cp.async.wait_group 1;" ::: "memory");
        else        asm volatile("cp.async.wait_group 0;" ::: "memory");
        __syncthreads();
        if (kt + 2 < 8) issue(kt + 2);

        const uint32_t st = sbase + (uint32_t)((kt % 3) * STG_BYTES);
        const uint32_t uAh = st + OFF_AH * 2, uAl = st + OFF_AL * 2;
        const uint32_t uBh = st + OFF_BH * 2, uBl = st + OFF_BL * 2;
        const int lrow = lane & 15, lkc = lane >> 4;

        #pragma unroll
        for (int kk = 0; kk < 2; kk++) {
            uint32_t fah[2][4], fal[2][4], fbh[2][4], fbl[2][4];
            #pragma unroll
            for (int mt = 0; mt < 2; mt++) {
                uint32_t off = (uint32_t)(((wm * 32 + mt * 16 + lrow) * ASTR + kk * 16 + lkc * 8) * 2);
                ldm4(fah[mt], uAh + off);
                ldm4(fal[mt], uAl + off);
            }
            #pragma unroll
            for (int ng = 0; ng < 2; ng++) {
                uint32_t off = (uint32_t)(((wn * 32 + ng * 16 + lrow) * ASTR + kk * 16 + lkc * 8) * 2);
                ldm4(fbh[ng], uBh + off);
                ldm4(fbl[ng], uBl + off);
            }
            #pragma unroll
            for (int mt = 0; mt < 2; mt++) {
                #pragma unroll
                for (int n = 0; n < 4; n++) {
                    uint32_t bh[2] = { fbh[n >> 1][n & 1], fbh[n >> 1][(n & 1) + 2] };
                    uint32_t bl[2] = { fbl[n >> 1][n & 1], fbl[n >> 1][(n & 1) + 2] };
                    mma16816(acc[mt][n], fah[mt], bh);
                    mma16816(acc[mt][n], fal[mt], bh);
                    mma16816(acc[mt][n], fah[mt], bl);
                }
            }
        }
    }

    // epilogue
    const int er = lane >> 2, ec = (lane & 3) * 2;
    #pragma unroll
    for (int mt = 0; mt < 2; mt++) {
        #pragma unroll
        for (int n = 0; n < 4; n++) {
            int col = n0 + wn * 32 + n * 8 + ec;
            float b0 = __ldg(bias + col), b1 = __ldg(bias + col + 1);
            #pragma unroll
            for (int h2 = 0; h2 < 2; h2++) {
                int row = row0 + wm * 32 + mt * 16 + er + 8 * h2;
                if (row < M) {
                    int orow = row;
                    if (remap) {
                        if (row < 20000)      orow = (row / 10000) * NQ + (row % 10000);
                        else if (row < 25000) { int rr = row - 20000; orow = (rr / 2500) * NQ + 10000 + rr % 2500; }
                        else                  { int rr = row - 25000; orow = (rr / 625)  * NQ + 12500 + rr % 625; }
                    }
                    float2 o = make_float2(acc[mt][n][2 * h2] + b0, acc[mt][n][2 * h2 + 1] + b1);
                    *(float2*)(C + (size_t)orow * N + col) = o;
                }
            }
        }
    }
}

// ---------------- fused softmax + deformable bilinear sampling ----------------
// warp = (query, head); lane = pg(2b) x cq(3b). Branchless clamp+mask corners,
// 32-bit byte offsets, attention prob folded into corner weights.
__global__ __launch_bounds__(256, 6)
void msda_sample(const float* __restrict__ rp)
{
    const int bq   = blockIdx.x;
    const int h    = threadIdx.x >> 5;
    const int lane = threadIdx.x & 31;
    const int pg   = lane >> 3;     // point group 0..3
    const int cq   = lane & 7;      // channel quad 0..7

    // --- softmax over 12 logits (lanes 0..11); butterfly within 16-lane group ---
    float lv = -1e30f;
    if (lane < LVL * PTS)
        lv = g_qout[(size_t)bq * 320 + 192 + h * 12 + lane];
    float m = lv;
    #pragma unroll
    for (int o = 8; o; o >>= 1) m = fmaxf(m, __shfl_xor_sync(0xffffffffu, m, o));
    float e = (lane < LVL * PTS) ? __expf(lv - m) : 0.f;
    float s = e;
    #pragma unroll
    for (int o = 8; o; o >>= 1) s += __shfl_xor_sync(0xffffffffu, s, o);
    const float prob = e / s;   // valid in lanes 0..15; broadcast sources are 0..11

    const float* offp = g_qout + (size_t)bq * 320 + h * 24;
    const float* rpq  = rp + (size_t)bq * 6;
    const char*  vb   = (const char*)g_vproj;
    // byte offset of this lane's channel quad within a pixel row (1024 B per pixel)
    const uint32_t laneOff = (uint32_t)((h * HD + cq * 4) * 4);
    const uint32_t batOff  = (bq >= NQ) ? (uint32_t)NQ * 1024u : 0u;

    float4 acc = make_float4(0.f, 0.f, 0.f, 0.f);

    #pragma unroll
    for (int l = 0; l < LVL; l++) {
        constexpr int HLc[3]   = {100, 50, 25};
        constexpr int WLc[3]   = {100, 50, 25};
        constexpr int LOFFc[3] = {0, 10000, 12500};
        const int   Wi = WLc[l], Hi = HLc[l];
        const float Wf = (float)Wi, Hf = (float)Hi;

        const float a = __shfl_sync(0xffffffffu, prob, l * PTS + pg);
        const float2 rxy = *(const float2*)(rpq + l * 2);
        const float2 oxy = *(const float2*)(offp + l * 8 + pg * 2);

        const float x = (rxy.x + oxy.x * (1.0f / Wf)) * Wf - 0.5f;
        const float y = (rxy.y + oxy.y * (1.0f / Hf)) * Hf - 0.5f;
        const float x0f = floorf(x), y0f = floorf(y);
        const float wx1 = x - x0f,  wy1 = y - y0f;
        const int ix0 = (int)x0f, iy0 = (int)y0f;
        const int ix1 = ix0 + 1,  iy1 = iy0 + 1;

        // masked x-weights (attention prob folded in), plain y-weights
        const float ax0 = (ix0 >= 0 && ix0 < Wi) ? (1.f - wx1) * a : 0.f;
        const float ax1 = (ix1 >= 0 && ix1 < Wi) ? wx1 * a : 0.f;
        const float my0 = (iy0 >= 0 && iy0 < Hi) ? (1.f - wy1) : 0.f;
        const float my1 = (iy1 >= 0 && iy1 < Hi) ? wy1 : 0.f;

        // clamped indices (always in-bounds loads; zero weight kills OOB)
        const int ix0c = min(max(ix0, 0), Wi - 1), ix1c = min(max(ix1, 0), Wi - 1);
        const int iy0c = min(max(iy0, 0), Hi - 1), iy1c = min(max(iy1, 0), Hi - 1);

        const uint32_t base = batOff + (uint32_t)LOFFc[l] * 1024u + laneOff;
        const uint32_t r0 = base + (uint32_t)(iy0c * Wi) * 1024u;
        const uint32_t r1 = base + (uint32_t)(iy1c * Wi) * 1024u;
        const uint32_t cx0 = (uint32_t)ix0c * 1024u, cx1 = (uint32_t)ix1c * 1024u;

        const float4 v00 = *(const float4*)(vb + (r0 + cx0));
        const float4 v01 = *(const float4*)(vb + (r0 + cx1));
        const float4 v10 = *(const float4*)(vb + (r1 + cx0));
        const float4 v11 = *(const float4*)(vb + (r1 + cx1));

        const float w00 = ax0 * my0, w01 = ax1 * my0;
        const float w10 = ax0 * my1, w11 = ax1 * my1;

        acc.x = fmaf(w00, v00.x, acc.x); acc.y = fmaf(w00, v00.y, acc.y);
        acc.z = fmaf(w00, v00.z, acc.z); acc.w = fmaf(w00, v00.w, acc.w);
        acc.x = fmaf(w01, v01.x, acc.x); acc.y = fmaf(w01, v01.y, acc.y);
        acc.z = fmaf(w01, v01.z, acc.z); acc.w = fmaf(w01, v01.w, acc.w);
        acc.x = fmaf(w10, v10.x, acc.x); acc.y = fmaf(w10, v10.y, acc.y);
        acc.z = fmaf(w10, v10.z, acc.z); acc.w = fmaf(w10, v10.w, acc.w);
        acc.x = fmaf(w11, v11.x, acc.x); acc.y = fmaf(w11, v11.y, acc.y);
        acc.z = fmaf(w11, v11.z, acc.z); acc.w = fmaf(w11, v11.w, acc.w);
    }

    // reduce across the 4 point groups (lanes differing in bits 3,4)
    #pragma unroll
    for (int o = 8; o <= 16; o <<= 1) {
        acc.x += __shfl_xor_sync(0xffffffffu, acc.x, o);
        acc.y += __shfl_xor_sync(0xffffffffu, acc.y, o);
        acc.z += __shfl_xor_sync(0xffffffffu, acc.z, o);
        acc.w += __shfl_xor_sync(0xffffffffu, acc.w, o);
    }

    if (pg == 0) {
        const size_t oi = (size_t)bq * DMODEL + h * HD + cq * 4;
        __nv_bfloat162 h0, l0, h1, l1;
        split2(acc.x, acc.y, h0, l0);
        split2(acc.z, acc.w, h1, l1);
        *(uint2*)(g_mhi + oi) = make_uint2(*(uint32_t*)&h0, *(uint32_t*)&h1);
        *(uint2*)(g_mlo + oi) = make_uint2(*(uint32_t*)&l0, *(uint32_t*)&l1);
    }
}

// ---------------- launch ----------------
extern "C" void kernel_launch(void* const* d_in, const int* in_sizes, int n_in,
                              void* d_out, int out_size)
{
    const float* query  = (const float*)d_in[0];
    const float* rp     = (const float*)d_in[1];
    const float* v0     = (const float*)d_in[2];
    const float* v1     = (const float*)d_in[3];
    const float* v2     = (const float*)d_in[4];
    const float* W_val  = (const float*)d_in[5];
    const float* b_val  = (const float*)d_in[6];
    const float* W_off  = (const float*)d_in[7];
    const float* b_off  = (const float*)d_in[8];
    const float* W_attn = (const float*)d_in[9];
    const float* b_attn = (const float*)d_in[10];
    const float* W_out  = (const float*)d_in[11];
    const float* b_out  = (const float*)d_in[12];
    float* out = (float*)d_out;

    cudaFuncSetAttribute(gemm_bf16, cudaFuncAttributeMaxDynamicSharedMemorySize, GEMM_DYNSMEM);

    // 1: all weight prep (4 transposes + pad + bias) in one launch
    prep_weights<<<233, dim3(32, 8)>>>(W_val, W_off, W_attn, W_out, b_off, b_attn);
    // 2: activation bf16 hi/lo splits (q + v) in one launch
    prep_acts<<<2 * CBLK, 256>>>(query, v0, v1, v2);
    // 3: fused vproj (y=0..3) + qout (y=4..8) GEMM, 3-term split-bf16
    gemm_bf16<<<dim3(206, 9), 256, GEMM_DYNSMEM>>>(1, 0, 0, b_val, nullptr, MQ, 0, 0);
    // 4: fused softmax + deformable sampling (branchless, 32-bit offsets)
    msda_sample<<<MQ, 256>>>(rp);
    // 5: output projection
    gemm_bf16<<<dim3(206, 4), 256, GEMM_DYNSMEM>>>(0, 2, 576, b_out, out, MQ, 256, 0);
}

// round 10
// speedup vs baseline: 2.4981x; 1.0262x over previous
#include <cuda_runtime.h>
#include <cuda_bf16.h>
#include <math.h>
#include <stdint.h>

// ---------------- problem constants ----------------
#define NQ      13125
#define BATCH   2
#define MQ      (BATCH * NQ)     // 26250
#define DMODEL  256
#define HEADS   8
#define HD      32
#define LVL     3
#define PTS     4

// ---------------- scratch (static device memory; no allocation) ----------------
__device__ __nv_bfloat16 g_qhi[(size_t)MQ * 256], g_qlo[(size_t)MQ * 256];
__device__ __nv_bfloat16 g_vhi[(size_t)MQ * 256], g_vlo[(size_t)MQ * 256];
__device__ __nv_bfloat16 g_mhi[(size_t)MQ * 256], g_mlo[(size_t)MQ * 256];
__device__ float g_vproj[(size_t)MQ * 256];   // projected values (fp32, for sampler)
__device__ float g_qout [(size_t)MQ * 320];   // [0..191]=offsets, [192..287]=logits, pad
// transposed weights, bf16 hi/lo, [row][k]; rows: 0..255 W_val^T, 256..575 [W_off;W_attn;pad]^T, 576..831 W_out^T
__device__ __nv_bfloat16 g_bthi[832 * 256], g_btlo[832 * 256];
__device__ float g_biasq[320];

// ---------------- small helpers ----------------
__device__ __forceinline__ uint32_t smem_to_u32(const void* p) {
    uint32_t a;
    asm("{ .reg .u64 t; cvta.to.shared.u64 t, %1; cvt.u32.u64 %0, t; }" : "=r"(a) : "l"(p));
    return a;
}
__device__ __forceinline__ void ldm4(uint32_t* f, uint32_t addr) {
    asm volatile("ldmatrix.sync.aligned.m8n8.x4.shared.b16 {%0,%1,%2,%3}, [%4];"
                 : "=r"(f[0]), "=r"(f[1]), "=r"(f[2]), "=r"(f[3]) : "r"(addr));
}
__device__ __forceinline__ void mma16816(float* d, const uint32_t* a, const uint32_t* b) {
    asm volatile("mma.sync.aligned.m16n8k16.row.col.f32.bf16.bf16.f32 "
                 "{%0,%1,%2,%3}, {%4,%5,%6,%7}, {%8,%9}, {%0,%1,%2,%3};"
                 : "+f"(d[0]), "+f"(d[1]), "+f"(d[2]), "+f"(d[3])
                 : "r"(a[0]), "r"(a[1]), "r"(a[2]), "r"(a[3]), "r"(b[0]), "r"(b[1]));
}
__device__ __forceinline__ void cpa16(uint32_t dst, const void* src, int bytes) {
    asm volatile("cp.async.cg.shared.global [%0], [%1], 16, %2;"
                 :: "r"(dst), "l"(src), "r"(bytes) : "memory");
}
__device__ __forceinline__ void split2(float x, float y, __nv_bfloat162& hi, __nv_bfloat162& lo) {
    hi = __floats2bfloat162_rn(x, y);
    float rx = x - __bfloat162float(hi.x);
    float ry = y - __bfloat162float(hi.y);
    lo = __floats2bfloat162_rn(rx, ry);
}

// ---------------- prep: activations fp32 -> bf16 hi/lo (q and v in one launch) ----------------
#define CBLK 6563   // ceil(MQ*64/256)
__global__ void prep_acts(const float* __restrict__ q, const float* __restrict__ v0,
                          const float* __restrict__ v1, const float* __restrict__ v2) {
    const int bid = blockIdx.x;
    const bool isq = (bid < CBLK);
    size_t i = (size_t)(isq ? bid : bid - CBLK) * 256 + threadIdx.x;
    if (i >= (size_t)MQ * 64) return;
    float4 v;
    if (isq) {
        v = ((const float4*)q)[i];
    } else {
        int row = (int)(i >> 6), c = (int)(i & 63);
        const float4* src;
        if (row < 20000)      src = (const float4*)(v0 + (size_t)row * 256);
        else if (row < 25000) src = (const float4*)(v1 + (size_t)(row - 20000) * 256);
        else                  src = (const float4*)(v2 + (size_t)(row - 25000) * 256);
        v = src[c];
    }
    __nv_bfloat162 h0, l0, h1, l1;
    split2(v.x, v.y, h0, l0);
    split2(v.z, v.w, h1, l1);
    __nv_bfloat16 *dh = isq ? g_qhi : g_vhi, *dl = isq ? g_qlo : g_vlo;
    ((__nv_bfloat162*)dh)[i * 2 + 0] = h0; ((__nv_bfloat162*)dh)[i * 2 + 1] = h1;
    ((__nv_bfloat162*)dl)[i * 2 + 0] = l0; ((__nv_bfloat162*)dl)[i * 2 + 1] = l1;
}

// ---------------- prep: all weight transposes + pad + combined bias, one launch ----------------
__global__ void prep_weights(const float* __restrict__ W_val, const float* __restrict__ W_off,
                             const float* __restrict__ W_attn, const float* __restrict__ W_out,
                             const float* __restrict__ b_off, const float* __restrict__ b_attn) {
    const int id = blockIdx.x;
    if (id >= 200) {   // fixup: zero pad rows 544..575 + combined bias (flat thread index)
        const int t = threadIdx.y * 32 + threadIdx.x;
        const int i = (id - 200) * 256 + t;
        if (i < 32 * 256) {
            g_bthi[(size_t)544 * 256 + i] = __float2bfloat16_rn(0.f);
            g_btlo[(size_t)544 * 256 + i] = __float2bfloat16_rn(0.f);
        }
        if (i < 320)
            g_biasq[i] = (i < 192) ? b_off[i] : (i < 288 ? b_attn[i - 192] : 0.f);
        return;
    }
    const float* W; int btrow, N, tix;
    if (id < 64)       { W = W_val;  btrow = 0;   N = 256; tix = id;      }
    else if (id < 112) { W = W_off;  btrow = 256; N = 192; tix = id - 64; }
    else if (id < 136) { W = W_attn; btrow = 448; N = 96;  tix = id - 112;}
    else               { W = W_out;  btrow = 576; N = 256; tix = id - 136;}
    const int ntiles = N / 32;
    const int n0 = (tix % ntiles) * 32, k0 = (tix / ntiles) * 32;

    __shared__ float t[32][33];
    #pragma unroll
    for (int j = 0; j < 4; j++) {
        int k = k0 + threadIdx.y + 8 * j;
        int n = n0 + threadIdx.x;
        t[threadIdx.y + 8 * j][threadIdx.x] = W[(size_t)k * N + n];
    }
    __syncthreads();
    #pragma unroll
    for (int j = 0; j < 4; j++) {
        int n = n0 + threadIdx.y + 8 * j;
        int k = k0 + threadIdx.x;
        float x = t[threadIdx.x][threadIdx.y + 8 * j];
        __nv_bfloat16 hi = __float2bfloat16_rn(x);
        g_bthi[(size_t)(btrow + n) * 256 + k] = hi;
        g_btlo[(size_t)(btrow + n) * 256 + k] = __float2bfloat16_rn(x - __bfloat162float(hi));
    }
}

// ---------------- split-bf16 tensor-core GEMM, 3-stage cp.async pipeline ----------------
#define ASTR 40
#define A_HALVES (128 * ASTR)
#define B_HALVES (64 * ASTR)
#define STG_HALVES (2 * A_HALVES + 2 * B_HALVES)
#define STG_BYTES  (STG_HALVES * 2)
#define OFF_AH 0
#define OFF_AL A_HALVES
#define OFF_BH (2 * A_HALVES)
#define OFF_BL (2 * A_HALVES + B_HALVES)
#define GEMM_DYNSMEM (3 * STG_BYTES)

__global__ __launch_bounds__(256, 2)
void gemm_bf16(int fusedvq, int asel_p, int btoff_p, const float* __restrict__ biasp,
               float* __restrict__ Cout, int M, int N_p, int remap_p)
{
    extern __shared__ __align__(16) __nv_bfloat16 dsm[];
    const uint32_t sbase = smem_to_u32(dsm);

    int asel = asel_p, btoff = btoff_p, N = N_p, remap = remap_p, n0;
    const float* bias = biasp;
    float* C;
    if (fusedvq) {
        if (blockIdx.y < 4) { asel = 1; btoff = 0;   N = 256; remap = 1; n0 = blockIdx.y * 64;      C = g_vproj; }
        else                { asel = 0; btoff = 256; N = 320; remap = 0; n0 = (blockIdx.y - 4) * 64; C = g_qout; bias = g_biasq; }
    } else {
        n0 = blockIdx.y * 64;
        C = Cout;
    }

    const __nv_bfloat16 *Ahi, *Alo;
    if (asel == 0)      { Ahi = g_qhi; Alo = g_qlo; }
    else if (asel == 1) { Ahi = g_vhi; Alo = g_vlo; }
    else                { Ahi = g_mhi; Alo = g_mlo; }
    const __nv_bfloat16* Bhi = g_bthi + (size_t)btoff * 256;
    const __nv_bfloat16* Blo = g_btlo + (size_t)btoff * 256;

    const int tid = threadIdx.x, lane = tid & 31, wid = tid >> 5;
    const int wm = wid >> 1, wn = wid & 1;
    const int row0 = blockIdx.x * 128;
    const int lr = tid >> 2, lc = tid & 3;

    auto issue = [&](int kt) {
        const uint32_t st = sbase + (uint32_t)((kt % 3) * STG_BYTES);
        const int k0 = kt * 32;
        #pragma unroll
        for (int t = 0; t < 2; t++) {
            const int r  = lr + t * 64;
            const int gr = row0 + r;
            const bool v = (gr < M);
            const size_t go = (size_t)(v ? gr : 0) * 256 + k0 + lc * 8;
            const uint32_t so = (uint32_t)((r * ASTR + lc * 8) * 2);
            cpa16(st + OFF_AH * 2 + so, Ahi + go, v ? 16 : 0);
            cpa16(st + OFF_AL * 2 + so, Alo + go, v ? 16 : 0);
        }
        {
            const size_t go = (size_t)(n0 + lr) * 256 + k0 + lc * 8;
            const uint32_t so = (uint32_t)((lr * ASTR + lc * 8) * 2);
            cpa16(st + OFF_BH * 2 + so, Bhi + go, 16);
            cpa16(st + OFF_BL * 2 + so, Blo + go, 16);
        }
        asm volatile("cp.async.commit_group;" ::: "memory");
    };

    float acc[2][4][4] = {};

    issue(0);
    issue(1);
    #pragma unroll 1
    for (int kt = 0; kt < 8; kt++) {
        if (kt < 7) asm volatile("cp.async.wait_group 1;" ::: "memory");
        else        asm volatile("cp.async.wait_group 0;" ::: "memory");
        __syncthreads();
        if (kt + 2 < 8) issue(kt + 2);

        const uint32_t st = sbase + (uint32_t)((kt % 3) * STG_BYTES);
        const uint32_t uAh = st + OFF_AH * 2, uAl = st + OFF_AL * 2;
        const uint32_t uBh = st + OFF_BH * 2, uBl = st + OFF_BL * 2;
        const int lrow = lane & 15, lkc = lane >> 4;

        #pragma unroll
        for (int kk = 0; kk < 2; kk++) {
            uint32_t fah[2][4], fal[2][4], fbh[2][4], fbl[2][4];
            #pragma unroll
            for (int mt = 0; mt < 2; mt++) {
                uint32_t off = (uint32_t)(((wm * 32 + mt * 16 + lrow) * ASTR + kk * 16 + lkc * 8) * 2);
                ldm4(fah[mt], uAh + off);
                ldm4(fal[mt], uAl + off);
            }
            #pragma unroll
            for (int ng = 0; ng < 2; ng++) {
                uint32_t off = (uint32_t)(((wn * 32 + ng * 16 + lrow) * ASTR + kk * 16 + lkc * 8) * 2);
                ldm4(fbh[ng], uBh + off);
                ldm4(fbl[ng], uBl + off);
            }
            #pragma unroll
            for (int mt = 0; mt < 2; mt++) {
                #pragma unroll
                for (int n = 0; n < 4; n++) {
                    uint32_t bh[2] = { fbh[n >> 1][n & 1], fbh[n >> 1][(n & 1) + 2] };
                    uint32_t bl[2] = { fbl[n >> 1][n & 1], fbl[n >> 1][(n & 1) + 2] };
                    mma16816(acc[mt][n], fah[mt], bh);
                    mma16816(acc[mt][n], fal[mt], bh);
                    mma16816(acc[mt][n], fah[mt], bl);
                }
            }
        }
    }

    // epilogue
    const int er = lane >> 2, ec = (lane & 3) * 2;
    #pragma unroll
    for (int mt = 0; mt < 2; mt++) {
        #pragma unroll
        for (int n = 0; n < 4; n++) {
            int col = n0 + wn * 32 + n * 8 + ec;
            float b0 = __ldg(bias + col), b1 = __ldg(bias + col + 1);
            #pragma unroll
            for (int h2 = 0; h2 < 2; h2++) {
                int row = row0 + wm * 32 + mt * 16 + er + 8 * h2;
                if (row < M) {
                    int orow = row;
                    if (remap) {
                        if (row < 20000)      orow = (row / 10000) * NQ + (row % 10000);
                        else if (row < 25000) { int rr = row - 20000; orow = (rr / 2500) * NQ + 10000 + rr % 2500; }
                        else                  { int rr = row - 25000; orow = (rr / 625)  * NQ + 12500 + rr % 625; }
                    }
                    float2 o = make_float2(acc[mt][n][2 * h2] + b0, acc[mt][n][2 * h2 + 1] + b1);
                    *(float2*)(C + (size_t)orow * N + col) = o;
                }
            }
        }
    }
}

// ---------------- fused softmax + deformable bilinear sampling (2-phase) ----------------
// warp = (query, head). Phase 1: lanes 0..11 compute per-point folded weights +
// absolute corner byte-offsets once, stage in smem. Phase 2: lanes pg(2b)xcq(3b)
// do pure LDS + gather + FMA.
__global__ __launch_bounds__(256, 6)
void msda_sample(const float* __restrict__ rp)
{
    __shared__ uint4  s_off[96];   // [h*12 + j] corner byte offsets
    __shared__ float4 s_w  [96];   // [h*12 + j] folded bilinear*prob weights

    const int bq   = blockIdx.x;
    const int h    = threadIdx.x >> 5;
    const int lane = threadIdx.x & 31;
    const int pg   = lane >> 3;     // point group 0..3
    const int cq   = lane & 7;      // channel quad 0..7

    const uint32_t batOff = (bq >= NQ) ? (uint32_t)NQ * 1024u : 0u;

    // ---- phase 1: softmax + per-point params (lanes 0..11) ----
    float lv = -1e30f;
    if (lane < 12)
        lv = g_qout[(size_t)bq * 320 + 192 + h * 12 + lane];
    float m = lv;
    #pragma unroll
    for (int o = 8; o; o >>= 1) m = fmaxf(m, __shfl_xor_sync(0xffffffffu, m, o));
    float e = (lane < 12) ? __expf(lv - m) : 0.f;
    float s = e;
    #pragma unroll
    for (int o = 8; o; o >>= 1) s += __shfl_xor_sync(0xffffffffu, s, o);

    if (lane < 12) {
        const float a = e / s;
        const int l = lane >> 2, p = lane & 3;
        const int Wi = 100 >> l, Hi = 100 >> l;
        const uint32_t loff = (l > 0 ? 10000u : 0u) + (l > 1 ? 2500u : 0u);
        const float Wf = (float)Wi, Hf = (float)Hi;

        const float2 rxy = *(const float2*)(rp + (size_t)bq * 6 + l * 2);
        const float2 oxy = *(const float2*)(g_qout + (size_t)bq * 320 + h * 24 + l * 8 + p * 2);

        const float x = (rxy.x + oxy.x * (1.0f / Wf)) * Wf - 0.5f;
        const float y = (rxy.y + oxy.y * (1.0f / Hf)) * Hf - 0.5f;
        const float x0f = floorf(x), y0f = floorf(y);
        const float wx1 = x - x0f,  wy1 = y - y0f;
        const int ix0 = (int)x0f, iy0 = (int)y0f;
        const int ix1 = ix0 + 1,  iy1 = iy0 + 1;

        const float ax0 = (ix0 >= 0 && ix0 < Wi) ? (1.f - wx1) * a : 0.f;
        const float ax1 = (ix1 >= 0 && ix1 < Wi) ? wx1 * a : 0.f;
        const float my0 = (iy0 >= 0 && iy0 < Hi) ? (1.f - wy1) : 0.f;
        const float my1 = (iy1 >= 0 && iy1 < Hi) ? wy1 : 0.f;

        const int ix0c = min(max(ix0, 0), Wi - 1), ix1c = min(max(ix1, 0), Wi - 1);
        const int iy0c = min(max(iy0, 0), Hi - 1), iy1c = min(max(iy1, 0), Hi - 1);

        const uint32_t base = batOff + loff * 1024u;
        const uint32_t r0 = base + (uint32_t)(iy0c * Wi) * 1024u;
        const uint32_t r1 = base + (uint32_t)(iy1c * Wi) * 1024u;
        const uint32_t cx0 = (uint32_t)ix0c * 1024u, cx1 = (uint32_t)ix1c * 1024u;

        s_off[h * 12 + lane] = make_uint4(r0 + cx0, r0 + cx1, r1 + cx0, r1 + cx1);
        s_w  [h * 12 + lane] = make_float4(ax0 * my0, ax1 * my0, ax0 * my1, ax1 * my1);
    }
    __syncwarp();

    // ---- phase 2: gather + FMA ----
    const char* vb = (const char*)g_vproj;
    const uint32_t laneOff = (uint32_t)((h * HD + cq * 4) * 4);
    float4 acc = make_float4(0.f, 0.f, 0.f, 0.f);

    #pragma unroll
    for (int l = 0; l < LVL; l++) {
        const int idx = h * 12 + l * 4 + pg;
        const uint4  o4 = s_off[idx];
        const float4 w4 = s_w[idx];

        const float4 v00 = *(const float4*)(vb + (o4.x + laneOff));
        const float4 v01 = *(const float4*)(vb + (o4.y + laneOff));
        const float4 v10 = *(const float4*)(vb + (o4.z + laneOff));
        const float4 v11 = *(const float4*)(vb + (o4.w + laneOff));

        acc.x = fmaf(w4.x, v00.x, acc.x); acc.y = fmaf(w4.x, v00.y, acc.y);
        acc.z = fmaf(w4.x, v00.z, acc.z); acc.w = fmaf(w4.x, v00.w, acc.w);
        acc.x = fmaf(w4.y, v01.x, acc.x); acc.y = fmaf(w4.y, v01.y, acc.y);
        acc.z = fmaf(w4.y, v01.z, acc.z); acc.w = fmaf(w4.y, v01.w, acc.w);
        acc.x = fmaf(w4.z, v10.x, acc.x); acc.y = fmaf(w4.z, v10.y, acc.y);
        acc.z = fmaf(w4.z, v10.z, acc.z); acc.w = fmaf(w4.z, v10.w, acc.w);
        acc.x = fmaf(w4.w, v11.x, acc.x); acc.y = fmaf(w4.w, v11.y, acc.y);
        acc.z = fmaf(w4.w, v11.z, acc.z); acc.w = fmaf(w4.w, v11.w, acc.w);
    }

    // reduce across the 4 point groups (lanes differing in bits 3,4)
    #pragma unroll
    for (int o = 8; o <= 16; o <<= 1) {
        acc.x += __shfl_xor_sync(0xffffffffu, acc.x, o);
        acc.y += __shfl_xor_sync(0xffffffffu, acc.y, o);
        acc.z += __shfl_xor_sync(0xffffffffu, acc.z, o);
        acc.w += __shfl_xor_sync(0xffffffffu, acc.w, o);
    }

    if (pg == 0) {
        const size_t oi = (size_t)bq * DMODEL + h * HD + cq * 4;
        __nv_bfloat162 h0, l0, h1, l1;
        split2(acc.x, acc.y, h0, l0);
        split2(acc.z, acc.w, h1, l1);
        *(uint2*)(g_mhi + oi) = make_uint2(*(uint32_t*)&h0, *(uint32_t*)&h1);
        *(uint2*)(g_mlo + oi) = make_uint2(*(uint32_t*)&l0, *(uint32_t*)&l1);
    }
}

// ---------------- launch ----------------
extern "C" void kernel_launch(void* const* d_in, const int* in_sizes, int n_in,
                              void* d_out, int out_size)
{
    const float* query  = (const float*)d_in[0];
    const float* rp     = (const float*)d_in[1];
    const float* v0     = (const float*)d_in[2];
    const float* v1     = (const float*)d_in[3];
    const float* v2     = (const float*)d_in[4];
    const float* W_val  = (const float*)d_in[5];
    const float* b_val  = (const float*)d_in[6];
    const float* W_off  = (const float*)d_in[7];
    const float* b_off  = (const float*)d_in[8];
    const float* W_attn = (const float*)d_in[9];
    const float* b_attn = (const float*)d_in[10];
    const float* W_out  = (const float*)d_in[11];
    const float* b_out  = (const float*)d_in[12];
    float* out = (float*)d_out;

    cudaFuncSetAttribute(gemm_bf16, cudaFuncAttributeMaxDynamicSharedMemorySize, GEMM_DYNSMEM);

    // 1: all weight prep (4 transposes + pad + bias) in one launch
    prep_weights<<<233, dim3(32, 8)>>>(W_val, W_off, W_attn, W_out, b_off, b_attn);
    // 2: activation bf16 hi/lo splits (q + v) in one launch
    prep_acts<<<2 * CBLK, 256>>>(query, v0, v1, v2);
    // 3: fused vproj (y=0..3) + qout (y=4..8) GEMM, 3-term split-bf16
    gemm_bf16<<<dim3(206, 9), 256, GEMM_DYNSMEM>>>(1, 0, 0, b_val, nullptr, MQ, 0, 0);
    // 4: fused softmax + deformable sampling (2-phase, smem-staged params)
    msda_sample<<<MQ, 256>>>(rp);
    // 5: output projection
    gemm_bf16<<<dim3(206, 4), 256, GEMM_DYNSMEM>>>(0, 2, 576, b_out, out, MQ, 256, 0);
}

// round 12
// speedup vs baseline: 2.5521x; 1.0216x over previous
#include <cuda_runtime.h>
#include <cuda_bf16.h>
#include <math.h>
#include <stdint.h>

// ---------------- problem constants ----------------
#define NQ      13125
#define BATCH   2
#define MQ      (BATCH * NQ)     // 26250
#define DMODEL  256
#define HEADS   8
#define HD      32
#define LVL     3
#define PTS     4

// ---------------- scratch (static device memory; no allocation) ----------------
__device__ float g_vproj[(size_t)MQ * 256];   // projected values (fp32, for sampler)
__device__ float g_qout [(size_t)MQ * 320];   // [0..191]=offsets, [192..287]=logits, pad
__device__ float g_mid  [(size_t)MQ * 256];   // sampler output (fp32)
// transposed weights, bf16 hi/lo, [row][k]; rows: 0..255 W_val^T, 256..575 [W_off;W_attn;pad]^T, 576..831 W_out^T
__device__ __nv_bfloat16 g_bthi[832 * 256], g_btlo[832 * 256];
__device__ float g_biasq[320];

// ---------------- small helpers ----------------
__device__ __forceinline__ uint32_t smem_to_u32(const void* p) {
    uint32_t a;
    asm("{ .reg .u64 t; cvta.to.shared.u64 t, %1; cvt.u32.u64 %0, t; }" : "=r"(a) : "l"(p));
    return a;
}
__device__ __forceinline__ void ldm4(uint32_t* f, uint32_t addr) {
    asm volatile("ldmatrix.sync.aligned.m8n8.x4.shared.b16 {%0,%1,%2,%3}, [%4];"
                 : "=r"(f[0]), "=r"(f[1]), "=r"(f[2]), "=r"(f[3]) : "r"(addr));
}
__device__ __forceinline__ void mma16816(float* d, const uint32_t* a, const uint32_t* b) {
    asm volatile("mma.sync.aligned.m16n8k16.row.col.f32.bf16.bf16.f32 "
                 "{%0,%1,%2,%3}, {%4,%5,%6,%7}, {%8,%9}, {%0,%1,%2,%3};"
                 : "+f"(d[0]), "+f"(d[1]), "+f"(d[2]), "+f"(d[3])
                 : "r"(a[0]), "r"(a[1]), "r"(a[2]), "r"(a[3]), "r"(b[0]), "r"(b[1]));
}
__device__ __forceinline__ void cpa16(uint32_t dst, const void* src, int bytes) {
    asm volatile("cp.async.cg.shared.global [%0], [%1], 16, %2;"
                 :: "r"(dst), "l"(src), "r"(bytes) : "memory");
}
__device__ __forceinline__ void split2(float x, float y, __nv_bfloat162& hi, __nv_bfloat162& lo) {
    hi = __floats2bfloat162_rn(x, y);
    float rx = x - __bfloat162float(hi.x);
    float ry = y - __bfloat162float(hi.y);
    lo = __floats2bfloat162_rn(rx, ry);
}
__device__ __forceinline__ uint32_t b2u(__nv_bfloat162 v) { return *(uint32_t*)&v; }

// ---------------- prep: all weight transposes + pad + combined bias, one launch ----------------
__global__ void prep_weights(const float* __restrict__ W_val, const float* __restrict__ W_off,
                             const float* __restrict__ W_attn, const float* __restrict__ W_out,
                             const float* __restrict__ b_off, const float* __restrict__ b_attn) {
    const int id = blockIdx.x;
    if (id >= 200) {   // fixup: zero pad rows 544..575 + combined bias (flat thread index)
        const int t = threadIdx.y * 32 + threadIdx.x;
        const int i = (id - 200) * 256 + t;
        if (i < 32 * 256) {
            g_bthi[(size_t)544 * 256 + i] = __float2bfloat16_rn(0.f);
            g_btlo[(size_t)544 * 256 + i] = __float2bfloat16_rn(0.f);
        }
        if (i < 320)
            g_biasq[i] = (i < 192) ? b_off[i] : (i < 288 ? b_attn[i - 192] : 0.f);
        return;
    }
    const float* W; int btrow, N, tix;
    if (id < 64)       { W = W_val;  btrow = 0;   N = 256; tix = id;      }
    else if (id < 112) { W = W_off;  btrow = 256; N = 192; tix = id - 64; }
    else if (id < 136) { W = W_attn; btrow = 448; N = 96;  tix = id - 112;}
    else               { W = W_out;  btrow = 576; N = 256; tix = id - 136;}
    const int ntiles = N / 32;
    const int n0 = (tix % ntiles) * 32, k0 = (tix / ntiles) * 32;

    __shared__ float t[32][33];
    #pragma unroll
    for (int j = 0; j < 4; j++) {
        int k = k0 + threadIdx.y + 8 * j;
        int n = n0 + threadIdx.x;
        t[threadIdx.y + 8 * j][threadIdx.x] = W[(size_t)k * N + n];
    }
    __syncthreads();
    #pragma unroll
    for (int j = 0; j < 4; j++) {
        int n = n0 + threadIdx.y + 8 * j;
        int k = k0 + threadIdx.x;
        float x = t[threadIdx.x][threadIdx.y + 8 * j];
        __nv_bfloat16 hi = __float2bfloat16_rn(x);
        g_bthi[(size_t)(btrow + n) * 256 + k] = hi;
        g_btlo[(size_t)(btrow + n) * 256 + k] = __float2bfloat16_rn(x - __bfloat162float(hi));
    }
}

// ---------------- split-bf16 tensor-core GEMM with in-loader fp32->bf16 hi/lo split ----------------
// C[M,N] = Ah@Bh + Al@Bh + Ah@Bl + bias. A read as fp32 (query / values / g_mid),
// converted in the loader. B (weights) pre-split bf16, loaded via cp.async.
// BM=128, BN=64, BK=32; 8 warps 4(M)x2(N); single-buffered smem, reg-staged A prefetch.
#define ASTR 40
__global__ __launch_bounds__(256, 2)
void gemm_bf16(int fusedvq,
               const float* __restrict__ Aq, const float* __restrict__ Av0,
               const float* __restrict__ Av1, const float* __restrict__ Av2,
               int btoff_p, const float* __restrict__ biasp,
               float* __restrict__ Cout, int M, int N_p, int remap_p)
{
    __shared__ __align__(16) __nv_bfloat16 sAh[128 * ASTR];
    __shared__ __align__(16) __nv_bfloat16 sAl[128 * ASTR];
    __shared__ __align__(16) __nv_bfloat16 sBh[64 * ASTR];
    __shared__ __align__(16) __nv_bfloat16 sBl[64 * ASTR];

    int asel, btoff = btoff_p, N = N_p, remap = remap_p, n0;
    const float* bias = biasp;
    float* C;
    if (fusedvq) {
        if (blockIdx.y < 4) { asel = 1; btoff = 0;   N = 256; remap = 1; n0 = blockIdx.y * 64;      C = g_vproj; }
        else                { asel = 0; btoff = 256; N = 320; remap = 0; n0 = (blockIdx.y - 4) * 64; C = g_qout; bias = g_biasq; }
    } else {
        asel = 2; n0 = blockIdx.y * 64; C = Cout;
    }

    const __nv_bfloat16* Bhi = g_bthi + (size_t)btoff * 256;
    const __nv_bfloat16* Blo = g_btlo + (size_t)btoff * 256;

    const int tid = threadIdx.x, lane = tid & 31, wid = tid >> 5;
    const int wm = wid >> 1, wn = wid & 1;
    const int row0 = blockIdx.x * 128;

    // ---- A loader: 2 threads per row, each covers 16 fp32 of the 32-wide k-slice ----
    const int ar = tid >> 1, ah = tid & 1;
    const float* arow;
    {
        int gr = row0 + ar;
        int rr = (gr < M) ? gr : 0;
        if (asel == 1) {
            if (rr < 20000)      arow = Av0 + (size_t)rr * 256;
            else if (rr < 25000) arow = Av1 + (size_t)(rr - 20000) * 256;
            else                 arow = Av2 + (size_t)(rr - 25000) * 256;
        } else if (asel == 0) {
            arow = Aq + (size_t)rr * 256;
        } else {
            arow = g_mid + (size_t)rr * 256;   // device-symbol resolved in device code
        }
        arow += ah * 16;
    }

    // ---- B loader mapping ----
    const int lr = tid >> 2, lc = tid & 3;
    const uint32_t uAh = smem_to_u32(sAh), uAl = smem_to_u32(sAl);
    const uint32_t uBh = smem_to_u32(sBh), uBl = smem_to_u32(sBl);

    float4 ra0, ra1, ra2, ra3;
    auto ldA = [&](int kt) {
        const float4* p = (const float4*)(arow + kt * 32);
        ra0 = p[0]; ra1 = p[1]; ra2 = p[2]; ra3 = p[3];
    };
    auto stsA = [&]() {
        __nv_bfloat162 h0, l0, h1, l1, h2, l2, h3, l3;
        split2(ra0.x, ra0.y, h0, l0); split2(ra0.z, ra0.w, h1, l1);
        split2(ra1.x, ra1.y, h2, l2); split2(ra1.z, ra1.w, h3, l3);
        *(uint4*)&sAh[ar * ASTR + ah * 16]     = make_uint4(b2u(h0), b2u(h1), b2u(h2), b2u(h3));
        *(uint4*)&sAl[ar * ASTR + ah * 16]     = make_uint4(b2u(l0), b2u(l1), b2u(l2), b2u(l3));
        split2(ra2.x, ra2.y, h0, l0); split2(ra2.z, ra2.w, h1, l1);
        split2(ra3.x, ra3.y, h2, l2); split2(ra3.z, ra3.w, h3, l3);
        *(uint4*)&sAh[ar * ASTR + ah * 16 + 8] = make_uint4(b2u(h0), b2u(h1), b2u(h2), b2u(h3));
        *(uint4*)&sAl[ar * ASTR + ah * 16 + 8] = make_uint4(b2u(l0), b2u(l1), b2u(l2), b2u(l3));
    };
    auto issueB = [&](int kt) {
        const size_t go = (size_t)(n0 + lr) * 256 + kt * 32 + lc * 8;
        const uint32_t so = (uint32_t)((lr * ASTR + lc * 8) * 2);
        cpa16(uBh + so, Bhi + go, 16);
        cpa16(uBl + so, Blo + go, 16);
        asm volatile("cp.async.commit_group;" ::: "memory");
    };

    float acc[2][4][4] = {};

    ldA(0);
    #pragma unroll 1
    for (int kt = 0; kt < 8; kt++) {
        if (kt) __syncthreads();           // previous compute done; smem free
        issueB(kt);
        stsA();
        if (kt < 7) ldA(kt + 1);           // overlap next A LDG with B cp.async + compute
        asm volatile("cp.async.wait_group 0;" ::: "memory");
        __syncthreads();

        const int lrow = lane & 15, lkc = lane >> 4;
        #pragma unroll
        for (int kk = 0; kk < 2; kk++) {
            uint32_t fah[2][4], fal[2][4], fbh[2][4], fbl[2][4];
            #pragma unroll
            for (int mt = 0; mt < 2; mt++) {
                uint32_t off = (uint32_t)(((wm * 32 + mt * 16 + lrow) * ASTR + kk * 16 + lkc * 8) * 2);
                ldm4(fah[mt], uAh + off);
                ldm4(fal[mt], uAl + off);
            }
            #pragma unroll
            for (int ng = 0; ng < 2; ng++) {
                uint32_t off = (uint32_t)(((wn * 32 + ng * 16 + lrow) * ASTR + kk * 16 + lkc * 8) * 2);
                ldm4(fbh[ng], uBh + off);
                ldm4(fbl[ng], uBl + off);
            }
            #pragma unroll
            for (int mt = 0; mt < 2; mt++) {
                #pragma unroll
                for (int n = 0; n < 4; n++) {
                    uint32_t bh[2] = { fbh[n >> 1][n & 1], fbh[n >> 1][(n & 1) + 2] };
                    uint32_t bl[2] = { fbl[n >> 1][n & 1], fbl[n >> 1][(n & 1) + 2] };
                    mma16816(acc[mt][n], fah[mt], bh);
                    mma16816(acc[mt][n], fal[mt], bh);
                    mma16816(acc[mt][n], fah[mt], bl);
                }
            }
        }
    }

    // epilogue
    const int er = lane >> 2, ec = (lane & 3) * 2;
    #pragma unroll
    for (int mt = 0; mt < 2; mt++) {
        #pragma unroll
        for (int n = 0; n < 4; n++) {
            int col = n0 + wn * 32 + n * 8 + ec;
            float b0 = __ldg(bias + col), b1 = __ldg(bias + col + 1);
            #pragma unroll
            for (int h2 = 0; h2 < 2; h2++) {
                int row = row0 + wm * 32 + mt * 16 + er + 8 * h2;
                if (row < M) {
                    int orow = row;
                    if (remap) {
                        if (row < 20000)      orow = (row / 10000) * NQ + (row % 10000);
                        else if (row < 25000) { int rr = row - 20000; orow = (rr / 2500) * NQ + 10000 + rr % 2500; }
                        else                  { int rr = row - 25000; orow = (rr / 625)  * NQ + 12500 + rr % 625; }
                    }
                    float2 o = make_float2(acc[mt][n][2 * h2] + b0, acc[mt][n][2 * h2 + 1] + b1);
                    *(float2*)(C + (size_t)orow * N + col) = o;
                }
            }
        }
    }
}

// ---------------- fused softmax + deformable bilinear sampling (2-phase) ----------------
// warp = (query, head). Phase 1: lanes 0..11 compute per-point folded weights +
// absolute corner byte-offsets once, stage in smem. Phase 2: lanes pg(2b)xcq(3b)
// do pure LDS + gather + FMA. Output: fp32 g_mid.
__global__ __launch_bounds__(256, 6)
void msda_sample(const float* __restrict__ rp)
{
    __shared__ uint4  s_off[96];   // [h*12 + j] corner byte offsets
    __shared__ float4 s_w  [96];   // [h*12 + j] folded bilinear*prob weights

    const int bq   = blockIdx.x;
    const int h    = threadIdx.x >> 5;
    const int lane = threadIdx.x & 31;
    const int pg   = lane >> 3;     // point group 0..3
    const int cq   = lane & 7;      // channel quad 0..7

    const uint32_t batOff = (bq >= NQ) ? (uint32_t)NQ * 1024u : 0u;

    // ---- phase 1: softmax + per-point params (lanes 0..11) ----
    float lv = -1e30f;
    if (lane < 12)
        lv = g_qout[(size_t)bq * 320 + 192 + h * 12 + lane];
    float m = lv;
    #pragma unroll
    for (int o = 8; o; o >>= 1) m = fmaxf(m, __shfl_xor_sync(0xffffffffu, m, o));
    float e = (lane < 12) ? __expf(lv - m) : 0.f;
    float s = e;
    #pragma unroll
    for (int o = 8; o; o >>= 1) s += __shfl_xor_sync(0xffffffffu, s, o);

    if (lane < 12) {
        const float a = e / s;
        const int l = lane >> 2, p = lane & 3;
        const int Wi = 100 >> l, Hi = 100 >> l;
        const uint32_t loff = (l > 0 ? 10000u : 0u) + (l > 1 ? 2500u : 0u);
        const float Wf = (float)Wi, Hf = (float)Hi;

        const float2 rxy = *(const float2*)(rp + (size_t)bq * 6 + l * 2);
        const float2 oxy = *(const float2*)(g_qout + (size_t)bq * 320 + h * 24 + l * 8 + p * 2);

        const float x = (rxy.x + oxy.x * (1.0f / Wf)) * Wf - 0.5f;
        const float y = (rxy.y + oxy.y * (1.0f / Hf)) * Hf - 0.5f;
        const float x0f = floorf(x), y0f = floorf(y);
        const float wx1 = x - x0f,  wy1 = y - y0f;
        const int ix0 = (int)x0f, iy0 = (int)y0f;
        const int ix1 = ix0 + 1,  iy1 = iy0 + 1;

        const float ax0 = (ix0 >= 0 && ix0 < Wi) ? (1.f - wx1) * a : 0.f;
        const float ax1 = (ix1 >= 0 && ix1 < Wi) ? wx1 * a : 0.f;
        const float my0 = (iy0 >= 0 && iy0 < Hi) ? (1.f - wy1) : 0.f;
        const float my1 = (iy1 >= 0 && iy1 < Hi) ? wy1 : 0.f;

        const int ix0c = min(max(ix0, 0), Wi - 1), ix1c = min(max(ix1, 0), Wi - 1);
        const int iy0c = min(max(iy0, 0), Hi - 1), iy1c = min(max(iy1, 0), Hi - 1);

        const uint32_t base = batOff + loff * 1024u;
        const uint32_t r0 = base + (uint32_t)(iy0c * Wi) * 1024u;
        const uint32_t r1 = base + (uint32_t)(iy1c * Wi) * 1024u;
        const uint32_t cx0 = (uint32_t)ix0c * 1024u, cx1 = (uint32_t)ix1c * 1024u;

        s_off[h * 12 + lane] = make_uint4(r0 + cx0, r0 + cx1, r1 + cx0, r1 + cx1);
        s_w  [h * 12 + lane] = make_float4(ax0 * my0, ax1 * my0, ax0 * my1, ax1 * my1);
    }
    __syncwarp();

    // ---- phase 2: gather + FMA ----
    const char* vb = (const char*)g_vproj;
    const uint32_t laneOff = (uint32_t)((h * HD + cq * 4) * 4);
    float4 acc = make_float4(0.f, 0.f, 0.f, 0.f);

    #pragma unroll
    for (int l = 0; l < LVL; l++) {
        const int idx = h * 12 + l * 4 + pg;
        const uint4  o4 = s_off[idx];
        const float4 w4 = s_w[idx];

        const float4 v00 = *(const float4*)(vb + (o4.x + laneOff));
        const float4 v01 = *(const float4*)(vb + (o4.y + laneOff));
        const float4 v10 = *(const float4*)(vb + (o4.z + laneOff));
        const float4 v11 = *(const float4*)(vb + (o4.w + laneOff));

        acc.x = fmaf(w4.x, v00.x, acc.x); acc.y = fmaf(w4.x, v00.y, acc.y);
        acc.z = fmaf(w4.x, v00.z, acc.z); acc.w = fmaf(w4.x, v00.w, acc.w);
        acc.x = fmaf(w4.y, v01.x, acc.x); acc.y = fmaf(w4.y, v01.y, acc.y);
        acc.z = fmaf(w4.y, v01.z, acc.z); acc.w = fmaf(w4.y, v01.w, acc.w);
        acc.x = fmaf(w4.z, v10.x, acc.x); acc.y = fmaf(w4.z, v10.y, acc.y);
        acc.z = fmaf(w4.z, v10.z, acc.z); acc.w = fmaf(w4.z, v10.w, acc.w);
        acc.x = fmaf(w4.w, v11.x, acc.x); acc.y = fmaf(w4.w, v11.y, acc.y);
        acc.z = fmaf(w4.w, v11.z, acc.z); acc.w = fmaf(w4.w, v11.w, acc.w);
    }

    // reduce across the 4 point groups (lanes differing in bits 3,4)
    #pragma unroll
    for (int o = 8; o <= 16; o <<= 1) {
        acc.x += __shfl_xor_sync(0xffffffffu, acc.x, o);
        acc.y += __shfl_xor_sync(0xffffffffu, acc.y, o);
        acc.z += __shfl_xor_sync(0xffffffffu, acc.z, o);
        acc.w += __shfl_xor_sync(0xffffffffu, acc.w, o);
    }

    if (pg == 0)
        *(float4*)(g_mid + (size_t)bq * DMODEL + h * HD + cq * 4) = acc;
}

// ---------------- launch ----------------
extern "C" void kernel_launch(void* const* d_in, const int* in_sizes, int n_in,
                              void* d_out, int out_size)
{
    const float* query  = (const float*)d_in[0];
    const float* rp     = (const float*)d_in[1];
    const float* v0     = (const float*)d_in[2];
    const float* v1     = (const float*)d_in[3];
    const float* v2     = (const float*)d_in[4];
    const float* W_val  = (const float*)d_in[5];
    const float* b_val  = (const float*)d_in[6];
    const float* W_off  = (const float*)d_in[7];
    const float* b_off  = (const float*)d_in[8];
    const float* W_attn = (const float*)d_in[9];
    const float* b_attn = (const float*)d_in[10];
    const float* W_out  = (const float*)d_in[11];
    const float* b_out  = (const float*)d_in[12];
    float* out = (float*)d_out;

    // 1: all weight prep (4 transposes + pad + bias) in one launch
    prep_weights<<<233, dim3(32, 8)>>>(W_val, W_off, W_attn, W_out, b_off, b_attn);
    // 2: fused vproj (y=0..3) + qout (y=4..8) GEMM; A converted fp32->bf16 hi/lo in-loader
    gemm_bf16<<<dim3(206, 9), 256>>>(1, query, v0, v1, v2, 0, b_val,
                                     nullptr, MQ, 0, 0);
    // 3: fused softmax + deformable sampling -> g_mid (fp32)
    msda_sample<<<MQ, 256>>>(rp);
    // 4: output projection (A = g_mid, resolved in device code; split in-loader)
    gemm_bf16<<<dim3(206, 4), 256>>>(0, nullptr, nullptr, nullptr, nullptr, 576, b_out,
                                     out, MQ, 256, 0);
}

// round 13
// speedup vs baseline: 2.5578x; 1.0022x over previous
#include <cuda_runtime.h>
#include <cuda_bf16.h>
#include <math.h>
#include <stdint.h>

// ---------------- problem constants ----------------
#define NQ      13125
#define BATCH   2
#define MQ      (BATCH * NQ)     // 26250
#define DMODEL  256
#define HEADS   8
#define HD      32
#define LVL     3
#define PTS     4

// ---------------- scratch (static device memory; no allocation) ----------------
__device__ float g_vproj[(size_t)MQ * 256];   // projected values (fp32, for sampler)
__device__ float g_qout [(size_t)MQ * 320];   // [0..191]=offsets, [192..287]=logits, pad
__device__ float g_mid  [(size_t)MQ * 256];   // sampler output (fp32)
// transposed weights, bf16 hi/lo, [row][k]; rows: 0..255 W_val^T, 256..575 [W_off;W_attn;pad]^T, 576..831 W_out^T
__device__ __nv_bfloat16 g_bthi[832 * 256], g_btlo[832 * 256];
__device__ float g_biasq[320];

// ---------------- small helpers ----------------
__device__ __forceinline__ uint32_t smem_to_u32(const void* p) {
    uint32_t a;
    asm("{ .reg .u64 t; cvta.to.shared.u64 t, %1; cvt.u32.u64 %0, t; }" : "=r"(a) : "l"(p));
    return a;
}
__device__ __forceinline__ void ldm4(uint32_t* f, uint32_t addr) {
    asm volatile("ldmatrix.sync.aligned.m8n8.x4.shared.b16 {%0,%1,%2,%3}, [%4];"
                 : "=r"(f[0]), "=r"(f[1]), "=r"(f[2]), "=r"(f[3]) : "r"(addr));
}
__device__ __forceinline__ void mma16816(float* d, const uint32_t* a, const uint32_t* b) {
    asm volatile("mma.sync.aligned.m16n8k16.row.col.f32.bf16.bf16.f32 "
                 "{%0,%1,%2,%3}, {%4,%5,%6,%7}, {%8,%9}, {%0,%1,%2,%3};"
                 : "+f"(d[0]), "+f"(d[1]), "+f"(d[2]), "+f"(d[3])
                 : "r"(a[0]), "r"(a[1]), "r"(a[2]), "r"(a[3]), "r"(b[0]), "r"(b[1]));
}
__device__ __forceinline__ void cpa16(uint32_t dst, const void* src, int bytes) {
    asm volatile("cp.async.cg.shared.global [%0], [%1], 16, %2;"
                 :: "r"(dst), "l"(src), "r"(bytes) : "memory");
}
__device__ __forceinline__ void split2(float x, float y, __nv_bfloat162& hi, __nv_bfloat162& lo) {
    hi = __floats2bfloat162_rn(x, y);
    float rx = x - __bfloat162float(hi.x);
    float ry = y - __bfloat162float(hi.y);
    lo = __floats2bfloat162_rn(rx, ry);
}
__device__ __forceinline__ uint32_t b2u(__nv_bfloat162 v) { return *(uint32_t*)&v; }

// ---------------- prep: all weight transposes + pad + combined bias, one launch ----------------
__global__ void prep_weights(const float* __restrict__ W_val, const float* __restrict__ W_off,
                             const float* __restrict__ W_attn, const float* __restrict__ W_out,
                             const float* __restrict__ b_off, const float* __restrict__ b_attn) {
    const int id = blockIdx.x;
    if (id >= 200) {   // fixup: zero pad rows 544..575 + combined bias (flat thread index)
        const int t = threadIdx.y * 32 + threadIdx.x;
        const int i = (id - 200) * 256 + t;
        if (i < 32 * 256) {
            g_bthi[(size_t)544 * 256 + i] = __float2bfloat16_rn(0.f);
            g_btlo[(size_t)544 * 256 + i] = __float2bfloat16_rn(0.f);
        }
        if (i < 320)
            g_biasq[i] = (i < 192) ? b_off[i] : (i < 288 ? b_attn[i - 192] : 0.f);
        return;
    }
    const float* W; int btrow, N, tix;
    if (id < 64)       { W = W_val;  btrow = 0;   N = 256; tix = id;      }
    else if (id < 112) { W = W_off;  btrow = 256; N = 192; tix = id - 64; }
    else if (id < 136) { W = W_attn; btrow = 448; N = 96;  tix = id - 112;}
    else               { W = W_out;  btrow = 576; N = 256; tix = id - 136;}
    const int ntiles = N / 32;
    const int n0 = (tix % ntiles) * 32, k0 = (tix / ntiles) * 32;

    __shared__ float t[32][33];
    #pragma unroll
    for (int j = 0; j < 4; j++) {
        int k = k0 + threadIdx.y + 8 * j;
        int n = n0 + threadIdx.x;
        t[threadIdx.y + 8 * j][threadIdx.x] = W[(size_t)k * N + n];
    }
    __syncthreads();
    #pragma unroll
    for (int j = 0; j < 4; j++) {
        int n = n0 + threadIdx.y + 8 * j;
        int k = k0 + threadIdx.x;
        float x = t[threadIdx.x][threadIdx.y + 8 * j];
        __nv_bfloat16 hi = __float2bfloat16_rn(x);
        g_bthi[(size_t)(btrow + n) * 256 + k] = hi;
        g_btlo[(size_t)(btrow + n) * 256 + k] = __float2bfloat16_rn(x - __bfloat162float(hi));
    }
}

// ---------------- split-bf16 tensor-core GEMM, 2-stage double-buffered ----------------
// C[M,N] = Ah@Bh + Al@Bh + Ah@Bl + bias. A read fp32, split in-loader (LDG->STS).
// B pre-split bf16 via cp.async, issued one K-tile ahead (latency hidden by compute).
// BM=128, BN=64, BK=32; 8 warps 4(M)x2(N). One __syncthreads per K-tile.
#define ASTR 40
#define A_HALVES (128 * ASTR)                      // 5120
#define B_HALVES (64 * ASTR)                       // 2560
#define STGH (2 * A_HALVES + 2 * B_HALVES)         // 15360 halves
#define STGB (STGH * 2)                            // 30720 bytes
#define GEMM_DYNSMEM (2 * STGB)                    // 61440

__global__ __launch_bounds__(256, 2)
void gemm_bf16(int fusedvq,
               const float* __restrict__ Aq, const float* __restrict__ Av0,
               const float* __restrict__ Av1, const float* __restrict__ Av2,
               int btoff_p, const float* __restrict__ biasp,
               float* __restrict__ Cout, int M, int N_p, int remap_p)
{
    extern __shared__ __align__(16) __nv_bfloat16 dsm[];
    const uint32_t sb = smem_to_u32(dsm);

    int asel, btoff = btoff_p, N = N_p, remap = remap_p, n0;
    const float* bias = biasp;
    float* C;
    if (fusedvq) {
        if (blockIdx.y < 4) { asel = 1; btoff = 0;   N = 256; remap = 1; n0 = blockIdx.y * 64;      C = g_vproj; }
        else                { asel = 0; btoff = 256; N = 320; remap = 0; n0 = (blockIdx.y - 4) * 64; C = g_qout; bias = g_biasq; }
    } else {
        asel = 2; n0 = blockIdx.y * 64; C = Cout;
    }

    const __nv_bfloat16* Bhi = g_bthi + (size_t)btoff * 256;
    const __nv_bfloat16* Blo = g_btlo + (size_t)btoff * 256;

    const int tid = threadIdx.x, lane = tid & 31, wid = tid >> 5;
    const int wm = wid >> 1, wn = wid & 1;
    const int row0 = blockIdx.x * 128;

    // ---- A loader: 2 threads per row, each covers 16 fp32 of the 32-wide k-slice ----
    const int ar = tid >> 1, ah = tid & 1;
    const float* arow;
    {
        int gr = row0 + ar;
        int rr = (gr < M) ? gr : 0;
        if (asel == 1) {
            if (rr < 20000)      arow = Av0 + (size_t)rr * 256;
            else if (rr < 25000) arow = Av1 + (size_t)(rr - 20000) * 256;
            else                 arow = Av2 + (size_t)(rr - 25000) * 256;
        } else if (asel == 0) {
            arow = Aq + (size_t)rr * 256;
        } else {
            arow = g_mid + (size_t)rr * 256;   // device symbol resolved in device code
        }
        arow += ah * 16;
    }

    // ---- B loader mapping ----
    const int lr = tid >> 2, lc = tid & 3;

    float4 ra0, ra1, ra2, ra3;
    auto ldA = [&](int kt) {
        const float4* p = (const float4*)(arow + kt * 32);
        ra0 = p[0]; ra1 = p[1]; ra2 = p[2]; ra3 = p[3];
    };
    auto stsA = [&](int s) {
        char* base = (char*)dsm + s * STGB;
        __nv_bfloat162 h0, l0, h1, l1, h2, l2, h3, l3;
        split2(ra0.x, ra0.y, h0, l0); split2(ra0.z, ra0.w, h1, l1);
        split2(ra1.x, ra1.y, h2, l2); split2(ra1.z, ra1.w, h3, l3);
        *(uint4*)(base + (ar * ASTR + ah * 16) * 2)                  = make_uint4(b2u(h0), b2u(h1), b2u(h2), b2u(h3));
        *(uint4*)(base + (A_HALVES + ar * ASTR + ah * 16) * 2)       = make_uint4(b2u(l0), b2u(l1), b2u(l2), b2u(l3));
        split2(ra2.x, ra2.y, h0, l0); split2(ra2.z, ra2.w, h1, l1);
        split2(ra3.x, ra3.y, h2, l2); split2(ra3.z, ra3.w, h3, l3);
        *(uint4*)(base + (ar * ASTR + ah * 16 + 8) * 2)              = make_uint4(b2u(h0), b2u(h1), b2u(h2), b2u(h3));
        *(uint4*)(base + (A_HALVES + ar * ASTR + ah * 16 + 8) * 2)   = make_uint4(b2u(l0), b2u(l1), b2u(l2), b2u(l3));
    };
    auto issueB = [&](int kt, int s) {
        const size_t go = (size_t)(n0 + lr) * 256 + kt * 32 + lc * 8;
        const uint32_t so = (uint32_t)((lr * ASTR + lc * 8) * 2);
        const uint32_t st = sb + (uint32_t)(s * STGB);
        cpa16(st + 2 * A_HALVES * 2 + so, Bhi + go, 16);
        cpa16(st + (2 * A_HALVES + B_HALVES) * 2 + so, Blo + go, 16);
        asm volatile("cp.async.commit_group;" ::: "memory");
    };

    float acc[2][4][4] = {};

    ldA(0);
    issueB(0, 0);
    #pragma unroll 1
    for (int kt = 0; kt < 8; kt++) {
        const int s = kt & 1;
        // write phase: A stage s was last READ by compute(kt-2); all threads passed
        // sync(kt-1) after that compute, so stores here are race-free.
        stsA(s);
        // B(kt) was issued during compute(kt-1) (or prologue) -> latency hidden.
        asm volatile("cp.async.wait_group 0;" ::: "memory");
        __syncthreads();
        // read phase: stage s^1 smem was read by compute(kt-1), which every thread
        // finished before sync above -> safe to overwrite via cp.async now.
        if (kt < 7) { issueB(kt + 1, s ^ 1); ldA(kt + 1); }

        const uint32_t st = sb + (uint32_t)(s * STGB);
        const uint32_t uAh = st, uAl = st + A_HALVES * 2;
        const uint32_t uBh = st + 2 * A_HALVES * 2, uBl = st + (2 * A_HALVES + B_HALVES) * 2;
        const int lrow = lane & 15, lkc = lane >> 4;

        #pragma unroll
        for (int kk = 0; kk < 2; kk++) {
            uint32_t fah[2][4], fal[2][4], fbh[2][4], fbl[2][4];
            #pragma unroll
            for (int mt = 0; mt < 2; mt++) {
                uint32_t off = (uint32_t)(((wm * 32 + mt * 16 + lrow) * ASTR + kk * 16 + lkc * 8) * 2);
                ldm4(fah[mt], uAh + off);
                ldm4(fal[mt], uAl + off);
            }
            #pragma unroll
            for (int ng = 0; ng < 2; ng++) {
                uint32_t off = (uint32_t)(((wn * 32 + ng * 16 + lrow) * ASTR + kk * 16 + lkc * 8) * 2);
                ldm4(fbh[ng], uBh + off);
                ldm4(fbl[ng], uBl + off);
            }
            #pragma unroll
            for (int mt = 0; mt < 2; mt++) {
                #pragma unroll
                for (int n = 0; n < 4; n++) {
                    uint32_t bh[2] = { fbh[n >> 1][n & 1], fbh[n >> 1][(n & 1) + 2] };
                    uint32_t bl[2] = { fbl[n >> 1][n & 1], fbl[n >> 1][(n & 1) + 2] };
                    mma16816(acc[mt][n], fah[mt], bh);
                    mma16816(acc[mt][n], fal[mt], bh);
                    mma16816(acc[mt][n], fah[mt], bl);
                }
            }
        }
    }

    // epilogue
    const int er = lane >> 2, ec = (lane & 3) * 2;
    #pragma unroll
    for (int mt = 0; mt < 2; mt++) {
        #pragma unroll
        for (int n = 0; n < 4; n++) {
            int col = n0 + wn * 32 + n * 8 + ec;
            float b0 = __ldg(bias + col), b1 = __ldg(bias + col + 1);
            #pragma unroll
            for (int h2 = 0; h2 < 2; h2++) {
                int row = row0 + wm * 32 + mt * 16 + er + 8 * h2;
                if (row < M) {
                    int orow = row;
                    if (remap) {
                        if (row < 20000)      orow = (row / 10000) * NQ + (row % 10000);
                        else if (row < 25000) { int rr = row - 20000; orow = (rr / 2500) * NQ + 10000 + rr % 2500; }
                        else                  { int rr = row - 25000; orow = (rr / 625)  * NQ + 12500 + rr % 625; }
                    }
                    float2 o = make_float2(acc[mt][n][2 * h2] + b0, acc[mt][n][2 * h2 + 1] + b1);
                    *(float2*)(C + (size_t)orow * N + col) = o;
                }
            }
        }
    }
}

// ---------------- fused softmax + deformable bilinear sampling (2-phase) ----------------
__global__ __launch_bounds__(256, 6)
void msda_sample(const float* __restrict__ rp)
{
    __shared__ uint4  s_off[96];   // [h*12 + j] corner byte offsets
    __shared__ float4 s_w  [96];   // [h*12 + j] folded bilinear*prob weights

    const int bq   = blockIdx.x;
    const int h    = threadIdx.x >> 5;
    const int lane = threadIdx.x & 31;
    const int pg   = lane >> 3;     // point group 0..3
    const int cq   = lane & 7;      // channel quad 0..7

    const uint32_t batOff = (bq >= NQ) ? (uint32_t)NQ * 1024u : 0u;

    // ---- phase 1: softmax + per-point params (lanes 0..11) ----
    float lv = -1e30f;
    if (lane < 12)
        lv = g_qout[(size_t)bq * 320 + 192 + h * 12 + lane];
    float m = lv;
    #pragma unroll
    for (int o = 8; o; o >>= 1) m = fmaxf(m, __shfl_xor_sync(0xffffffffu, m, o));
    float e = (lane < 12) ? __expf(lv - m) : 0.f;
    float s = e;
    #pragma unroll
    for (int o = 8; o; o >>= 1) s += __shfl_xor_sync(0xffffffffu, s, o);

    if (lane < 12) {
        const float a = e / s;
        const int l = lane >> 2, p = lane & 3;
        const int Wi = 100 >> l, Hi = 100 >> l;
        const uint32_t loff = (l > 0 ? 10000u : 0u) + (l > 1 ? 2500u : 0u);
        const float Wf = (float)Wi, Hf = (float)Hi;

        const float2 rxy = *(const float2*)(rp + (size_t)bq * 6 + l * 2);
        const float2 oxy = *(const float2*)(g_qout + (size_t)bq * 320 + h * 24 + l * 8 + p * 2);

        const float x = (rxy.x + oxy.x * (1.0f / Wf)) * Wf - 0.5f;
        const float y = (rxy.y + oxy.y * (1.0f / Hf)) * Hf - 0.5f;
        const float x0f = floorf(x), y0f = floorf(y);
        const float wx1 = x - x0f,  wy1 = y - y0f;
        const int ix0 = (int)x0f, iy0 = (int)y0f;
        const int ix1 = ix0 + 1,  iy1 = iy0 + 1;

        const float ax0 = (ix0 >= 0 && ix0 < Wi) ? (1.f - wx1) * a : 0.f;
        const float ax1 = (ix1 >= 0 && ix1 < Wi) ? wx1 * a : 0.f;
        const float my0 = (iy0 >= 0 && iy0 < Hi) ? (1.f - wy1) : 0.f;
        const float my1 = (iy1 >= 0 && iy1 < Hi) ? wy1 : 0.f;

        const int ix0c = min(max(ix0, 0), Wi - 1), ix1c = min(max(ix1, 0), Wi - 1);
        const int iy0c = min(max(iy0, 0), Hi - 1), iy1c = min(max(iy1, 0), Hi - 1);

        const uint32_t base = batOff + loff * 1024u;
        const uint32_t r0 = base + (uint32_t)(iy0c * Wi) * 1024u;
        const uint32_t r1 = base + (uint32_t)(iy1c * Wi) * 1024u;
        const uint32_t cx0 = (uint32_t)ix0c * 1024u, cx1 = (uint32_t)ix1c * 1024u;

        s_off[h * 12 + lane] = make_uint4(r0 + cx0, r0 + cx1, r1 + cx0, r1 + cx1);
        s_w  [h * 12 + lane] = make_float4(ax0 * my0, ax1 * my0, ax0 * my1, ax1 * my1);
    }
    __syncwarp();

    // ---- phase 2: gather + FMA ----
    const char* vb = (const char*)g_vproj;
    const uint32_t laneOff = (uint32_t)((h * HD + cq * 4) * 4);
    float4 acc = make_float4(0.f, 0.f, 0.f, 0.f);

    #pragma unroll
    for (int l = 0; l < LVL; l++) {
        const int idx = h * 12 + l * 4 + pg;
        const uint4  o4 = s_off[idx];
        const float4 w4 = s_w[idx];

        const float4 v00 = *(const float4*)(vb + (o4.x + laneOff));
        const float4 v01 = *(const float4*)(vb + (o4.y + laneOff));
        const float4 v10 = *(const float4*)(vb + (o4.z + laneOff));
        const float4 v11 = *(const float4*)(vb + (o4.w + laneOff));

        acc.x = fmaf(w4.x, v00.x, acc.x); acc.y = fmaf(w4.x, v00.y, acc.y);
        acc.z = fmaf(w4.x, v00.z, acc.z); acc.w = fmaf(w4.x, v00.w, acc.w);
        acc.x = fmaf(w4.y, v01.x, acc.x); acc.y = fmaf(w4.y, v01.y, acc.y);
        acc.z = fmaf(w4.y, v01.z, acc.z); acc.w = fmaf(w4.y, v01.w, acc.w);
        acc.x = fmaf(w4.z, v10.x, acc.x); acc.y = fmaf(w4.z, v10.y, acc.y);
        acc.z = fmaf(w4.z, v10.z, acc.z); acc.w = fmaf(w4.z, v10.w, acc.w);
        acc.x = fmaf(w4.w, v11.x, acc.x); acc.y = fmaf(w4.w, v11.y, acc.y);
        acc.z = fmaf(w4.w, v11.z, acc.z); acc.w = fmaf(w4.w, v11.w, acc.w);
    }

    // reduce across the 4 point groups (lanes differing in bits 3,4)
    #pragma unroll
    for (int o = 8; o <= 16; o <<= 1) {
        acc.x += __shfl_xor_sync(0xffffffffu, acc.x, o);
        acc.y += __shfl_xor_sync(0xffffffffu, acc.y, o);
        acc.z += __shfl_xor_sync(0xffffffffu, acc.z, o);
        acc.w += __shfl_xor_sync(0xffffffffu, acc.w, o);
    }

    if (pg == 0)
        *(float4*)(g_mid + (size_t)bq * DMODEL + h * HD + cq * 4) = acc;
}

// ---------------- launch ----------------
extern "C" void kernel_launch(void* const* d_in, const int* in_sizes, int n_in,
                              void* d_out, int out_size)
{
    const float* query  = (const float*)d_in[0];
    const float* rp     = (const float*)d_in[1];
    const float* v0     = (const float*)d_in[2];
    const float* v1     = (const float*)d_in[3];
    const float* v2     = (const float*)d_in[4];
    const float* W_val  = (const float*)d_in[5];
    const float* b_val  = (const float*)d_in[6];
    const float* W_off  = (const float*)d_in[7];
    const float* b_off  = (const float*)d_in[8];
    const float* W_attn = (const float*)d_in[9];
    const float* b_attn = (const float*)d_in[10];
    const float* W_out  = (const float*)d_in[11];
    const float* b_out  = (const float*)d_in[12];
    float* out = (float*)d_out;

    cudaFuncSetAttribute(gemm_bf16, cudaFuncAttributeMaxDynamicSharedMemorySize, GEMM_DYNSMEM);

    // 1: all weight prep (4 transposes + pad + bias) in one launch
    prep_weights<<<233, dim3(32, 8)>>>(W_val, W_off, W_attn, W_out, b_off, b_attn);
    // 2: fused vproj (y=0..3) + qout (y=4..8) GEMM; double-buffered pipeline
    gemm_bf16<<<dim3(206, 9), 256, GEMM_DYNSMEM>>>(1, query, v0, v1, v2, 0, b_val,
                                                   nullptr, MQ, 0, 0);
    // 3: fused softmax + deformable sampling -> g_mid (fp32)
    msda_sample<<<MQ, 256>>>(rp);
    // 4: output projection (A = g_mid, resolved in device code)
    gemm_bf16<<<dim3(206, 4), 256, GEMM_DYNSMEM>>>(0, nullptr, nullptr, nullptr, nullptr, 576, b_out,
                                                   out, MQ, 256, 0);
}

// round 14
// speedup vs baseline: 2.7234x; 1.0647x over previous
#include <cuda_runtime.h>
#include <cuda_bf16.h>
#include <math.h>
#include <stdint.h>

// ---------------- problem constants ----------------
#define NQ      13125
#define BATCH   2
#define MQ      (BATCH * NQ)     // 26250
#define DMODEL  256
#define HEADS   8
#define HD      32
#define LVL     3
#define PTS     4

// ---------------- scratch (static device memory; no allocation) ----------------
__device__ float g_vproj[(size_t)MQ * 256];   // projected values (fp32, for sampler)
__device__ float g_qout [(size_t)MQ * 320];   // [0..191]=offsets, [192..287]=logits, pad
__device__ float g_mid  [(size_t)MQ * 256];   // sampler output (fp32)
// transposed weights, bf16 hi/lo, [row][k]; rows: 0..255 W_val^T, 256..575 [W_off;W_attn;pad]^T, 576..831 W_out^T
__device__ __nv_bfloat16 g_bthi[832 * 256], g_btlo[832 * 256];
__device__ float g_biasq[320];

// ---------------- small helpers ----------------
__device__ __forceinline__ uint32_t smem_to_u32(const void* p) {
    uint32_t a;
    asm("{ .reg .u64 t; cvta.to.shared.u64 t, %1; cvt.u32.u64 %0, t; }" : "=r"(a) : "l"(p));
    return a;
}
__device__ __forceinline__ void ldm4(uint32_t* f, uint32_t addr) {
    asm volatile("ldmatrix.sync.aligned.m8n8.x4.shared.b16 {%0,%1,%2,%3}, [%4];"
                 : "=r"(f[0]), "=r"(f[1]), "=r"(f[2]), "=r"(f[3]) : "r"(addr));
}
__device__ __forceinline__ void mma16816(float* d, const uint32_t* a, const uint32_t* b) {
    asm volatile("mma.sync.aligned.m16n8k16.row.col.f32.bf16.bf16.f32 "
                 "{%0,%1,%2,%3}, {%4,%5,%6,%7}, {%8,%9}, {%0,%1,%2,%3};"
                 : "+f"(d[0]), "+f"(d[1]), "+f"(d[2]), "+f"(d[3])
                 : "r"(a[0]), "r"(a[1]), "r"(a[2]), "r"(a[3]), "r"(b[0]), "r"(b[1]));
}
__device__ __forceinline__ void cpa16(uint32_t dst, const void* src, int bytes) {
    asm volatile("cp.async.cg.shared.global [%0], [%1], 16, %2;"
                 :: "r"(dst), "l"(src), "r"(bytes) : "memory");
}
__device__ __forceinline__ void split2(float x, float y, __nv_bfloat162& hi, __nv_bfloat162& lo) {
    hi = __floats2bfloat162_rn(x, y);
    float rx = x - __bfloat162float(hi.x);
    float ry = y - __bfloat162float(hi.y);
    lo = __floats2bfloat162_rn(rx, ry);
}
__device__ __forceinline__ uint32_t b2u(__nv_bfloat162 v) { return *(uint32_t*)&v; }

// ---------------- prep: all weight transposes + pad + combined bias, one launch ----------------
__global__ void prep_weights(const float* __restrict__ W_val, const float* __restrict__ W_off,
                             const float* __restrict__ W_attn, const float* __restrict__ W_out,
                             const float* __restrict__ b_off, const float* __restrict__ b_attn) {
    const int id = blockIdx.x;
    if (id >= 200) {   // fixup: zero pad rows 544..575 + combined bias (flat thread index)
        const int t = threadIdx.y * 32 + threadIdx.x;
        const int i = (id - 200) * 256 + t;
        if (i < 32 * 256) {
            g_bthi[(size_t)544 * 256 + i] = __float2bfloat16_rn(0.f);
            g_btlo[(size_t)544 * 256 + i] = __float2bfloat16_rn(0.f);
        }
        if (i < 320)
            g_biasq[i] = (i < 192) ? b_off[i] : (i < 288 ? b_attn[i - 192] : 0.f);
        return;
    }
    const float* W; int btrow, N, tix;
    if (id < 64)       { W = W_val;  btrow = 0;   N = 256; tix = id;      }
    else if (id < 112) { W = W_off;  btrow = 256; N = 192; tix = id - 64; }
    else if (id < 136) { W = W_attn; btrow = 448; N = 96;  tix = id - 112;}
    else               { W = W_out;  btrow = 576; N = 256; tix = id - 136;}
    const int ntiles = N / 32;
    const int n0 = (tix % ntiles) * 32, k0 = (tix / ntiles) * 32;

    __shared__ float t[32][33];
    #pragma unroll
    for (int j = 0; j < 4; j++) {
        int k = k0 + threadIdx.y + 8 * j;
        int n = n0 + threadIdx.x;
        t[threadIdx.y + 8 * j][threadIdx.x] = W[(size_t)k * N + n];
    }
    __syncthreads();
    #pragma unroll
    for (int j = 0; j < 4; j++) {
        int n = n0 + threadIdx.y + 8 * j;
        int k = k0 + threadIdx.x;
        float x = t[threadIdx.x][threadIdx.y + 8 * j];
        __nv_bfloat16 hi = __float2bfloat16_rn(x);
        g_bthi[(size_t)(btrow + n) * 256 + k] = hi;
        g_btlo[(size_t)(btrow + n) * 256 + k] = __float2bfloat16_rn(x - __bfloat162float(hi));
    }
}

// ---------------- split-bf16 tensor-core GEMM, A direct-to-register ----------------
// C[M,N] = Ah@Bh + Al@Bh + Ah@Bl + bias.
// A: fp32 in gmem, loaded per-lane in mma fragment layout (LDG.64), split in regs.
// B: pre-split bf16, cp.async double-buffered smem + ldmatrix.
// BM=128, BN=64, BK=32; 8 warps 4(M)x2(N). One __syncthreads per K-tile.
#define ASTR 40
#define B_HALVES (64 * ASTR)                       // 2560 halves per (hi|lo) stage part

__global__ __launch_bounds__(256, 2)
void gemm_bf16(int fusedvq,
               const float* __restrict__ Aq, const float* __restrict__ Av0,
               const float* __restrict__ Av1, const float* __restrict__ Av2,
               int btoff_p, const float* __restrict__ biasp,
               float* __restrict__ Cout, int M, int N_p, int remap_p)
{
    __shared__ __align__(16) __nv_bfloat16 sB[2][2 * B_HALVES];  // [stage][hi|lo]

    int asel, btoff = btoff_p, N = N_p, remap = remap_p, n0;
    const float* bias = biasp;
    float* C;
    if (fusedvq) {
        if (blockIdx.y < 4) { asel = 1; btoff = 0;   N = 256; remap = 1; n0 = blockIdx.y * 64;      C = g_vproj; }
        else                { asel = 0; btoff = 256; N = 320; remap = 0; n0 = (blockIdx.y - 4) * 64; C = g_qout; bias = g_biasq; }
    } else {
        asel = 2; n0 = blockIdx.y * 64; C = Cout;
    }

    const __nv_bfloat16* Bhi = g_bthi + (size_t)btoff * 256;
    const __nv_bfloat16* Blo = g_btlo + (size_t)btoff * 256;

    const int tid = threadIdx.x, lane = tid & 31, wid = tid >> 5;
    const int wm = wid >> 1, wn = wid & 1;
    const int row0 = blockIdx.x * 128;
    const int groupID = lane >> 2, tig = lane & 3;

    // ---- per-lane A row pointers in mma fragment layout (4 rows: mt x {g, g+8}) ----
    const float* aptr[2][2];
    #pragma unroll
    for (int mt = 0; mt < 2; mt++) {
        #pragma unroll
        for (int j = 0; j < 2; j++) {
            int r = row0 + wm * 32 + mt * 16 + groupID + j * 8;
            int rr = (r < M) ? r : 0;   // clamped rows produce garbage masked in epilogue
            const float* src;
            if (asel == 1) {
                if (rr < 20000)      src = Av0 + (size_t)rr * 256;
                else if (rr < 25000) src = Av1 + (size_t)(rr - 20000) * 256;
                else                 src = Av2 + (size_t)(rr - 25000) * 256;
            } else if (asel == 0) {
                src = Aq + (size_t)rr * 256;
            } else {
                src = g_mid + (size_t)rr * 256;   // device symbol resolved in device code
            }
            aptr[mt][j] = src + tig * 2;
        }
    }

    // ---- B loader mapping (unchanged, proven) ----
    const int lr = tid >> 2, lc = tid & 3;
    const uint32_t uB0 = smem_to_u32(sB[0]);
    auto issueB = [&](int kt, int s) {
        const size_t go = (size_t)(n0 + lr) * 256 + kt * 32 + lc * 8;
        const uint32_t so = (uint32_t)((lr * ASTR + lc * 8) * 2);
        const uint32_t st = uB0 + (uint32_t)(s * 2 * B_HALVES * 2);
        cpa16(st + so, Bhi + go, 16);
        cpa16(st + B_HALVES * 2 + so, Blo + go, 16);
        asm volatile("cp.async.commit_group;" ::: "memory");
    };

    // ---- A raw prefetch (one kk ahead): 8 float2 = frag rows x {k, k+8} ----
    float2 fA[2][4];
    auto ldA = [&](int ko) {
        #pragma unroll
        for (int mt = 0; mt < 2; mt++) {
            fA[mt][0] = *(const float2*)(aptr[mt][0] + ko);
            fA[mt][1] = *(const float2*)(aptr[mt][1] + ko);
            fA[mt][2] = *(const float2*)(aptr[mt][0] + ko + 8);
            fA[mt][3] = *(const float2*)(aptr[mt][1] + ko + 8);
        }
    };

    float acc[2][4][4] = {};

    issueB(0, 0);
    ldA(0);
    #pragma unroll 1
    for (int kt = 0; kt < 8; kt++) {
        const int s = kt & 1;
        asm volatile("cp.async.wait_group 0;" ::: "memory");
        __syncthreads();                      // B(kt) visible; stage s^1 reads done
        if (kt < 7) issueB(kt + 1, s ^ 1);

        const uint32_t uBh = uB0 + (uint32_t)(s * 2 * B_HALVES * 2);
        const uint32_t uBl = uBh + B_HALVES * 2;
        const int lrow = lane & 15, lkc = lane >> 4;

        #pragma unroll
        for (int kk = 0; kk < 2; kk++) {
            // convert current A raw floats -> bf16 hi/lo fragments (in regs)
            uint32_t ah[2][4], al[2][4];
            #pragma unroll
            for (int mt = 0; mt < 2; mt++) {
                #pragma unroll
                for (int j = 0; j < 4; j++) {
                    __nv_bfloat162 hi, lo;
                    split2(fA[mt][j].x, fA[mt][j].y, hi, lo);
                    ah[mt][j] = b2u(hi);
                    al[mt][j] = b2u(lo);
                }
            }
            // prefetch next A slice (hidden under the mma block below)
            if (!(kt == 7 && kk == 1))
                ldA(kk == 0 ? kt * 32 + 16 : (kt + 1) * 32);

            uint32_t fbh[2][4], fbl[2][4];
            #pragma unroll
            for (int ng = 0; ng < 2; ng++) {
                uint32_t off = (uint32_t)(((wn * 32 + ng * 16 + lrow) * ASTR + kk * 16 + lkc * 8) * 2);
                ldm4(fbh[ng], uBh + off);
                ldm4(fbl[ng], uBl + off);
            }
            #pragma unroll
            for (int mt = 0; mt < 2; mt++) {
                #pragma unroll
                for (int n = 0; n < 4; n++) {
                    uint32_t bh[2] = { fbh[n >> 1][n & 1], fbh[n >> 1][(n & 1) + 2] };
                    uint32_t bl[2] = { fbl[n >> 1][n & 1], fbl[n >> 1][(n & 1) + 2] };
                    mma16816(acc[mt][n], ah[mt], bh);
                    mma16816(acc[mt][n], al[mt], bh);
                    mma16816(acc[mt][n], ah[mt], bl);
                }
            }
        }
    }

    // epilogue
    const int er = lane >> 2, ec = (lane & 3) * 2;
    #pragma unroll
    for (int mt = 0; mt < 2; mt++) {
        #pragma unroll
        for (int n = 0; n < 4; n++) {
            int col = n0 + wn * 32 + n * 8 + ec;
            float b0 = __ldg(bias + col), b1 = __ldg(bias + col + 1);
            #pragma unroll
            for (int h2 = 0; h2 < 2; h2++) {
                int row = row0 + wm * 32 + mt * 16 + er + 8 * h2;
                if (row < M) {
                    int orow = row;
                    if (remap) {
                        if (row < 20000)      orow = (row / 10000) * NQ + (row % 10000);
                        else if (row < 25000) { int rr = row - 20000; orow = (rr / 2500) * NQ + 10000 + rr % 2500; }
                        else                  { int rr = row - 25000; orow = (rr / 625)  * NQ + 12500 + rr % 625; }
                    }
                    float2 o = make_float2(acc[mt][n][2 * h2] + b0, acc[mt][n][2 * h2 + 1] + b1);
                    *(float2*)(C + (size_t)orow * N + col) = o;
                }
            }
        }
    }
}

// ---------------- fused softmax + deformable bilinear sampling (2-phase) ----------------
__global__ __launch_bounds__(256, 6)
void msda_sample(const float* __restrict__ rp)
{
    __shared__ uint4  s_off[96];   // [h*12 + j] corner byte offsets
    __shared__ float4 s_w  [96];   // [h*12 + j] folded bilinear*prob weights

    const int bq   = blockIdx.x;
    const int h    = threadIdx.x >> 5;
    const int lane = threadIdx.x & 31;
    const int pg   = lane >> 3;     // point group 0..3
    const int cq   = lane & 7;      // channel quad 0..7

    const uint32_t batOff = (bq >= NQ) ? (uint32_t)NQ * 1024u : 0u;

    // ---- phase 1: softmax + per-point params (lanes 0..11) ----
    float lv = -1e30f;
    if (lane < 12)
        lv = g_qout[(size_t)bq * 320 + 192 + h * 12 + lane];
    float m = lv;
    #pragma unroll
    for (int o = 8; o; o >>= 1) m = fmaxf(m, __shfl_xor_sync(0xffffffffu, m, o));
    float e = (lane < 12) ? __expf(lv - m) : 0.f;
    float s = e;
    #pragma unroll
    for (int o = 8; o; o >>= 1) s += __shfl_xor_sync(0xffffffffu, s, o);

    if (lane < 12) {
        const float a = e / s;
        const int l = lane >> 2, p = lane & 3;
        const int Wi = 100 >> l, Hi = 100 >> l;
        const uint32_t loff = (l > 0 ? 10000u : 0u) + (l > 1 ? 2500u : 0u);
        const float Wf = (float)Wi, Hf = (float)Hi;

        const float2 rxy = *(const float2*)(rp + (size_t)bq * 6 + l * 2);
        const float2 oxy = *(const float2*)(g_qout + (size_t)bq * 320 + h * 24 + l * 8 + p * 2);

        const float x = (rxy.x + oxy.x * (1.0f / Wf)) * Wf - 0.5f;
        const float y = (rxy.y + oxy.y * (1.0f / Hf)) * Hf - 0.5f;
        const float x0f = floorf(x), y0f = floorf(y);
        const float wx1 = x - x0f,  wy1 = y - y0f;
        const int ix0 = (int)x0f, iy0 = (int)y0f;
        const int ix1 = ix0 + 1,  iy1 = iy0 + 1;

        const float ax0 = (ix0 >= 0 && ix0 < Wi) ? (1.f - wx1) * a : 0.f;
        const float ax1 = (ix1 >= 0 && ix1 < Wi) ? wx1 * a : 0.f;
        const float my0 = (iy0 >= 0 && iy0 < Hi) ? (1.f - wy1) : 0.f;
        const float my1 = (iy1 >= 0 && iy1 < Hi) ? wy1 : 0.f;

        const int ix0c = min(max(ix0, 0), Wi - 1), ix1c = min(max(ix1, 0), Wi - 1);
        const int iy0c = min(max(iy0, 0), Hi - 1), iy1c = min(max(iy1, 0), Hi - 1);

        const uint32_t base = batOff + loff * 1024u;
        const uint32_t r0 = base + (uint32_t)(iy0c * Wi) * 1024u;
        const uint32_t r1 = base + (uint32_t)(iy1c * Wi) * 1024u;
        const uint32_t cx0 = (uint32_t)ix0c * 1024u, cx1 = (uint32_t)ix1c * 1024u;

        s_off[h * 12 + lane] = make_uint4(r0 + cx0, r0 + cx1, r1 + cx0, r1 + cx1);
        s_w  [h * 12 + lane] = make_float4(ax0 * my0, ax1 * my0, ax0 * my1, ax1 * my1);
    }
    __syncwarp();

    // ---- phase 2: gather + FMA ----
    const char* vb = (const char*)g_vproj;
    const uint32_t laneOff = (uint32_t)((h * HD + cq * 4) * 4);
    float4 acc = make_float4(0.f, 0.f, 0.f, 0.f);

    #pragma unroll
    for (int l = 0; l < LVL; l++) {
        const int idx = h * 12 + l * 4 + pg;
        const uint4  o4 = s_off[idx];
        const float4 w4 = s_w[idx];

        const float4 v00 = *(const float4*)(vb + (o4.x + laneOff));
        const float4 v01 = *(const float4*)(vb + (o4.y + laneOff));
        const float4 v10 = *(const float4*)(vb + (o4.z + laneOff));
        const float4 v11 = *(const float4*)(vb + (o4.w + laneOff));

        acc.x = fmaf(w4.x, v00.x, acc.x); acc.y = fmaf(w4.x, v00.y, acc.y);
        acc.z = fmaf(w4.x, v00.z, acc.z); acc.w = fmaf(w4.x, v00.w, acc.w);
        acc.x = fmaf(w4.y, v01.x, acc.x); acc.y = fmaf(w4.y, v01.y, acc.y);
        acc.z = fmaf(w4.y, v01.z, acc.z); acc.w = fmaf(w4.y, v01.w, acc.w);
        acc.x = fmaf(w4.z, v10.x, acc.x); acc.y = fmaf(w4.z, v10.y, acc.y);
        acc.z = fmaf(w4.z, v10.z, acc.z); acc.w = fmaf(w4.z, v10.w, acc.w);
        acc.x = fmaf(w4.w, v11.x, acc.x); acc.y = fmaf(w4.w, v11.y, acc.y);
        acc.z = fmaf(w4.w, v11.z, acc.z); acc.w = fmaf(w4.w, v11.w, acc.w);
    }

    // reduce across the 4 point groups (lanes differing in bits 3,4)
    #pragma unroll
    for (int o = 8; o <= 16; o <<= 1) {
        acc.x += __shfl_xor_sync(0xffffffffu, acc.x, o);
        acc.y += __shfl_xor_sync(0xffffffffu, acc.y, o);
        acc.z += __shfl_xor_sync(0xffffffffu, acc.z, o);
        acc.w += __shfl_xor_sync(0xffffffffu, acc.w, o);
    }

    if (pg == 0)
        *(float4*)(g_mid + (size_t)bq * DMODEL + h * HD + cq * 4) = acc;
}

// ---------------- launch ----------------
extern "C" void kernel_launch(void* const* d_in, const int* in_sizes, int n_in,
                              void* d_out, int out_size)
{
    const float* query  = (const float*)d_in[0];
    const float* rp     = (const float*)d_in[1];
    const float* v0     = (const float*)d_in[2];
    const float* v1     = (const float*)d_in[3];
    const float* v2     = (const float*)d_in[4];
    const float* W_val  = (const float*)d_in[5];
    const float* b_val  = (const float*)d_in[6];
    const float* W_off  = (const float*)d_in[7];
    const float* b_off  = (const float*)d_in[8];
    const float* W_attn = (const float*)d_in[9];
    const float* b_attn = (const float*)d_in[10];
    const float* W_out  = (const float*)d_in[11];
    const float* b_out  = (const float*)d_in[12];
    float* out = (float*)d_out;

    // 1: all weight prep (4 transposes + pad + bias) in one launch
    prep_weights<<<233, dim3(32, 8)>>>(W_val, W_off, W_attn, W_out, b_off, b_attn);
    // 2: fused vproj (y=0..3) + qout (y=4..8) GEMM; A direct-to-register
    gemm_bf16<<<dim3(206, 9), 256>>>(1, query, v0, v1, v2, 0, b_val,
                                     nullptr, MQ, 0, 0);
    // 3: fused softmax + deformable sampling -> g_mid (fp32)
    msda_sample<<<MQ, 256>>>(rp);
    // 4: output projection (A = g_mid, resolved in device code)
    gemm_bf16<<<dim3(206, 4), 256>>>(0, nullptr, nullptr, nullptr, nullptr, 576, b_out,
                                     out, MQ, 256, 0);
}

// round 15
// speedup vs baseline: 2.7516x; 1.0104x over previous
#include <cuda_runtime.h>
#include <cuda_bf16.h>
#include <math.h>
#include <stdint.h>

// ---------------- problem constants ----------------
#define NQ      13125
#define BATCH   2
#define MQ      (BATCH * NQ)     // 26250
#define DMODEL  256
#define HEADS   8
#define HD      32
#define LVL     3
#define PTS     4

// ---------------- scratch (static device memory; no allocation) ----------------
__device__ float g_vproj[(size_t)MQ * 256];   // projected values (fp32, for sampler)
__device__ float g_qout [(size_t)MQ * 320];   // [0..191]=offsets, [192..287]=logits, pad
__device__ float g_mid  [(size_t)MQ * 256];   // sampler output (fp32)
// fragment-packed weights: 26 n-blocks x 8 kt x 4 q x 32 lanes, uint4 each (hi & lo)
// n-blocks: 0..7 = W_val^T, 8..17 = [W_off;W_attn;pad]^T (N=320), 18..25 = W_out^T
#define PB_ELEMS (26 * 8 * 4 * 32)   // 26624
__device__ uint4 g_pbhi[PB_ELEMS], g_pblo[PB_ELEMS];
__device__ float g_biasq[320];

// ---------------- small helpers ----------------
__device__ __forceinline__ void mma16816(float* d, const uint32_t* a, const uint32_t* b) {
    asm volatile("mma.sync.aligned.m16n8k16.row.col.f32.bf16.bf16.f32 "
                 "{%0,%1,%2,%3}, {%4,%5,%6,%7}, {%8,%9}, {%0,%1,%2,%3};"
                 : "+f"(d[0]), "+f"(d[1]), "+f"(d[2]), "+f"(d[3])
                 : "r"(a[0]), "r"(a[1]), "r"(a[2]), "r"(a[3]), "r"(b[0]), "r"(b[1]));
}
__device__ __forceinline__ void split2(float x, float y, __nv_bfloat162& hi, __nv_bfloat162& lo) {
    hi = __floats2bfloat162_rn(x, y);
    float rx = x - __bfloat162float(hi.x);
    float ry = y - __bfloat162float(hi.y);
    lo = __floats2bfloat162_rn(rx, ry);
}
__device__ __forceinline__ uint32_t b2u(__nv_bfloat162 v) { return *(uint32_t*)&v; }

// ---------------- prep: pack all weights into per-lane mma fragment order ----------------
// Output record for (gnb, kt): 4 q-slots x 32 lanes x uint4.
// q = kk*2 + j; lane l = g*4+t. uint4 = { b(n=2j,k0), b(2j,k0+8), b(2j+1,k0), b(2j+1,k0+8) }
// where b(n,k) = bf16x2 of W[k..k+1][Nb+n*8+g], k0 = kt*32+kk*16+t*2, Nb = gnb*32.
__global__ void prep_pack(const float* __restrict__ W_val, const float* __restrict__ W_off,
                          const float* __restrict__ W_attn, const float* __restrict__ W_out,
                          const float* __restrict__ b_off, const float* __restrict__ b_attn) {
    const int id = blockIdx.x * 256 + threadIdx.x;
    if (id >= PB_ELEMS) {              // tail block: combined bias for qout
        const int i = id - PB_ELEMS;
        if (i < 320)
            g_biasq[i] = (i < 192) ? b_off[i] : (i < 288 ? b_attn[i - 192] : 0.f);
        return;
    }
    const int l   = id & 31;
    const int q   = (id >> 5) & 3;
    const int kt  = (id >> 7) & 7;
    const int gnb = id >> 10;
    const int g = l >> 2, t = l & 3;
    const int j = q & 1, kk = q >> 1;
    const int ka = kt * 32 + kk * 16 + t * 2;
    const int Nb = gnb * 32;
    const int nx = Nb + (2 * j) * 8 + g;
    const int nz = Nb + (2 * j + 1) * 8 + g;

    auto getW = [&](int k, int r) -> float {
        if (r < 256) return W_val[(size_t)k * 256 + r];
        r -= 256;
        if (r < 192) return W_off[(size_t)k * 192 + r];
        if (r < 288) return W_attn[(size_t)k * 96 + (r - 192)];
        if (r < 320) return 0.f;
        return W_out[(size_t)k * 256 + (r - 320)];
    };

    uint4 hi4, lo4;
    __nv_bfloat162 h, lo;
    split2(getW(ka,     nx), getW(ka + 1, nx), h, lo); hi4.x = b2u(h); lo4.x = b2u(lo);
    split2(getW(ka + 8, nx), getW(ka + 9, nx), h, lo); hi4.y = b2u(h); lo4.y = b2u(lo);
    split2(getW(ka,     nz), getW(ka + 1, nz), h, lo); hi4.z = b2u(h); lo4.z = b2u(lo);
    split2(getW(ka + 8, nz), getW(ka + 9, nz), h, lo); hi4.w = b2u(h); lo4.w = b2u(lo);
    g_pbhi[id] = hi4;
    g_pblo[id] = lo4;
}

// ---------------- split-bf16 tensor-core GEMM: smem-free, barrier-free ----------------
// C[M,N] = Ah@Bh + Al@Bh + Ah@Bl + bias.
// A: fp32 in gmem, per-lane fragment LDG.64, split in regs (round-14 path).
// B: fragment-packed bf16 hi/lo, per-lane coalesced LDG.128 (4 hi + 4 lo per kt).
// BM=128, BN=64, BK=32; 8 warps 4(M)x2(N). No shared memory, no __syncthreads.
__global__ __launch_bounds__(256, 2)
void gemm_bf16(int fusedvq,
               const float* __restrict__ Aq, const float* __restrict__ Av0,
               const float* __restrict__ Av1, const float* __restrict__ Av2,
               const float* __restrict__ biasp,
               float* __restrict__ Cout, int M, int N_p, int remap_p)
{
    int asel, N = N_p, remap = remap_p, n0, gnb;
    const float* bias = biasp;
    float* C;
    if (fusedvq) {
        if (blockIdx.y < 4) { asel = 1; N = 256; remap = 1; n0 = blockIdx.y * 64;       gnb = blockIdx.y * 2;           C = g_vproj; }
        else                { asel = 0; N = 320; remap = 0; n0 = (blockIdx.y - 4) * 64; gnb = 8 + (blockIdx.y - 4) * 2; C = g_qout; bias = g_biasq; }
    } else {
        asel = 2; n0 = blockIdx.y * 64; gnb = 18 + blockIdx.y * 2; C = Cout;
    }

    const int tid = threadIdx.x, lane = tid & 31, wid = tid >> 5;
    const int wm = wid >> 1, wn = wid & 1;
    const int row0 = blockIdx.x * 128;
    const int groupID = lane >> 2, tig = lane & 3;
    gnb += wn;

    // ---- per-lane A row pointers in mma fragment layout ----
    const float* aptr[2][2];
    #pragma unroll
    for (int mt = 0; mt < 2; mt++) {
        #pragma unroll
        for (int j = 0; j < 2; j++) {
            int r = row0 + wm * 32 + mt * 16 + groupID + j * 8;
            int rr = (r < M) ? r : 0;
            const float* src;
            if (asel == 1) {
                if (rr < 20000)      src = Av0 + (size_t)rr * 256;
                else if (rr < 25000) src = Av1 + (size_t)(rr - 20000) * 256;
                else                 src = Av2 + (size_t)(rr - 25000) * 256;
            } else if (asel == 0) {
                src = Aq + (size_t)rr * 256;
            } else {
                src = g_mid + (size_t)rr * 256;
            }
            aptr[mt][j] = src + tig * 2;
        }
    }

    // ---- packed-B base (per warp, per kt: 128 uint4) ----
    const uint4* pbh = g_pbhi + (size_t)gnb * (8 * 128) + lane;
    const uint4* pbl = g_pblo + (size_t)gnb * (8 * 128) + lane;

    // ---- A raw prefetch ----
    float2 fA[2][4];
    auto ldA = [&](int ko) {
        #pragma unroll
        for (int mt = 0; mt < 2; mt++) {
            fA[mt][0] = *(const float2*)(aptr[mt][0] + ko);
            fA[mt][1] = *(const float2*)(aptr[mt][1] + ko);
            fA[mt][2] = *(const float2*)(aptr[mt][0] + ko + 8);
            fA[mt][3] = *(const float2*)(aptr[mt][1] + ko + 8);
        }
    };

    float acc[2][4][4] = {};

    ldA(0);
    #pragma unroll 1
    for (int kt = 0; kt < 8; kt++) {
        // issue all B loads for this K-tile up front (MLP=8, coalesced 512B each)
        uint4 BH[4], BL[4];
        #pragma unroll
        for (int q = 0; q < 4; q++) BH[q] = __ldg(pbh + kt * 128 + q * 32);
        #pragma unroll
        for (int q = 0; q < 4; q++) BL[q] = __ldg(pbl + kt * 128 + q * 32);

        #pragma unroll
        for (int kk = 0; kk < 2; kk++) {
            // convert current A raw floats -> bf16 hi/lo fragments (in regs)
            uint32_t ah[2][4], al[2][4];
            #pragma unroll
            for (int mt = 0; mt < 2; mt++) {
                #pragma unroll
                for (int j = 0; j < 4; j++) {
                    __nv_bfloat162 hi, lo;
                    split2(fA[mt][j].x, fA[mt][j].y, hi, lo);
                    ah[mt][j] = b2u(hi);
                    al[mt][j] = b2u(lo);
                }
            }
            // prefetch next A slice (hidden under the mma block below)
            if (!(kt == 7 && kk == 1))
                ldA(kk == 0 ? kt * 32 + 16 : (kt + 1) * 32);

            #pragma unroll
            for (int mt = 0; mt < 2; mt++) {
                #pragma unroll
                for (int n = 0; n < 4; n++) {
                    const uint4 Qh = BH[kk * 2 + (n >> 1)];
                    const uint4 Ql = BL[kk * 2 + (n >> 1)];
                    uint32_t bh[2], bl[2];
                    if (n & 1) { bh[0] = Qh.z; bh[1] = Qh.w; bl[0] = Ql.z; bl[1] = Ql.w; }
                    else       { bh[0] = Qh.x; bh[1] = Qh.y; bl[0] = Ql.x; bl[1] = Ql.y; }
                    mma16816(acc[mt][n], ah[mt], bh);
                    mma16816(acc[mt][n], al[mt], bh);
                    mma16816(acc[mt][n], ah[mt], bl);
                }
            }
        }
    }

    // epilogue
    const int er = lane >> 2, ec = (lane & 3) * 2;
    #pragma unroll
    for (int mt = 0; mt < 2; mt++) {
        #pragma unroll
        for (int n = 0; n < 4; n++) {
            int col = n0 + wn * 32 + n * 8 + ec;
            float b0 = __ldg(bias + col), b1 = __ldg(bias + col + 1);
            #pragma unroll
            for (int h2 = 0; h2 < 2; h2++) {
                int row = row0 + wm * 32 + mt * 16 + er + 8 * h2;
                if (row < M) {
                    int orow = row;
                    if (remap) {
                        if (row < 20000)      orow = (row / 10000) * NQ + (row % 10000);
                        else if (row < 25000) { int rr = row - 20000; orow = (rr / 2500) * NQ + 10000 + rr % 2500; }
                        else                  { int rr = row - 25000; orow = (rr / 625)  * NQ + 12500 + rr % 625; }
                    }
                    float2 o = make_float2(acc[mt][n][2 * h2] + b0, acc[mt][n][2 * h2 + 1] + b1);
                    *(float2*)(C + (size_t)orow * N + col) = o;
                }
            }
        }
    }
}

// ---------------- fused softmax + deformable bilinear sampling (2-phase) ----------------
__global__ __launch_bounds__(256, 6)
void msda_sample(const float* __restrict__ rp)
{
    __shared__ uint4  s_off[96];   // [h*12 + j] corner byte offsets
    __shared__ float4 s_w  [96];   // [h*12 + j] folded bilinear*prob weights

    const int bq   = blockIdx.x;
    const int h    = threadIdx.x >> 5;
    const int lane = threadIdx.x & 31;
    const int pg   = lane >> 3;     // point group 0..3
    const int cq   = lane & 7;      // channel quad 0..7

    const uint32_t batOff = (bq >= NQ) ? (uint32_t)NQ * 1024u : 0u;

    // ---- phase 1: softmax + per-point params (lanes 0..11) ----
    float lv = -1e30f;
    if (lane < 12)
        lv = g_qout[(size_t)bq * 320 + 192 + h * 12 + lane];
    float m = lv;
    #pragma unroll
    for (int o = 8; o; o >>= 1) m = fmaxf(m, __shfl_xor_sync(0xffffffffu, m, o));
    float e = (lane < 12) ? __expf(lv - m) : 0.f;
    float s = e;
    #pragma unroll
    for (int o = 8; o; o >>= 1) s += __shfl_xor_sync(0xffffffffu, s, o);

    if (lane < 12) {
        const float a = e / s;
        const int l = lane >> 2, p = lane & 3;
        const int Wi = 100 >> l, Hi = 100 >> l;
        const uint32_t loff = (l > 0 ? 10000u : 0u) + (l > 1 ? 2500u : 0u);
        const float Wf = (float)Wi, Hf = (float)Hi;

        const float2 rxy = *(const float2*)(rp + (size_t)bq * 6 + l * 2);
        const float2 oxy = *(const float2*)(g_qout + (size_t)bq * 320 + h * 24 + l * 8 + p * 2);

        const float x = (rxy.x + oxy.x * (1.0f / Wf)) * Wf - 0.5f;
        const float y = (rxy.y + oxy.y * (1.0f / Hf)) * Hf - 0.5f;
        const float x0f = floorf(x), y0f = floorf(y);
        const float wx1 = x - x0f,  wy1 = y - y0f;
        const int ix0 = (int)x0f, iy0 = (int)y0f;
        const int ix1 = ix0 + 1,  iy1 = iy0 + 1;

        const float ax0 = (ix0 >= 0 && ix0 < Wi) ? (1.f - wx1) * a : 0.f;
        const float ax1 = (ix1 >= 0 && ix1 < Wi) ? wx1 * a : 0.f;
        const float my0 = (iy0 >= 0 && iy0 < Hi) ? (1.f - wy1) : 0.f;
        const float my1 = (iy1 >= 0 && iy1 < Hi) ? wy1 : 0.f;

        const int ix0c = min(max(ix0, 0), Wi - 1), ix1c = min(max(ix1, 0), Wi - 1);
        const int iy0c = min(max(iy0, 0), Hi - 1), iy1c = min(max(iy1, 0), Hi - 1);

        const uint32_t base = batOff + loff * 1024u;
        const uint32_t r0 = base + (uint32_t)(iy0c * Wi) * 1024u;
        const uint32_t r1 = base + (uint32_t)(iy1c * Wi) * 1024u;
        const uint32_t cx0 = (uint32_t)ix0c * 1024u, cx1 = (uint32_t)ix1c * 1024u;

        s_off[h * 12 + lane] = make_uint4(r0 + cx0, r0 + cx1, r1 + cx0, r1 + cx1);
        s_w  [h * 12 + lane] = make_float4(ax0 * my0, ax1 * my0, ax0 * my1, ax1 * my1);
    }
    __syncwarp();

    // ---- phase 2: gather + FMA ----
    const char* vb = (const char*)g_vproj;
    const uint32_t laneOff = (uint32_t)((h * HD + cq * 4) * 4);
    float4 acc = make_float4(0.f, 0.f, 0.f, 0.f);

    #pragma unroll
    for (int l = 0; l < LVL; l++) {
        const int idx = h * 12 + l * 4 + pg;
        const uint4  o4 = s_off[idx];
        const float4 w4 = s_w[idx];

        const float4 v00 = *(const float4*)(vb + (o4.x + laneOff));
        const float4 v01 = *(const float4*)(vb + (o4.y + laneOff));
        const float4 v10 = *(const float4*)(vb + (o4.z + laneOff));
        const float4 v11 = *(const float4*)(vb + (o4.w + laneOff));

        acc.x = fmaf(w4.x, v00.x, acc.x); acc.y = fmaf(w4.x, v00.y, acc.y);
        acc.z = fmaf(w4.x, v00.z, acc.z); acc.w = fmaf(w4.x, v00.w, acc.w);
        acc.x = fmaf(w4.y, v01.x, acc.x); acc.y = fmaf(w4.y, v01.y, acc.y);
        acc.z = fmaf(w4.y, v01.z, acc.z); acc.w = fmaf(w4.y, v01.w, acc.w);
        acc.x = fmaf(w4.z, v10.x, acc.x); acc.y = fmaf(w4.z, v10.y, acc.y);
        acc.z = fmaf(w4.z, v10.z, acc.z); acc.w = fmaf(w4.z, v10.w, acc.w);
        acc.x = fmaf(w4.w, v11.x, acc.x); acc.y = fmaf(w4.w, v11.y, acc.y);
        acc.z = fmaf(w4.w, v11.z, acc.z); acc.w = fmaf(w4.w, v11.w, acc.w);
    }

    // reduce across the 4 point groups (lanes differing in bits 3,4)
    #pragma unroll
    for (int o = 8; o <= 16; o <<= 1) {
        acc.x += __shfl_xor_sync(0xffffffffu, acc.x, o);
        acc.y += __shfl_xor_sync(0xffffffffu, acc.y, o);
        acc.z += __shfl_xor_sync(0xffffffffu, acc.z, o);
        acc.w += __shfl_xor_sync(0xffffffffu, acc.w, o);
    }

    if (pg == 0)
        *(float4*)(g_mid + (size_t)bq * DMODEL + h * HD + cq * 4) = acc;
}

// ---------------- launch ----------------
extern "C" void kernel_launch(void* const* d_in, const int* in_sizes, int n_in,
                              void* d_out, int out_size)
{
    const float* query  = (const float*)d_in[0];
    const float* rp     = (const float*)d_in[1];
    const float* v0     = (const float*)d_in[2];
    const float* v1     = (const float*)d_in[3];
    const float* v2     = (const float*)d_in[4];
    const float* W_val  = (const float*)d_in[5];
    const float* b_val  = (const float*)d_in[6];
    const float* W_off  = (const float*)d_in[7];
    const float* b_off  = (const float*)d_in[8];
    const float* W_attn = (const float*)d_in[9];
    const float* b_attn = (const float*)d_in[10];
    const float* W_out  = (const float*)d_in[11];
    const float* b_out  = (const float*)d_in[12];
    float* out = (float*)d_out;

    // 1: pack all weights into per-lane fragment order + combined bias
    prep_pack<<<(PB_ELEMS + 320 + 255) / 256, 256>>>(W_val, W_off, W_attn, W_out, b_off, b_attn);
    // 2: fused vproj (y=0..3) + qout (y=4..8) GEMM; smem-free, barrier-free
    gemm_bf16<<<dim3(206, 9), 256>>>(1, query, v0, v1, v2, b_val, nullptr, MQ, 0, 0);
    // 3: fused softmax + deformable sampling -> g_mid (fp32)
    msda_sample<<<MQ, 256>>>(rp);
    // 4: output projection (A = g_mid, resolved in device code)
    gemm_bf16<<<dim3(206, 4), 256>>>(0, nullptr, nullptr, nullptr, nullptr, b_out, out, MQ, 256, 0);
}

// round 16
// speedup vs baseline: 2.8289x; 1.0281x over previous
#include <cuda_runtime.h>
#include <cuda_bf16.h>
#include <math.h>
#include <stdint.h>

// ---------------- problem constants ----------------
#define NQ      13125
#define BATCH   2
#define MQ      (BATCH * NQ)     // 26250
#define DMODEL  256
#define HEADS   8
#define HD      32
#define LVL     3
#define PTS     4

// ---------------- scratch (static device memory; no allocation) ----------------
__device__ float g_vproj[(size_t)MQ * 256];   // projected values (fp32, for sampler)
__device__ float g_qout [(size_t)MQ * 320];   // [0..191]=offsets, [192..287]=logits, pad
__device__ float g_mid  [(size_t)MQ * 256];   // sampler output (fp32)
// fragment-packed weights: 26 n-blocks x 8 kt x 4 q x 32 lanes, uint4 each (hi & lo)
// n-blocks: 0..7 = W_val^T, 8..17 = [W_off;W_attn;pad]^T (N=320), 18..25 = W_out^T
#define PB_ELEMS (26 * 8 * 4 * 32)   // 26624
__device__ uint4 g_pbhi[PB_ELEMS], g_pblo[PB_ELEMS];
__device__ float g_biasq[320];

// ---------------- small helpers ----------------
__device__ __forceinline__ void mma16816(float* d, const uint32_t* a, const uint32_t* b) {
    asm volatile("mma.sync.aligned.m16n8k16.row.col.f32.bf16.bf16.f32 "
                 "{%0,%1,%2,%3}, {%4,%5,%6,%7}, {%8,%9}, {%0,%1,%2,%3};"
                 : "+f"(d[0]), "+f"(d[1]), "+f"(d[2]), "+f"(d[3])
                 : "r"(a[0]), "r"(a[1]), "r"(a[2]), "r"(a[3]), "r"(b[0]), "r"(b[1]));
}
__device__ __forceinline__ void split2(float x, float y, __nv_bfloat162& hi, __nv_bfloat162& lo) {
    hi = __floats2bfloat162_rn(x, y);
    float rx = x - __bfloat162float(hi.x);
    float ry = y - __bfloat162float(hi.y);
    lo = __floats2bfloat162_rn(rx, ry);
}
__device__ __forceinline__ uint32_t b2u(__nv_bfloat162 v) { return *(uint32_t*)&v; }

// ---------------- prep: pack all weights into per-lane mma fragment order ----------------
__global__ void prep_pack(const float* __restrict__ W_val, const float* __restrict__ W_off,
                          const float* __restrict__ W_attn, const float* __restrict__ W_out,
                          const float* __restrict__ b_off, const float* __restrict__ b_attn) {
    const int id = blockIdx.x * 256 + threadIdx.x;
    if (id >= PB_ELEMS) {              // tail block: combined bias for qout
        const int i = id - PB_ELEMS;
        if (i < 320)
            g_biasq[i] = (i < 192) ? b_off[i] : (i < 288 ? b_attn[i - 192] : 0.f);
        return;
    }
    const int l   = id & 31;
    const int q   = (id >> 5) & 3;
    const int kt  = (id >> 7) & 7;
    const int gnb = id >> 10;
    const int g = l >> 2, t = l & 3;
    const int j = q & 1, kk = q >> 1;
    const int ka = kt * 32 + kk * 16 + t * 2;
    const int Nb = gnb * 32;
    const int nx = Nb + (2 * j) * 8 + g;
    const int nz = Nb + (2 * j + 1) * 8 + g;

    auto getW = [&](int k, int r) -> float {
        if (r < 256) return W_val[(size_t)k * 256 + r];
        r -= 256;
        if (r < 192) return W_off[(size_t)k * 192 + r];
        if (r < 288) return W_attn[(size_t)k * 96 + (r - 192)];
        if (r < 320) return 0.f;
        return W_out[(size_t)k * 256 + (r - 320)];
    };

    uint4 hi4, lo4;
    __nv_bfloat162 h, lo;
    split2(getW(ka,     nx), getW(ka + 1, nx), h, lo); hi4.x = b2u(h); lo4.x = b2u(lo);
    split2(getW(ka + 8, nx), getW(ka + 9, nx), h, lo); hi4.y = b2u(h); lo4.y = b2u(lo);
    split2(getW(ka,     nz), getW(ka + 1, nz), h, lo); hi4.z = b2u(h); lo4.z = b2u(lo);
    split2(getW(ka + 8, nz), getW(ka + 9, nz), h, lo); hi4.w = b2u(h); lo4.w = b2u(lo);
    g_pbhi[id] = hi4;
    g_pblo[id] = lo4;
}

// ---------------- split-bf16 tensor-core GEMM: smem-free, barrier-free ----------------
__global__ __launch_bounds__(256, 2)
void gemm_bf16(int fusedvq,
               const float* __restrict__ Aq, const float* __restrict__ Av0,
               const float* __restrict__ Av1, const float* __restrict__ Av2,
               const float* __restrict__ biasp,
               float* __restrict__ Cout, int M, int N_p, int remap_p)
{
    int asel, N = N_p, remap = remap_p, n0, gnb;
    const float* bias = biasp;
    float* C;
    if (fusedvq) {
        if (blockIdx.y < 4) { asel = 1; N = 256; remap = 1; n0 = blockIdx.y * 64;       gnb = blockIdx.y * 2;           C = g_vproj; }
        else                { asel = 0; N = 320; remap = 0; n0 = (blockIdx.y - 4) * 64; gnb = 8 + (blockIdx.y - 4) * 2; C = g_qout; bias = g_biasq; }
    } else {
        asel = 2; n0 = blockIdx.y * 64; gnb = 18 + blockIdx.y * 2; C = Cout;
    }

    const int tid = threadIdx.x, lane = tid & 31, wid = tid >> 5;
    const int wm = wid >> 1, wn = wid & 1;
    const int row0 = blockIdx.x * 128;
    const int groupID = lane >> 2, tig = lane & 3;
    gnb += wn;

    // ---- per-lane A row pointers in mma fragment layout ----
    const float* aptr[2][2];
    #pragma unroll
    for (int mt = 0; mt < 2; mt++) {
        #pragma unroll
        for (int j = 0; j < 2; j++) {
            int r = row0 + wm * 32 + mt * 16 + groupID + j * 8;
            int rr = (r < M) ? r : 0;
            const float* src;
            if (asel == 1) {
                if (rr < 20000)      src = Av0 + (size_t)rr * 256;
                else if (rr < 25000) src = Av1 + (size_t)(rr - 20000) * 256;
                else                 src = Av2 + (size_t)(rr - 25000) * 256;
            } else if (asel == 0) {
                src = Aq + (size_t)rr * 256;
            } else {
                src = g_mid + (size_t)rr * 256;
            }
            aptr[mt][j] = src + tig * 2;
        }
    }

    // ---- packed-B base (per warp, per kt: 128 uint4) ----
    const uint4* pbh = g_pbhi + (size_t)gnb * (8 * 128) + lane;
    const uint4* pbl = g_pblo + (size_t)gnb * (8 * 128) + lane;

    // ---- A raw prefetch ----
    float2 fA[2][4];
    auto ldA = [&](int ko) {
        #pragma unroll
        for (int mt = 0; mt < 2; mt++) {
            fA[mt][0] = *(const float2*)(aptr[mt][0] + ko);
            fA[mt][1] = *(const float2*)(aptr[mt][1] + ko);
            fA[mt][2] = *(const float2*)(aptr[mt][0] + ko + 8);
            fA[mt][3] = *(const float2*)(aptr[mt][1] + ko + 8);
        }
    };

    float acc[2][4][4] = {};

    ldA(0);
    #pragma unroll 1
    for (int kt = 0; kt < 8; kt++) {
        // issue all B loads for this K-tile up front (MLP=8, coalesced 512B each)
        uint4 BH[4], BL[4];
        #pragma unroll
        for (int q = 0; q < 4; q++) BH[q] = __ldg(pbh + kt * 128 + q * 32);
        #pragma unroll
        for (int q = 0; q < 4; q++) BL[q] = __ldg(pbl + kt * 128 + q * 32);

        #pragma unroll
        for (int kk = 0; kk < 2; kk++) {
            // convert current A raw floats -> bf16 hi/lo fragments (in regs)
            uint32_t ah[2][4], al[2][4];
            #pragma unroll
            for (int mt = 0; mt < 2; mt++) {
                #pragma unroll
                for (int j = 0; j < 4; j++) {
                    __nv_bfloat162 hi, lo;
                    split2(fA[mt][j].x, fA[mt][j].y, hi, lo);
                    ah[mt][j] = b2u(hi);
                    al[mt][j] = b2u(lo);
                }
            }
            // prefetch next A slice (hidden under the mma block below)
            if (!(kt == 7 && kk == 1))
                ldA(kk == 0 ? kt * 32 + 16 : (kt + 1) * 32);

            #pragma unroll
            for (int mt = 0; mt < 2; mt++) {
                #pragma unroll
                for (int n = 0; n < 4; n++) {
                    const uint4 Qh = BH[kk * 2 + (n >> 1)];
                    const uint4 Ql = BL[kk * 2 + (n >> 1)];
                    uint32_t bh[2], bl[2];
                    if (n & 1) { bh[0] = Qh.z; bh[1] = Qh.w; bl[0] = Ql.z; bl[1] = Ql.w; }
                    else       { bh[0] = Qh.x; bh[1] = Qh.y; bl[0] = Ql.x; bl[1] = Ql.y; }
                    mma16816(acc[mt][n], ah[mt], bh);
                    mma16816(acc[mt][n], al[mt], bh);
                    mma16816(acc[mt][n], ah[mt], bl);
                }
            }
        }
    }

    // epilogue
    const int er = lane >> 2, ec = (lane & 3) * 2;
    #pragma unroll
    for (int mt = 0; mt < 2; mt++) {
        #pragma unroll
        for (int n = 0; n < 4; n++) {
            int col = n0 + wn * 32 + n * 8 + ec;
            float b0 = __ldg(bias + col), b1 = __ldg(bias + col + 1);
            #pragma unroll
            for (int h2 = 0; h2 < 2; h2++) {
                int row = row0 + wm * 32 + mt * 16 + er + 8 * h2;
                if (row < M) {
                    int orow = row;
                    if (remap) {
                        if (row < 20000)      orow = (row / 10000) * NQ + (row % 10000);
                        else if (row < 25000) { int rr = row - 20000; orow = (rr / 2500) * NQ + 10000 + rr % 2500; }
                        else                  { int rr = row - 25000; orow = (rr / 625)  * NQ + 12500 + rr % 625; }
                    }
                    float2 o = make_float2(acc[mt][n][2 * h2] + b0, acc[mt][n][2 * h2 + 1] + b1);
                    *(float2*)(C + (size_t)orow * N + col) = o;
                }
            }
        }
    }
}

// ---------------- fused softmax + deformable bilinear sampling (2-phase) ----------------
// launch_bounds(256,7): cap regs ~36 so 7 CTAs/SM fit (was 6 at 40 regs).
// Any rematerialization lands in once-executed phase-1, not the gather loop.
__global__ __launch_bounds__(256, 7)
void msda_sample(const float* __restrict__ rp)
{
    __shared__ uint4  s_off[96];   // [h*12 + j] corner byte offsets
    __shared__ float4 s_w  [96];   // [h*12 + j] folded bilinear*prob weights

    const int bq   = blockIdx.x;
    const int h    = threadIdx.x >> 5;
    const int lane = threadIdx.x & 31;
    const int pg   = lane >> 3;     // point group 0..3
    const int cq   = lane & 7;      // channel quad 0..7

    const uint32_t batOff = (bq >= NQ) ? (uint32_t)NQ * 1024u : 0u;

    // ---- phase 1: softmax + per-point params (lanes 0..11) ----
    float lv = -1e30f;
    if (lane < 12)
        lv = g_qout[(size_t)bq * 320 + 192 + h * 12 + lane];
    float m = lv;
    #pragma unroll
    for (int o = 8; o; o >>= 1) m = fmaxf(m, __shfl_xor_sync(0xffffffffu, m, o));
    float e = (lane < 12) ? __expf(lv - m) : 0.f;
    float s = e;
    #pragma unroll
    for (int o = 8; o; o >>= 1) s += __shfl_xor_sync(0xffffffffu, s, o);

    if (lane < 12) {
        const float a = e / s;
        const int l = lane >> 2, p = lane & 3;
        const int Wi = 100 >> l, Hi = 100 >> l;
        const uint32_t loff = (l > 0 ? 10000u : 0u) + (l > 1 ? 2500u : 0u);
        const float Wf = (float)Wi, Hf = (float)Hi;

        const float2 rxy = *(const float2*)(rp + (size_t)bq * 6 + l * 2);
        const float2 oxy = *(const float2*)(g_qout + (size_t)bq * 320 + h * 24 + l * 8 + p * 2);

        const float x = (rxy.x + oxy.x * (1.0f / Wf)) * Wf - 0.5f;
        const float y = (rxy.y + oxy.y * (1.0f / Hf)) * Hf - 0.5f;
        const float x0f = floorf(x), y0f = floorf(y);
        const float wx1 = x - x0f,  wy1 = y - y0f;
        const int ix0 = (int)x0f, iy0 = (int)y0f;
        const int ix1 = ix0 + 1,  iy1 = iy0 + 1;

        const float ax0 = (ix0 >= 0 && ix0 < Wi) ? (1.f - wx1) * a : 0.f;
        const float ax1 = (ix1 >= 0 && ix1 < Wi) ? wx1 * a : 0.f;
        const float my0 = (iy0 >= 0 && iy0 < Hi) ? (1.f - wy1) : 0.f;
        const float my1 = (iy1 >= 0 && iy1 < Hi) ? wy1 : 0.f;

        const int ix0c = min(max(ix0, 0), Wi - 1), ix1c = min(max(ix1, 0), Wi - 1);
        const int iy0c = min(max(iy0, 0), Hi - 1), iy1c = min(max(iy1, 0), Hi - 1);

        const uint32_t base = batOff + loff * 1024u;
        const uint32_t r0 = base + (uint32_t)(iy0c * Wi) * 1024u;
        const uint32_t r1 = base + (uint32_t)(iy1c * Wi) * 1024u;
        const uint32_t cx0 = (uint32_t)ix0c * 1024u, cx1 = (uint32_t)ix1c * 1024u;

        s_off[h * 12 + lane] = make_uint4(r0 + cx0, r0 + cx1, r1 + cx0, r1 + cx1);
        s_w  [h * 12 + lane] = make_float4(ax0 * my0, ax1 * my0, ax0 * my1, ax1 * my1);
    }
    __syncwarp();

    // ---- phase 2: gather + FMA ----
    const char* vb = (const char*)g_vproj;
    const uint32_t laneOff = (uint32_t)((h * HD + cq * 4) * 4);
    float4 acc = make_float4(0.f, 0.f, 0.f, 0.f);

    #pragma unroll
    for (int l = 0; l < LVL; l++) {
        const int idx = h * 12 + l * 4 + pg;
        const uint4  o4 = s_off[idx];
        const float4 w4 = s_w[idx];

        const float4 v00 = *(const float4*)(vb + (o4.x + laneOff));
        const float4 v01 = *(const float4*)(vb + (o4.y + laneOff));
        const float4 v10 = *(const float4*)(vb + (o4.z + laneOff));
        const float4 v11 = *(const float4*)(vb + (o4.w + laneOff));

        acc.x = fmaf(w4.x, v00.x, acc.x); acc.y = fmaf(w4.x, v00.y, acc.y);
        acc.z = fmaf(w4.x, v00.z, acc.z); acc.w = fmaf(w4.x, v00.w, acc.w);
        acc.x = fmaf(w4.y, v01.x, acc.x); acc.y = fmaf(w4.y, v01.y, acc.y);
        acc.z = fmaf(w4.y, v01.z, acc.z); acc.w = fmaf(w4.y, v01.w, acc.w);
        acc.x = fmaf(w4.z, v10.x, acc.x); acc.y = fmaf(w4.z, v10.y, acc.y);
        acc.z = fmaf(w4.z, v10.z, acc.z); acc.w = fmaf(w4.z, v10.w, acc.w);
        acc.x = fmaf(w4.w, v11.x, acc.x); acc.y = fmaf(w4.w, v11.y, acc.y);
        acc.z = fmaf(w4.w, v11.z, acc.z); acc.w = fmaf(w4.w, v11.w, acc.w);
    }

    // reduce across the 4 point groups (lanes differing in bits 3,4)
    #pragma unroll
    for (int o = 8; o <= 16; o <<= 1) {
        acc.x += __shfl_xor_sync(0xffffffffu, acc.x, o);
        acc.y += __shfl_xor_sync(0xffffffffu, acc.y, o);
        acc.z += __shfl_xor_sync(0xffffffffu, acc.z, o);
        acc.w += __shfl_xor_sync(0xffffffffu, acc.w, o);
    }

    if (pg == 0)
        *(float4*)(g_mid + (size_t)bq * DMODEL + h * HD + cq * 4) = acc;
}

// ---------------- launch ----------------
extern "C" void kernel_launch(void* const* d_in, const int* in_sizes, int n_in,
                              void* d_out, int out_size)
{
    const float* query  = (const float*)d_in[0];
    const float* rp     = (const float*)d_in[1];
    const float* v0     = (const float*)d_in[2];
    const float* v1     = (const float*)d_in[3];
    const float* v2     = (const float*)d_in[4];
    const float* W_val  = (const float*)d_in[5];
    const float* b_val  = (const float*)d_in[6];
    const float* W_off  = (const float*)d_in[7];
    const float* b_off  = (const float*)d_in[8];
    const float* W_attn = (const float*)d_in[9];
    const float* b_attn = (const float*)d_in[10];
    const float* W_out  = (const float*)d_in[11];
    const float* b_out  = (const float*)d_in[12];
    float* out = (float*)d_out;

    // 1: pack all weights into per-lane fragment order + combined bias
    prep_pack<<<(PB_ELEMS + 320 + 255) / 256, 256>>>(W_val, W_off, W_attn, W_out, b_off, b_attn);
    // 2: fused vproj (y=0..3) + qout (y=4..8) GEMM; smem-free, barrier-free
    gemm_bf16<<<dim3(206, 9), 256>>>(1, query, v0, v1, v2, b_val, nullptr, MQ, 0, 0);
    // 3: fused softmax + deformable sampling -> g_mid (fp32)
    msda_sample<<<MQ, 256>>>(rp);
    // 4: output projection (A = g_mid, resolved in device code)
    gemm_bf16<<<dim3(206, 4), 256>>>(0, nullptr, nullptr, nullptr, nullptr, b_out, out, MQ, 256, 0);
}

// round 17
// speedup vs baseline: 3.1117x; 1.1000x over previous
#include <cuda_runtime.h>
#include <cuda_bf16.h>
#include <math.h>
#include <stdint.h>

// ---------------- problem constants ----------------
#define NQ      13125
#define BATCH   2
#define MQ      (BATCH * NQ)     // 26250
#define DMODEL  256
#define HEADS   8
#define HD      32
#define LVL     3
#define PTS     4
#define NRB     206              // ceil(MQ/128)

// ---------------- scratch (static device memory; no allocation) ----------------
__device__ float g_vproj[(size_t)MQ * 256];   // projected values (fp32, for sampler)
__device__ float g_qout [(size_t)MQ * 320];   // [0..191]=offsets, [192..287]=logits, pad
__device__ float g_mid  [(size_t)MQ * 256];   // sampler output (fp32)
// fragment-packed weights: 26 n-blocks x 8 kt x 4 q x 32 lanes, uint4 each (hi & lo)
#define PB_ELEMS (26 * 8 * 4 * 32)   // 26624
__device__ uint4 g_pbhi[PB_ELEMS], g_pblo[PB_ELEMS];
// fragment-packed activations: 3 matrices (0=query,1=values,2=g_mid)
// record: (rb, wm, kt, q, lane) -> uint4;  q = kk*2 + mt
#define PA_PER_MAT ((size_t)NRB * 4 * 8 * 4 * 32)   // 843776
__device__ uint4 g_pahi[3 * PA_PER_MAT], g_palo[3 * PA_PER_MAT];
__device__ float g_biasq[320];

// ---------------- small helpers ----------------
__device__ __forceinline__ void mma16816(float* d, const uint32_t* a, const uint32_t* b) {
    asm volatile("mma.sync.aligned.m16n8k16.row.col.f32.bf16.bf16.f32 "
                 "{%0,%1,%2,%3}, {%4,%5,%6,%7}, {%8,%9}, {%0,%1,%2,%3};"
                 : "+f"(d[0]), "+f"(d[1]), "+f"(d[2]), "+f"(d[3])
                 : "r"(a[0]), "r"(a[1]), "r"(a[2]), "r"(a[3]), "r"(b[0]), "r"(b[1]));
}
__device__ __forceinline__ void split2(float x, float y, __nv_bfloat162& hi, __nv_bfloat162& lo) {
    hi = __floats2bfloat162_rn(x, y);
    float rx = x - __bfloat162float(hi.x);
    float ry = y - __bfloat162float(hi.y);
    lo = __floats2bfloat162_rn(rx, ry);
}
__device__ __forceinline__ uint32_t b2u(__nv_bfloat162 v) { return *(uint32_t*)&v; }

// ---------------- prep: pack weights into per-lane mma fragment order ----------------
__global__ void prep_pack(const float* __restrict__ W_val, const float* __restrict__ W_off,
                          const float* __restrict__ W_attn, const float* __restrict__ W_out,
                          const float* __restrict__ b_off, const float* __restrict__ b_attn) {
    const int id = blockIdx.x * 256 + threadIdx.x;
    if (id >= PB_ELEMS) {
        const int i = id - PB_ELEMS;
        if (i < 320)
            g_biasq[i] = (i < 192) ? b_off[i] : (i < 288 ? b_attn[i - 192] : 0.f);
        return;
    }
    const int l   = id & 31;
    const int q   = (id >> 5) & 3;
    const int kt  = (id >> 7) & 7;
    const int gnb = id >> 10;
    const int g = l >> 2, t = l & 3;
    const int j = q & 1, kk = q >> 1;
    const int ka = kt * 32 + kk * 16 + t * 2;
    const int Nb = gnb * 32;
    const int nx = Nb + (2 * j) * 8 + g;
    const int nz = Nb + (2 * j + 1) * 8 + g;

    auto getW = [&](int k, int r) -> float {
        if (r < 256) return W_val[(size_t)k * 256 + r];
        r -= 256;
        if (r < 192) return W_off[(size_t)k * 192 + r];
        if (r < 288) return W_attn[(size_t)k * 96 + (r - 192)];
        if (r < 320) return 0.f;
        return W_out[(size_t)k * 256 + (r - 320)];
    };

    uint4 hi4, lo4;
    __nv_bfloat162 h, lo;
    split2(getW(ka,     nx), getW(ka + 1, nx), h, lo); hi4.x = b2u(h); lo4.x = b2u(lo);
    split2(getW(ka + 8, nx), getW(ka + 9, nx), h, lo); hi4.y = b2u(h); lo4.y = b2u(lo);
    split2(getW(ka,     nz), getW(ka + 1, nz), h, lo); hi4.z = b2u(h); lo4.z = b2u(lo);
    split2(getW(ka + 8, nz), getW(ka + 9, nz), h, lo); hi4.w = b2u(h); lo4.w = b2u(lo);
    g_pbhi[id] = hi4;
    g_pblo[id] = lo4;
}

// ---------------- prep: pack activations into per-lane mma fragment order ----------------
// grid: (NRB, 4 ktpairs, nmat); block 256. Each block: 128 rows x 64 k.
// Record uint4 = { (row g,k0), (row g+8,k0), (row g,k0+8), (row g+8,k0+8) } bf16x2,
// k0 = kt*32 + kk*16 + 2t;  q = kk*2 + mt  (matches GEMM consumption order).
__global__ void packA(const float* __restrict__ Aq, const float* __restrict__ Av0,
                      const float* __restrict__ Av1, const float* __restrict__ Av2,
                      int matbase)
{
    __shared__ float sA[128][68];
    const int rb = blockIdx.x, kp = blockIdx.y;
    const int mat = matbase + blockIdx.z;
    const int k0 = kp * 64;
    const int tid = threadIdx.x;

    #pragma unroll
    for (int i = 0; i < 8; i++) {
        int fi = tid + i * 256;           // 0..2047
        int r = fi >> 4, c = fi & 15;     // float4 index within 64-k slice
        int row = rb * 128 + r;
        int rr = (row < MQ) ? row : 0;
        const float* src;
        if (mat == 1) {
            if (rr < 20000)      src = Av0 + (size_t)rr * 256;
            else if (rr < 25000) src = Av1 + (size_t)(rr - 20000) * 256;
            else                 src = Av2 + (size_t)(rr - 25000) * 256;
        } else if (mat == 0) {
            src = Aq + (size_t)rr * 256;
        } else {
            src = g_mid + (size_t)rr * 256;
        }
        float4 v = *(const float4*)(src + k0 + c * 4);
        sA[r][c * 4 + 0] = v.x; sA[r][c * 4 + 1] = v.y;
        sA[r][c * 4 + 2] = v.z; sA[r][c * 4 + 3] = v.w;
    }
    __syncthreads();

    #pragma unroll
    for (int i = 0; i < 4; i++) {
        int oid = tid + i * 256;          // 0..1023
        int lane = oid & 31, q = (oid >> 5) & 3, ktl = (oid >> 7) & 1, wm = oid >> 8;
        int g = lane >> 2, t = lane & 3, mt = q & 1, kk = q >> 1;
        int ks = ktl * 32 + kk * 16 + 2 * t;
        int r0 = wm * 32 + mt * 16 + g, r1 = r0 + 8;

        uint4 hi4, lo4; __nv_bfloat162 h, lo;
        split2(sA[r0][ks],     sA[r0][ks + 1], h, lo); hi4.x = b2u(h); lo4.x = b2u(lo);
        split2(sA[r1][ks],     sA[r1][ks + 1], h, lo); hi4.y = b2u(h); lo4.y = b2u(lo);
        split2(sA[r0][ks + 8], sA[r0][ks + 9], h, lo); hi4.z = b2u(h); lo4.z = b2u(lo);
        split2(sA[r1][ks + 8], sA[r1][ks + 9], h, lo); hi4.w = b2u(h); lo4.w = b2u(lo);

        int kt = kp * 2 + ktl;
        size_t oidx = (size_t)mat * PA_PER_MAT
                    + ((((size_t)rb * 4 + wm) * 8 + kt) * 4 + q) * 32 + lane;
        g_pahi[oidx] = hi4;
        g_palo[oidx] = lo4;
    }
}

// ---------------- split-bf16 tensor-core GEMM: fully packed, smem/barrier-free ----------------
// C[M,N] = Ah@Bh + Al@Bh + Ah@Bl + bias.  Both operands fragment-packed bf16 hi/lo,
// per-lane coalesced LDG.128.  BM=128, BN=64, BK=32; 8 warps 4(M)x2(N).
__global__ __launch_bounds__(256, 2)
void gemm_bf16(int fusedvq, const float* __restrict__ biasp,
               float* __restrict__ Cout, int M, int N_p, int remap_p)
{
    int amat, N = N_p, remap = remap_p, n0, gnb;
    const float* bias = biasp;
    float* C;
    if (fusedvq) {
        if (blockIdx.y < 4) { amat = 1; N = 256; remap = 1; n0 = blockIdx.y * 64;       gnb = blockIdx.y * 2;           C = g_vproj; }
        else                { amat = 0; N = 320; remap = 0; n0 = (blockIdx.y - 4) * 64; gnb = 8 + (blockIdx.y - 4) * 2; C = g_qout; bias = g_biasq; }
    } else {
        amat = 2; n0 = blockIdx.y * 64; gnb = 18 + blockIdx.y * 2; C = Cout;
    }

    const int tid = threadIdx.x, lane = tid & 31, wid = tid >> 5;
    const int wm = wid >> 1, wn = wid & 1;
    const int row0 = blockIdx.x * 128;
    gnb += wn;

    const uint4* pah = g_pahi + (size_t)amat * PA_PER_MAT
                     + (((size_t)blockIdx.x * 4 + wm) * 8) * 128 + lane;
    const uint4* pal = g_palo + (size_t)amat * PA_PER_MAT
                     + (((size_t)blockIdx.x * 4 + wm) * 8) * 128 + lane;
    const uint4* pbh = g_pbhi + (size_t)gnb * (8 * 128) + lane;
    const uint4* pbl = g_pblo + (size_t)gnb * (8 * 128) + lane;

    float acc[2][4][4] = {};

    #pragma unroll 1
    for (int kt = 0; kt < 8; kt++) {
        uint4 AH[4], AL[4], BH[4], BL[4];
        #pragma unroll
        for (int q = 0; q < 4; q++) AH[q] = __ldg(pah + kt * 128 + q * 32);
        #pragma unroll
        for (int q = 0; q < 4; q++) AL[q] = __ldg(pal + kt * 128 + q * 32);
        #pragma unroll
        for (int q = 0; q < 4; q++) BH[q] = __ldg(pbh + kt * 128 + q * 32);
        #pragma unroll
        for (int q = 0; q < 4; q++) BL[q] = __ldg(pbl + kt * 128 + q * 32);

        #pragma unroll
        for (int kk = 0; kk < 2; kk++) {
            #pragma unroll
            for (int mt = 0; mt < 2; mt++) {
                const uint32_t* ah = (const uint32_t*)&AH[kk * 2 + mt];
                const uint32_t* al = (const uint32_t*)&AL[kk * 2 + mt];
                #pragma unroll
                for (int n = 0; n < 4; n++) {
                    const uint4 Qh = BH[kk * 2 + (n >> 1)];
                    const uint4 Ql = BL[kk * 2 + (n >> 1)];
                    uint32_t bh[2], bl[2];
                    if (n & 1) { bh[0] = Qh.z; bh[1] = Qh.w; bl[0] = Ql.z; bl[1] = Ql.w; }
                    else       { bh[0] = Qh.x; bh[1] = Qh.y; bl[0] = Ql.x; bl[1] = Ql.y; }
                    mma16816(acc[mt][n], ah, bh);
                    mma16816(acc[mt][n], al, bh);
                    mma16816(acc[mt][n], ah, bl);
                }
            }
        }
    }

    // epilogue
    const int er = lane >> 2, ec = (lane & 3) * 2;
    #pragma unroll
    for (int mt = 0; mt < 2; mt++) {
        #pragma unroll
        for (int n = 0; n < 4; n++) {
            int col = n0 + wn * 32 + n * 8 + ec;
            float b0 = __ldg(bias + col), b1 = __ldg(bias + col + 1);
            #pragma unroll
            for (int h2 = 0; h2 < 2; h2++) {
                int row = row0 + wm * 32 + mt * 16 + er + 8 * h2;
                if (row < M) {
                    int orow = row;
                    if (remap) {
                        if (row < 20000)      orow = (row / 10000) * NQ + (row % 10000);
                        else if (row < 25000) { int rr = row - 20000; orow = (rr / 2500) * NQ + 10000 + rr % 2500; }
                        else                  { int rr = row - 25000; orow = (rr / 625)  * NQ + 12500 + rr % 625; }
                    }
                    float2 o = make_float2(acc[mt][n][2 * h2] + b0, acc[mt][n][2 * h2 + 1] + b1);
                    *(float2*)(C + (size_t)orow * N + col) = o;
                }
            }
        }
    }
}

// ---------------- fused softmax + deformable bilinear sampling (2-phase) ----------------
__global__ __launch_bounds__(256, 7)
void msda_sample(const float* __restrict__ rp)
{
    __shared__ uint4  s_off[96];
    __shared__ float4 s_w  [96];

    const int bq   = blockIdx.x;
    const int h    = threadIdx.x >> 5;
    const int lane = threadIdx.x & 31;
    const int pg   = lane >> 3;
    const int cq   = lane & 7;

    const uint32_t batOff = (bq >= NQ) ? (uint32_t)NQ * 1024u : 0u;

    float lv = -1e30f;
    if (lane < 12)
        lv = g_qout[(size_t)bq * 320 + 192 + h * 12 + lane];
    float m = lv;
    #pragma unroll
    for (int o = 8; o; o >>= 1) m = fmaxf(m, __shfl_xor_sync(0xffffffffu, m, o));
    float e = (lane < 12) ? __expf(lv - m) : 0.f;
    float s = e;
    #pragma unroll
    for (int o = 8; o; o >>= 1) s += __shfl_xor_sync(0xffffffffu, s, o);

    if (lane < 12) {
        const float a = e / s;
        const int l = lane >> 2, p = lane & 3;
        const int Wi = 100 >> l, Hi = 100 >> l;
        const uint32_t loff = (l > 0 ? 10000u : 0u) + (l > 1 ? 2500u : 0u);
        const float Wf = (float)Wi, Hf = (float)Hi;

        const float2 rxy = *(const float2*)(rp + (size_t)bq * 6 + l * 2);
        const float2 oxy = *(const float2*)(g_qout + (size_t)bq * 320 + h * 24 + l * 8 + p * 2);

        const float x = (rxy.x + oxy.x * (1.0f / Wf)) * Wf - 0.5f;
        const float y = (rxy.y + oxy.y * (1.0f / Hf)) * Hf - 0.5f;
        const float x0f = floorf(x), y0f = floorf(y);
        const float wx1 = x - x0f,  wy1 = y - y0f;
        const int ix0 = (int)x0f, iy0 = (int)y0f;
        const int ix1 = ix0 + 1,  iy1 = iy0 + 1;

        const float ax0 = (ix0 >= 0 && ix0 < Wi) ? (1.f - wx1) * a : 0.f;
        const float ax1 = (ix1 >= 0 && ix1 < Wi) ? wx1 * a : 0.f;
        const float my0 = (iy0 >= 0 && iy0 < Hi) ? (1.f - wy1) : 0.f;
        const float my1 = (iy1 >= 0 && iy1 < Hi) ? wy1 : 0.f;

        const int ix0c = min(max(ix0, 0), Wi - 1), ix1c = min(max(ix1, 0), Wi - 1);
        const int iy0c = min(max(iy0, 0), Hi - 1), iy1c = min(max(iy1, 0), Hi - 1);

        const uint32_t base = batOff + loff * 1024u;
        const uint32_t r0 = base + (uint32_t)(iy0c * Wi) * 1024u;
        const uint32_t r1 = base + (uint32_t)(iy1c * Wi) * 1024u;
        const uint32_t cx0 = (uint32_t)ix0c * 1024u, cx1 = (uint32_t)ix1c * 1024u;

        s_off[h * 12 + lane] = make_uint4(r0 + cx0, r0 + cx1, r1 + cx0, r1 + cx1);
        s_w  [h * 12 + lane] = make_float4(ax0 * my0, ax1 * my0, ax0 * my1, ax1 * my1);
    }
    __syncwarp();

    const char* vb = (const char*)g_vproj;
    const uint32_t laneOff = (uint32_t)((h * HD + cq * 4) * 4);
    float4 acc = make_float4(0.f, 0.f, 0.f, 0.f);

    #pragma unroll
    for (int l = 0; l < LVL; l++) {
        const int idx = h * 12 + l * 4 + pg;
        const uint4  o4 = s_off[idx];
        const float4 w4 = s_w[idx];

        const float4 v00 = *(const float4*)(vb + (o4.x + laneOff));
        const float4 v01 = *(const float4*)(vb + (o4.y + laneOff));
        const float4 v10 = *(const float4*)(vb + (o4.z + laneOff));
        const float4 v11 = *(const float4*)(vb + (o4.w + laneOff));

        acc.x = fmaf(w4.x, v00.x, acc.x); acc.y = fmaf(w4.x, v00.y, acc.y);
        acc.z = fmaf(w4.x, v00.z, acc.z); acc.w = fmaf(w4.x, v00.w, acc.w);
        acc.x = fmaf(w4.y, v01.x, acc.x); acc.y = fmaf(w4.y, v01.y, acc.y);
        acc.z = fmaf(w4.y, v01.z, acc.z); acc.w = fmaf(w4.y, v01.w, acc.w);
        acc.x = fmaf(w4.z, v10.x, acc.x); acc.y = fmaf(w4.z, v10.y, acc.y);
        acc.z = fmaf(w4.z, v10.z, acc.z); acc.w = fmaf(w4.z, v10.w, acc.w);
        acc.x = fmaf(w4.w, v11.x, acc.x); acc.y = fmaf(w4.w, v11.y, acc.y);
        acc.z = fmaf(w4.w, v11.z, acc.z); acc.w = fmaf(w4.w, v11.w, acc.w);
    }

    #pragma unroll
    for (int o = 8; o <= 16; o <<= 1) {
        acc.x += __shfl_xor_sync(0xffffffffu, acc.x, o);
        acc.y += __shfl_xor_sync(0xffffffffu, acc.y, o);
        acc.z += __shfl_xor_sync(0xffffffffu, acc.z, o);
        acc.w += __shfl_xor_sync(0xffffffffu, acc.w, o);
    }

    if (pg == 0)
        *(float4*)(g_mid + (size_t)bq * DMODEL + h * HD + cq * 4) = acc;
}

// ---------------- launch ----------------
extern "C" void kernel_launch(void* const* d_in, const int* in_sizes, int n_in,
                              void* d_out, int out_size)
{
    const float* query  = (const float*)d_in[0];
    const float* rp     = (const float*)d_in[1];
    const float* v0     = (const float*)d_in[2];
    const float* v1     = (const float*)d_in[3];
    const float* v2     = (const float*)d_in[4];
    const float* W_val  = (const float*)d_in[5];
    const float* b_val  = (const float*)d_in[6];
    const float* W_off  = (const float*)d_in[7];
    const float* b_off  = (const float*)d_in[8];
    const float* W_attn = (const float*)d_in[9];
    const float* b_attn = (const float*)d_in[10];
    const float* W_out  = (const float*)d_in[11];
    const float* b_out  = (const float*)d_in[12];
    float* out = (float*)d_out;

    // 1: pack weights + combined bias
    prep_pack<<<(PB_ELEMS + 320 + 255) / 256, 256>>>(W_val, W_off, W_attn, W_out, b_off, b_attn);
    // 2: pack query (slot 0) + values (slot 1) into fragment order
    packA<<<dim3(NRB, 4, 2), 256>>>(query, v0, v1, v2, 0);
    // 3: fused vproj (y=0..3) + qout (y=4..8) GEMM, fully packed operands
    gemm_bf16<<<dim3(NRB, 9), 256>>>(1, b_val, nullptr, MQ, 0, 0);
    // 4: fused softmax + deformable sampling -> g_mid (fp32)
    msda_sample<<<MQ, 256>>>(rp);
    // 5: pack g_mid (slot 2)
    packA<<<dim3(NRB, 4, 1), 256>>>(nullptr, nullptr, nullptr, nullptr, 2);
    // 6: output projection
    gemm_bf16<<<dim3(NRB, 4), 256>>>(0, b_out, out, MQ, 256, 0);
}